// round 1
// baseline (speedup 1.0000x reference)
#include <cuda_runtime.h>
#include <math.h>

// Problem constants
#define NTOK 4608          // B*H*W = 2*48*48
#define DIM 384
#define HGT 48
#define WID 48
#define NCELL 72           // B*6*6
#define NHEAD 6
#define HD 64

// ---------------- scratch (device globals; no allocation allowed) -------------
__device__ float g_scond[NCELL * DIM];        // silu(cond)
__device__ float g_sa1[768];                  // row scales g/||v|| for ada1_v
__device__ float g_sa2[768];
__device__ float g_sg1[384];
__device__ float g_sg2[384];
__device__ float g_ab1[NCELL * 768];          // per-cell a,b (adaln1)
__device__ float g_ab2[NCELL * 768];
__device__ float g_g1[NCELL * 384];           // per-cell gate1 mod
__device__ float g_g2[NCELL * 384];
__device__ float g_h[NTOK * DIM];             // adaln output
__device__ float g_qkv[NTOK * 1152];
__device__ float g_attn[NTOK * DIM];
__device__ float g_x[NTOK * DIM];             // x after first residual
__device__ float g_mlp[NTOK * 1536];

// ---------------- small prep kernels -----------------------------------------

__global__ void silu_k(const float* __restrict__ cond) {
    int i = blockIdx.x * blockDim.x + threadIdx.x;
    if (i < NCELL * DIM) {
        float v = cond[i];
        g_scond[i] = v / (1.0f + __expf(-v));
    }
}

// s[r] = g[r] / ||v[r]||, one warp per row
__global__ void rowscale_k(const float* __restrict__ v, const float* __restrict__ g,
                           float* __restrict__ s) {
    int r = blockIdx.x * 8 + (threadIdx.x >> 5);
    int lane = threadIdx.x & 31;
    const float* vr = v + r * DIM;
    float p = 0.0f;
    for (int i = lane; i < DIM; i += 32) { float t = vr[i]; p += t * t; }
    #pragma unroll
    for (int o = 16; o; o >>= 1) p += __shfl_xor_sync(0xffffffffu, p, o);
    if (lane == 0) s[r] = g[r] * rsqrtf(p);
}

// out[cell][r] = s[r] * dot(silu_cond[cell], v[r]); grid (72, R/8)
__global__ void mod_k(const float* __restrict__ v, const float* __restrict__ s,
                      float* __restrict__ out, int R) {
    int cell = blockIdx.x;
    int r = blockIdx.y * 8 + (threadIdx.x >> 5);
    int lane = threadIdx.x & 31;
    const float* sc = g_scond + cell * DIM;
    const float* vr = v + r * DIM;
    float p = 0.0f;
    for (int i = lane; i < DIM; i += 32) p += sc[i] * vr[i];
    #pragma unroll
    for (int o = 16; o; o >>= 1) p += __shfl_xor_sync(0xffffffffu, p, o);
    if (lane == 0) out[cell * R + r] = p * s[r];
}

// ---------------- adaLN: LN + per-cell (1+a)*xn + b ---------------------------
__global__ void adaln_k(const float* __restrict__ x, const float* __restrict__ gamma,
                        const float* __restrict__ beta, const float* __restrict__ ab,
                        float* __restrict__ out) {
    int t = blockIdx.x;
    int c = threadIdx.x;                 // 384 threads
    int wid = c >> 5, lane = c & 31;
    __shared__ float red[12];
    __shared__ float s_mu, s_var;
    float v = x[t * DIM + c];

    float s = v;
    #pragma unroll
    for (int o = 16; o; o >>= 1) s += __shfl_xor_sync(0xffffffffu, s, o);
    if (!lane) red[wid] = s;
    __syncthreads();
    if (c == 0) {
        float m = 0.0f;
        #pragma unroll
        for (int i = 0; i < 12; i++) m += red[i];
        s_mu = m * (1.0f / 384.0f);
    }
    __syncthreads();
    float mu = s_mu;
    float d = v - mu;
    s = d * d;
    #pragma unroll
    for (int o = 16; o; o >>= 1) s += __shfl_xor_sync(0xffffffffu, s, o);
    if (!lane) red[wid] = s;
    __syncthreads();
    if (c == 0) {
        float m = 0.0f;
        #pragma unroll
        for (int i = 0; i < 12; i++) m += red[i];
        s_var = m * (1.0f / 384.0f);
    }
    __syncthreads();

    float y = d * rsqrtf(s_var + 1e-6f) * gamma[c] + beta[c];
    int b = t / (HGT * WID);
    int rem = t % (HGT * WID);
    int hh = rem / WID, ww = rem % WID;
    int cell = b * 36 + (hh >> 3) * 6 + (ww >> 3);
    float a = ab[cell * 768 + c];
    float bb = ab[cell * 768 + 384 + c];
    out[t * DIM + c] = y * (1.0f + a) + bb;
}

// ---------------- SGEMM 128x128x8, 8x8 micro-tiles ----------------------------
// C[N][M] = epi(A[N][K] @ W[M][K]^T + bias)
// EPI 0: plain +bias  1: gelu(tanh)  2/3: res + val*gate[cell] (M must be 384)
template <int EPI>
__global__ void __launch_bounds__(256, 2)
sgemm_k(const float* __restrict__ A, const float* __restrict__ W,
        const float* __restrict__ bias, float* __restrict__ C,
        int K, int M,
        const float* __restrict__ res, const float* __restrict__ gate) {
    __shared__ float As[8][132];
    __shared__ float Bs[8][132];
    const int tx = threadIdx.x & 15;
    const int ty = threadIdx.x >> 4;
    const int row0 = blockIdx.y * 128;
    const int col0 = blockIdx.x * 128;
    const int lrow = threadIdx.x >> 1;
    const int lk = (threadIdx.x & 1) * 4;

    float acc[8][8];
    #pragma unroll
    for (int i = 0; i < 8; i++)
        #pragma unroll
        for (int j = 0; j < 8; j++) acc[i][j] = 0.0f;

    const float* Ap = A + (size_t)(row0 + lrow) * K + lk;
    const float* Wp = W + (size_t)(col0 + lrow) * K + lk;

    for (int kt = 0; kt < K; kt += 8) {
        float4 a4 = *(const float4*)(Ap + kt);
        float4 w4 = *(const float4*)(Wp + kt);
        As[lk + 0][lrow] = a4.x; As[lk + 1][lrow] = a4.y;
        As[lk + 2][lrow] = a4.z; As[lk + 3][lrow] = a4.w;
        Bs[lk + 0][lrow] = w4.x; Bs[lk + 1][lrow] = w4.y;
        Bs[lk + 2][lrow] = w4.z; Bs[lk + 3][lrow] = w4.w;
        __syncthreads();
        #pragma unroll
        for (int k = 0; k < 8; k++) {
            float ra[8], rb[8];
            #pragma unroll
            for (int i = 0; i < 8; i++) ra[i] = As[k][ty * 8 + i];
            #pragma unroll
            for (int j = 0; j < 8; j++) rb[j] = Bs[k][tx * 8 + j];
            #pragma unroll
            for (int i = 0; i < 8; i++)
                #pragma unroll
                for (int j = 0; j < 8; j++) acc[i][j] += ra[i] * rb[j];
        }
        __syncthreads();
    }

    #pragma unroll
    for (int i = 0; i < 8; i++) {
        int r = row0 + ty * 8 + i;
        const float* gt = nullptr;
        const float* rs = nullptr;
        if (EPI >= 2) {
            int b = r / (HGT * WID);
            int rem = r % (HGT * WID);
            int hh = rem / WID, ww = rem % WID;
            gt = gate + (b * 36 + (hh >> 3) * 6 + (ww >> 3)) * 384;
            rs = res + (size_t)r * 384;
        }
        #pragma unroll
        for (int j = 0; j < 8; j++) {
            int cc = col0 + tx * 8 + j;
            float val = acc[i][j] + bias[cc];
            if (EPI == 1) {
                float x3 = val * val * val;
                val = 0.5f * val * (1.0f + tanhf(0.7978845608028654f * (val + 0.044715f * x3)));
            }
            if (EPI <= 1) {
                C[(size_t)r * M + cc] = val;
            } else {
                C[(size_t)r * 384 + cc] = rs[cc] + val * gt[cc];
            }
        }
    }
}

// ---------------- neighborhood attention (7x7), warp = (token, head) ----------
__global__ void natten_k() {
    int t = blockIdx.x;
    int head = threadIdx.x >> 5;
    int lane = threadIdx.x & 31;
    int b = t / (HGT * WID);
    int rem = t % (HGT * WID);
    int hh = rem / WID, ww = rem % WID;
    int hs = hh - 3; hs = hs < 0 ? 0 : (hs > HGT - 7 ? HGT - 7 : hs);
    int ws = ww - 3; ws = ws < 0 ? 0 : (ws > WID - 7 ? WID - 7 : ws);

    const float2* qb = (const float2*)(g_qkv + (size_t)t * 1152 + head * HD);
    float2 q = qb[lane];

    float lg[49];
    float mx = -1e30f;
    #pragma unroll
    for (int nb = 0; nb < 49; nb++) {
        int tk = (b * HGT + hs + nb / 7) * WID + ws + nb % 7;
        const float2* kb = (const float2*)(g_qkv + (size_t)tk * 1152 + 384 + head * HD);
        float2 kv = kb[lane];
        float p = q.x * kv.x + q.y * kv.y;
        #pragma unroll
        for (int o = 16; o; o >>= 1) p += __shfl_xor_sync(0xffffffffu, p, o);
        p *= 0.125f;  // 1/sqrt(64)
        lg[nb] = p;
        mx = fmaxf(mx, p);
    }
    float s = 0.0f;
    #pragma unroll
    for (int nb = 0; nb < 49; nb++) {
        float e = __expf(lg[nb] - mx);
        lg[nb] = e;
        s += e;
    }
    float inv = 1.0f / s;
    float o0 = 0.0f, o1 = 0.0f;
    #pragma unroll
    for (int nb = 0; nb < 49; nb++) {
        int tk = (b * HGT + hs + nb / 7) * WID + ws + nb % 7;
        const float2* vb = (const float2*)(g_qkv + (size_t)tk * 1152 + 768 + head * HD);
        float2 vv = vb[lane];
        float w = lg[nb] * inv;
        o0 += w * vv.x;
        o1 += w * vv.y;
    }
    ((float2*)(g_attn + (size_t)t * DIM + head * HD))[lane] = make_float2(o0, o1);
}

// ---------------- launch ------------------------------------------------------
extern "C" void kernel_launch(void* const* d_in, const int* in_sizes, int n_in,
                              void* d_out, int out_size) {
    const float* x       = (const float*)d_in[0];
    const float* cond    = (const float*)d_in[1];
    const float* ln1_g   = (const float*)d_in[2];
    const float* ln1_b   = (const float*)d_in[3];
    const float* ada1_v  = (const float*)d_in[4];
    const float* ada1_g  = (const float*)d_in[5];
    const float* ln2_g   = (const float*)d_in[6];
    const float* ln2_b   = (const float*)d_in[7];
    const float* ada2_v  = (const float*)d_in[8];
    const float* ada2_g  = (const float*)d_in[9];
    const float* gate1_v = (const float*)d_in[10];
    const float* gate1_g = (const float*)d_in[11];
    const float* gate2_v = (const float*)d_in[12];
    const float* gate2_g = (const float*)d_in[13];
    const float* w_qkv   = (const float*)d_in[14];
    const float* b_qkv   = (const float*)d_in[15];
    const float* w_out   = (const float*)d_in[16];
    const float* b_out   = (const float*)d_in[17];
    const float* w_mlp1  = (const float*)d_in[18];
    const float* b_mlp1  = (const float*)d_in[19];
    const float* w_mlp2  = (const float*)d_in[20];
    const float* b_mlp2  = (const float*)d_in[21];
    float* out = (float*)d_out;

    float *p_sa1, *p_sa2, *p_sg1, *p_sg2;
    float *p_ab1, *p_ab2, *p_g1, *p_g2;
    float *p_h, *p_qkv, *p_attn, *p_x, *p_mlp;
    cudaGetSymbolAddress((void**)&p_sa1, g_sa1);
    cudaGetSymbolAddress((void**)&p_sa2, g_sa2);
    cudaGetSymbolAddress((void**)&p_sg1, g_sg1);
    cudaGetSymbolAddress((void**)&p_sg2, g_sg2);
    cudaGetSymbolAddress((void**)&p_ab1, g_ab1);
    cudaGetSymbolAddress((void**)&p_ab2, g_ab2);
    cudaGetSymbolAddress((void**)&p_g1, g_g1);
    cudaGetSymbolAddress((void**)&p_g2, g_g2);
    cudaGetSymbolAddress((void**)&p_h, g_h);
    cudaGetSymbolAddress((void**)&p_qkv, g_qkv);
    cudaGetSymbolAddress((void**)&p_attn, g_attn);
    cudaGetSymbolAddress((void**)&p_x, g_x);
    cudaGetSymbolAddress((void**)&p_mlp, g_mlp);

    // cond path
    silu_k<<<(NCELL * DIM + 255) / 256, 256>>>(cond);
    rowscale_k<<<768 / 8, 256>>>(ada1_v, ada1_g, p_sa1);
    rowscale_k<<<768 / 8, 256>>>(ada2_v, ada2_g, p_sa2);
    rowscale_k<<<384 / 8, 256>>>(gate1_v, gate1_g, p_sg1);
    rowscale_k<<<384 / 8, 256>>>(gate2_v, gate2_g, p_sg2);
    mod_k<<<dim3(NCELL, 768 / 8), 256>>>(ada1_v, p_sa1, p_ab1, 768);
    mod_k<<<dim3(NCELL, 768 / 8), 256>>>(ada2_v, p_sa2, p_ab2, 768);
    mod_k<<<dim3(NCELL, 384 / 8), 256>>>(gate1_v, p_sg1, p_g1, 384);
    mod_k<<<dim3(NCELL, 384 / 8), 256>>>(gate2_v, p_sg2, p_g2, 384);

    // branch 1: adaln -> qkv -> natten -> proj(+gate1, +residual)
    adaln_k<<<NTOK, DIM>>>(x, ln1_g, ln1_b, p_ab1, p_h);
    sgemm_k<0><<<dim3(1152 / 128, NTOK / 128), 256>>>(p_h, w_qkv, b_qkv, p_qkv, 384, 1152, nullptr, nullptr);
    natten_k<<<NTOK, NHEAD * 32>>>();
    sgemm_k<2><<<dim3(384 / 128, NTOK / 128), 256>>>(p_attn, w_out, b_out, p_x, 384, 384, x, p_g1);

    // branch 2: adaln -> mlp1(gelu) -> mlp2(+gate2, +residual)
    adaln_k<<<NTOK, DIM>>>(p_x, ln2_g, ln2_b, p_ab2, p_h);
    sgemm_k<1><<<dim3(1536 / 128, NTOK / 128), 256>>>(p_h, w_mlp1, b_mlp1, p_mlp, 384, 1536, nullptr, nullptr);
    sgemm_k<3><<<dim3(384 / 128, NTOK / 128), 256>>>(p_mlp, w_mlp2, b_mlp2, out, 1536, 384, p_x, p_g2);
}

// round 4
// speedup vs baseline: 1.9564x; 1.9564x over previous
#include <cuda_runtime.h>
#include <cuda_bf16.h>
#include <cstdint>
#include <math.h>

// Problem constants
#define NTOK 4608          // B*H*W = 2*48*48
#define DIM 384
#define HGT 48
#define WID 48
#define NCELL 72           // B*6*6
#define NHEAD 6
#define HD 64

// ---------------- scratch (device globals; no allocation allowed) -------------
__device__ float g_scond[NCELL * DIM];        // silu(cond)
__device__ float g_ab1[NCELL * 768];          // per-cell a,b (adaln1)
__device__ float g_ab2[NCELL * 768];
__device__ float g_g1[NCELL * 384];           // per-cell gate1 mod
__device__ float g_g2[NCELL * 384];
__device__ float g_h[NTOK * DIM];             // adaln output
__device__ float g_qkv[NTOK * 1152];
__device__ float g_attn[NTOK * DIM];
__device__ float g_x[NTOK * DIM];             // x after first residual
__device__ float g_mlp[NTOK * 1536];

// ---------------- small prep kernels -----------------------------------------

__global__ void silu_k(const float* __restrict__ cond) {
    int i = blockIdx.x * blockDim.x + threadIdx.x;
    if (i < NCELL * DIM) {
        float v = cond[i];
        g_scond[i] = v / (1.0f + __expf(-v));
    }
}

// fused weight-norm + modulation: out[cell][r] = g[r]/||v[r]|| * dot(scond[cell], v[r])
__global__ void modall_k(const float* __restrict__ a1v, const float* __restrict__ a1g,
                         const float* __restrict__ a2v, const float* __restrict__ a2g,
                         const float* __restrict__ g1v, const float* __restrict__ g1g,
                         const float* __restrict__ g2v, const float* __restrict__ g2g) {
    int cell = blockIdx.x;
    int r = blockIdx.y * 8 + (threadIdx.x >> 5);      // 0..2303
    int lane = threadIdx.x & 31;
    const float* v; const float* g; float* out; int R; int rl;
    if (r < 768)       { rl = r;        v = a1v; g = a1g; out = g_ab1; R = 768; }
    else if (r < 1536) { rl = r - 768;  v = a2v; g = a2g; out = g_ab2; R = 768; }
    else if (r < 1920) { rl = r - 1536; v = g1v; g = g1g; out = g_g1;  R = 384; }
    else               { rl = r - 1920; v = g2v; g = g2g; out = g_g2;  R = 384; }
    const float* sc = g_scond + cell * DIM;
    const float* vr = v + rl * DIM;
    float p = 0.0f, n = 0.0f;
    for (int i = lane; i < DIM; i += 32) {
        float t = vr[i];
        p += sc[i] * t;
        n += t * t;
    }
    #pragma unroll
    for (int o = 16; o; o >>= 1) {
        p += __shfl_xor_sync(0xffffffffu, p, o);
        n += __shfl_xor_sync(0xffffffffu, n, o);
    }
    if (lane == 0) out[cell * R + rl] = g[rl] * rsqrtf(n) * p;
}

// ---------------- adaLN: LN + per-cell (1+a)*xn + b ---------------------------
__global__ void adaln_k(const float* __restrict__ x, const float* __restrict__ gamma,
                        const float* __restrict__ beta, const float* __restrict__ ab,
                        float* __restrict__ out) {
    int t = blockIdx.x;
    int c = threadIdx.x;                 // 384 threads
    int wid = c >> 5, lane = c & 31;
    __shared__ float red[12];
    __shared__ float s_mu, s_var;
    float v = x[t * DIM + c];

    float s = v;
    #pragma unroll
    for (int o = 16; o; o >>= 1) s += __shfl_xor_sync(0xffffffffu, s, o);
    if (!lane) red[wid] = s;
    __syncthreads();
    if (c == 0) {
        float m = 0.0f;
        #pragma unroll
        for (int i = 0; i < 12; i++) m += red[i];
        s_mu = m * (1.0f / 384.0f);
    }
    __syncthreads();
    float mu = s_mu;
    float d = v - mu;
    s = d * d;
    #pragma unroll
    for (int o = 16; o; o >>= 1) s += __shfl_xor_sync(0xffffffffu, s, o);
    if (!lane) red[wid] = s;
    __syncthreads();
    if (c == 0) {
        float m = 0.0f;
        #pragma unroll
        for (int i = 0; i < 12; i++) m += red[i];
        s_var = m * (1.0f / 384.0f);
    }
    __syncthreads();

    float y = d * rsqrtf(s_var + 1e-6f) * gamma[c] + beta[c];
    int b = t / (HGT * WID);
    int rem = t % (HGT * WID);
    int hh = rem / WID, ww = rem % WID;
    int cell = b * 36 + (hh >> 3) * 6 + (ww >> 3);
    float a = ab[cell * 768 + c];
    float bb = ab[cell * 768 + 384 + c];
    out[t * DIM + c] = y * (1.0f + a) + bb;
}

// ================= mma.sync split-bf16 GEMM ====================================
// C[N][M] = epi(A[N][K] @ W[M][K]^T + bias), fp32 in/out
// a = a_hi + a_lo (bf16); D += Ah*Bh + Ah*Bl + Al*Bh (fp32 accum) -> ~1e-5 rel err
// EPI 0: +bias  1: gelu(tanh)  2/3: res + val*gate[cell] (M must be 384)

__device__ __forceinline__ uint32_t smem_u32(const void* p) {
    uint32_t a;
    asm("{ .reg .u64 t; cvta.to.shared.u64 t, %1; cvt.u32.u64 %0, t; }" : "=r"(a) : "l"(p));
    return a;
}
__device__ __forceinline__ void ldsm_x4(uint32_t* r, uint32_t addr) {
    asm volatile("ldmatrix.sync.aligned.m8n8.x4.shared.b16 {%0,%1,%2,%3}, [%4];"
                 : "=r"(r[0]), "=r"(r[1]), "=r"(r[2]), "=r"(r[3]) : "r"(addr));
}
// B fragment: NON-transposed (pairs of consecutive K elements from a W row)
__device__ __forceinline__ void ldsm_x2(uint32_t* r, uint32_t addr) {
    asm volatile("ldmatrix.sync.aligned.m8n8.x2.shared.b16 {%0,%1}, [%2];"
                 : "=r"(r[0]), "=r"(r[1]) : "r"(addr));
}
__device__ __forceinline__ void mma_bf16(float* c, const uint32_t* a, const uint32_t* b) {
    asm volatile("mma.sync.aligned.m16n8k16.row.col.f32.bf16.bf16.f32 "
                 "{%0,%1,%2,%3}, {%4,%5,%6,%7}, {%8,%9}, {%0,%1,%2,%3};"
                 : "+f"(c[0]), "+f"(c[1]), "+f"(c[2]), "+f"(c[3])
                 : "r"(a[0]), "r"(a[1]), "r"(a[2]), "r"(a[3]), "r"(b[0]), "r"(b[1]));
}

#define PITCH 40   // bf16 elements per SMEM row (32 + 8 pad)

__device__ __forceinline__ void split4(float4 v, uint2& hi, uint2& lo) {
    __nv_bfloat162 h0 = __float22bfloat162_rn(make_float2(v.x, v.y));
    __nv_bfloat162 h1 = __float22bfloat162_rn(make_float2(v.z, v.w));
    float2 f0 = __bfloat1622float2(h0);
    float2 f1 = __bfloat1622float2(h1);
    __nv_bfloat162 l0 = __float22bfloat162_rn(make_float2(v.x - f0.x, v.y - f0.y));
    __nv_bfloat162 l1 = __float22bfloat162_rn(make_float2(v.z - f1.x, v.w - f1.y));
    hi.x = *reinterpret_cast<uint32_t*>(&h0); hi.y = *reinterpret_cast<uint32_t*>(&h1);
    lo.x = *reinterpret_cast<uint32_t*>(&l0); lo.y = *reinterpret_cast<uint32_t*>(&l1);
}

template <int EPI>
__global__ void __launch_bounds__(256, 1)
hgemm_k(const float* __restrict__ A, const float* __restrict__ W,
        const float* __restrict__ bias, float* __restrict__ C,
        int K, int M,
        const float* __restrict__ res, const float* __restrict__ gate) {
    __shared__ __align__(16) __nv_bfloat16 sAh[128 * PITCH];
    __shared__ __align__(16) __nv_bfloat16 sAl[128 * PITCH];
    __shared__ __align__(16) __nv_bfloat16 sBh[128 * PITCH];
    __shared__ __align__(16) __nv_bfloat16 sBl[128 * PITCH];

    const int tid = threadIdx.x;
    const int lane = tid & 31;
    const int w = tid >> 5;
    const int wr = w >> 2;          // 0..1 (64-row band)
    const int wc = w & 3;           // 0..3 (32-col band)
    const int row0 = blockIdx.y * 128;
    const int col0 = blockIdx.x * 128;

    float acc[4][4][4];
    #pragma unroll
    for (int i = 0; i < 4; i++)
        #pragma unroll
        for (int j = 0; j < 4; j++)
            #pragma unroll
            for (int q = 0; q < 4; q++) acc[i][j][q] = 0.0f;

    const int ldrow = tid >> 1;              // 0..127
    const int ldcol = (tid & 1) * 16;        // 0 or 16
    const float* Ap = A + (size_t)(row0 + ldrow) * K + ldcol;
    const float* Wp = W + (size_t)(col0 + ldrow) * K + ldcol;

    const uint32_t uAh = smem_u32(sAh), uAl = smem_u32(sAl);
    const uint32_t uBh = smem_u32(sBh), uBl = smem_u32(sBl);

    const int nCh = K >> 5;
    float4 aR[4], bR[4];
    #pragma unroll
    for (int i = 0; i < 4; i++) {
        aR[i] = *(const float4*)(Ap + i * 4);
        bR[i] = *(const float4*)(Wp + i * 4);
    }

    for (int c = 0; c < nCh; c++) {
        __syncthreads();   // previous iteration's mma reads done
        // split-store current chunk
        {
            uint32_t so = (uint32_t)(ldrow * PITCH + ldcol) * 2;
            #pragma unroll
            for (int i = 0; i < 4; i++) {
                uint2 hi, lo;
                split4(aR[i], hi, lo);
                *(uint2*)((char*)sAh + so + i * 8) = hi;
                *(uint2*)((char*)sAl + so + i * 8) = lo;
                split4(bR[i], hi, lo);
                *(uint2*)((char*)sBh + so + i * 8) = hi;
                *(uint2*)((char*)sBl + so + i * 8) = lo;
            }
        }
        __syncthreads();
        // prefetch next chunk (hidden under mma below)
        if (c + 1 < nCh) {
            #pragma unroll
            for (int i = 0; i < 4; i++) {
                aR[i] = *(const float4*)(Ap + (c + 1) * 32 + i * 4);
                bR[i] = *(const float4*)(Wp + (c + 1) * 32 + i * 4);
            }
        }
        // mma over two k16 steps
        #pragma unroll
        for (int ks = 0; ks < 2; ks++) {
            const int k0 = ks * 16;
            uint32_t ah[4][4], al[4][4], bh[4][2], bl[4][2];
            const int arow = lane & 15;
            const int acol = k0 + ((lane >> 4) << 3);
            #pragma unroll
            for (int mt = 0; mt < 4; mt++) {
                uint32_t off = (uint32_t)((wr * 64 + mt * 16 + arow) * PITCH + acol) * 2;
                ldsm_x4(ah[mt], uAh + off);
                ldsm_x4(al[mt], uAl + off);
            }
            const int brow = lane & 7;
            const int bcol = k0 + (((lane >> 3) & 1) << 3);
            #pragma unroll
            for (int nt = 0; nt < 4; nt++) {
                uint32_t off = (uint32_t)((wc * 32 + nt * 8 + brow) * PITCH + bcol) * 2;
                ldsm_x2(bh[nt], uBh + off);
                ldsm_x2(bl[nt], uBl + off);
            }
            #pragma unroll
            for (int mt = 0; mt < 4; mt++)
                #pragma unroll
                for (int nt = 0; nt < 4; nt++) {
                    mma_bf16(acc[mt][nt], ah[mt], bh[nt]);
                    mma_bf16(acc[mt][nt], ah[mt], bl[nt]);
                    mma_bf16(acc[mt][nt], al[mt], bh[nt]);
                }
        }
    }

    // epilogue straight from accum registers
    #pragma unroll
    for (int mt = 0; mt < 4; mt++) {
        #pragma unroll
        for (int half = 0; half < 2; half++) {
            const int r = row0 + wr * 64 + mt * 16 + (lane >> 2) + half * 8;
            const float* gt = nullptr;
            const float* rs = nullptr;
            if (EPI >= 2) {
                int b = r / (HGT * WID);
                int rem = r % (HGT * WID);
                int hh = rem / WID, ww = rem % WID;
                gt = gate + (b * 36 + (hh >> 3) * 6 + (ww >> 3)) * 384;
                rs = res + (size_t)r * 384;
            }
            #pragma unroll
            for (int nt = 0; nt < 4; nt++) {
                const int cc = col0 + wc * 32 + nt * 8 + (lane & 3) * 2;
                float v0 = acc[mt][nt][half * 2 + 0] + bias[cc];
                float v1 = acc[mt][nt][half * 2 + 1] + bias[cc + 1];
                if (EPI == 1) {
                    float x3 = v0 * v0 * v0;
                    v0 = 0.5f * v0 * (1.0f + tanhf(0.7978845608028654f * (v0 + 0.044715f * x3)));
                    x3 = v1 * v1 * v1;
                    v1 = 0.5f * v1 * (1.0f + tanhf(0.7978845608028654f * (v1 + 0.044715f * x3)));
                }
                if (EPI <= 1) {
                    *(float2*)(C + (size_t)r * M + cc) = make_float2(v0, v1);
                } else {
                    float2 o;
                    o.x = rs[cc]     + v0 * gt[cc];
                    o.y = rs[cc + 1] + v1 * gt[cc + 1];
                    *(float2*)(C + (size_t)r * 384 + cc) = o;
                }
            }
        }
    }
}

// ---------------- neighborhood attention (7x7), warp = (token, head) ----------
__global__ void natten_k() {
    int t = blockIdx.x;
    int head = threadIdx.x >> 5;
    int lane = threadIdx.x & 31;
    int b = t / (HGT * WID);
    int rem = t % (HGT * WID);
    int hh = rem / WID, ww = rem % WID;
    int hs = hh - 3; hs = hs < 0 ? 0 : (hs > HGT - 7 ? HGT - 7 : hs);
    int ws = ww - 3; ws = ws < 0 ? 0 : (ws > WID - 7 ? WID - 7 : ws);

    const float2* qb = (const float2*)(g_qkv + (size_t)t * 1152 + head * HD);
    float2 q = qb[lane];

    float lg[49];
    float mx = -1e30f;
    #pragma unroll
    for (int nb = 0; nb < 49; nb++) {
        int tk = (b * HGT + hs + nb / 7) * WID + ws + nb % 7;
        const float2* kb = (const float2*)(g_qkv + (size_t)tk * 1152 + 384 + head * HD);
        float2 kv = kb[lane];
        float p = q.x * kv.x + q.y * kv.y;
        #pragma unroll
        for (int o = 16; o; o >>= 1) p += __shfl_xor_sync(0xffffffffu, p, o);
        p *= 0.125f;  // 1/sqrt(64)
        lg[nb] = p;
        mx = fmaxf(mx, p);
    }
    float s = 0.0f;
    #pragma unroll
    for (int nb = 0; nb < 49; nb++) {
        float e = __expf(lg[nb] - mx);
        lg[nb] = e;
        s += e;
    }
    float inv = 1.0f / s;
    float o0 = 0.0f, o1 = 0.0f;
    #pragma unroll
    for (int nb = 0; nb < 49; nb++) {
        int tk = (b * HGT + hs + nb / 7) * WID + ws + nb % 7;
        const float2* vb = (const float2*)(g_qkv + (size_t)tk * 1152 + 768 + head * HD);
        float2 vv = vb[lane];
        float w = lg[nb] * inv;
        o0 += w * vv.x;
        o1 += w * vv.y;
    }
    ((float2*)(g_attn + (size_t)t * DIM + head * HD))[lane] = make_float2(o0, o1);
}

// ---------------- launch ------------------------------------------------------
extern "C" void kernel_launch(void* const* d_in, const int* in_sizes, int n_in,
                              void* d_out, int out_size) {
    const float* x       = (const float*)d_in[0];
    const float* cond    = (const float*)d_in[1];
    const float* ln1_g   = (const float*)d_in[2];
    const float* ln1_b   = (const float*)d_in[3];
    const float* ada1_v  = (const float*)d_in[4];
    const float* ada1_g  = (const float*)d_in[5];
    const float* ln2_g   = (const float*)d_in[6];
    const float* ln2_b   = (const float*)d_in[7];
    const float* ada2_v  = (const float*)d_in[8];
    const float* ada2_g  = (const float*)d_in[9];
    const float* gate1_v = (const float*)d_in[10];
    const float* gate1_g = (const float*)d_in[11];
    const float* gate2_v = (const float*)d_in[12];
    const float* gate2_g = (const float*)d_in[13];
    const float* w_qkv   = (const float*)d_in[14];
    const float* b_qkv   = (const float*)d_in[15];
    const float* w_out   = (const float*)d_in[16];
    const float* b_out   = (const float*)d_in[17];
    const float* w_mlp1  = (const float*)d_in[18];
    const float* b_mlp1  = (const float*)d_in[19];
    const float* w_mlp2  = (const float*)d_in[20];
    const float* b_mlp2  = (const float*)d_in[21];
    float* out = (float*)d_out;

    float *p_ab1, *p_ab2, *p_g1, *p_g2, *p_h, *p_qkv, *p_attn, *p_x, *p_mlp;
    cudaGetSymbolAddress((void**)&p_ab1, g_ab1);
    cudaGetSymbolAddress((void**)&p_ab2, g_ab2);
    cudaGetSymbolAddress((void**)&p_g1, g_g1);
    cudaGetSymbolAddress((void**)&p_g2, g_g2);
    cudaGetSymbolAddress((void**)&p_h, g_h);
    cudaGetSymbolAddress((void**)&p_qkv, g_qkv);
    cudaGetSymbolAddress((void**)&p_attn, g_attn);
    cudaGetSymbolAddress((void**)&p_x, g_x);
    cudaGetSymbolAddress((void**)&p_mlp, g_mlp);

    // cond path
    silu_k<<<(NCELL * DIM + 255) / 256, 256>>>(cond);
    modall_k<<<dim3(NCELL, 2304 / 8), 256>>>(ada1_v, ada1_g, ada2_v, ada2_g,
                                             gate1_v, gate1_g, gate2_v, gate2_g);

    // branch 1: adaln -> qkv -> natten -> proj(+gate1, +residual)
    adaln_k<<<NTOK, DIM>>>(x, ln1_g, ln1_b, p_ab1, p_h);
    hgemm_k<0><<<dim3(1152 / 128, NTOK / 128), 256>>>(p_h, w_qkv, b_qkv, p_qkv, 384, 1152, nullptr, nullptr);
    natten_k<<<NTOK, NHEAD * 32>>>();
    hgemm_k<2><<<dim3(384 / 128, NTOK / 128), 256>>>(p_attn, w_out, b_out, p_x, 384, 384, x, p_g1);

    // branch 2: adaln -> mlp1(gelu) -> mlp2(+gate2, +residual)
    adaln_k<<<NTOK, DIM>>>(p_x, ln2_g, ln2_b, p_ab2, p_h);
    hgemm_k<1><<<dim3(1536 / 128, NTOK / 128), 256>>>(p_h, w_mlp1, b_mlp1, p_mlp, 384, 1536, nullptr, nullptr);
    hgemm_k<3><<<dim3(384 / 128, NTOK / 128), 256>>>(p_mlp, w_mlp2, b_mlp2, out, 1536, 384, p_x, p_g2);
}

// round 5
// speedup vs baseline: 1.9573x; 1.0005x over previous
#include <cuda_runtime.h>
#include <cuda_bf16.h>
#include <cstdint>
#include <math.h>

// Problem constants
#define NTOK 4608          // B*H*W = 2*48*48
#define DIM 384
#define HGT 48
#define WID 48
#define NCELL 72           // B*6*6
#define NHEAD 6
#define HD 64

// ---------------- scratch (device globals; no allocation allowed) -------------
__device__ float g_scond[NCELL * DIM];
__device__ float g_ab1[NCELL * 768];
__device__ float g_ab2[NCELL * 768];
__device__ float g_g1[NCELL * 384];
__device__ float g_g2[NCELL * 384];
__device__ float g_qkv[NTOK * 1152];
__device__ float g_x[NTOK * DIM];

// bf16 hi/lo pre-split buffers
__device__ __align__(16) __nv_bfloat16 g_wqkv_h[1152 * 384];
__device__ __align__(16) __nv_bfloat16 g_wqkv_l[1152 * 384];
__device__ __align__(16) __nv_bfloat16 g_wout_h[384 * 384];
__device__ __align__(16) __nv_bfloat16 g_wout_l[384 * 384];
__device__ __align__(16) __nv_bfloat16 g_wm1_h[1536 * 384];
__device__ __align__(16) __nv_bfloat16 g_wm1_l[1536 * 384];
__device__ __align__(16) __nv_bfloat16 g_wm2_h[384 * 1536];
__device__ __align__(16) __nv_bfloat16 g_wm2_l[384 * 1536];
__device__ __align__(16) __nv_bfloat16 g_h_h[NTOK * 384];
__device__ __align__(16) __nv_bfloat16 g_h_l[NTOK * 384];
__device__ __align__(16) __nv_bfloat16 g_attn_h[NTOK * 384];
__device__ __align__(16) __nv_bfloat16 g_attn_l[NTOK * 384];
__device__ __align__(16) __nv_bfloat16 g_mlp_h[NTOK * 1536];
__device__ __align__(16) __nv_bfloat16 g_mlp_l[NTOK * 1536];

// ---------------- helpers -----------------------------------------------------
__device__ __forceinline__ uint32_t smem_u32(const void* p) {
    uint32_t a;
    asm("{ .reg .u64 t; cvta.to.shared.u64 t, %1; cvt.u32.u64 %0, t; }" : "=r"(a) : "l"(p));
    return a;
}
__device__ __forceinline__ void cp16(uint32_t dst, const void* src) {
    asm volatile("cp.async.ca.shared.global [%0], [%1], 16;" :: "r"(dst), "l"(src));
}
#define CP_COMMIT() asm volatile("cp.async.commit_group;" ::: "memory")
template <int N> __device__ __forceinline__ void cp_wait() {
    asm volatile("cp.async.wait_group %0;" :: "n"(N) : "memory");
}
__device__ __forceinline__ void ldsm_x4(uint32_t* r, uint32_t addr) {
    asm volatile("ldmatrix.sync.aligned.m8n8.x4.shared.b16 {%0,%1,%2,%3}, [%4];"
                 : "=r"(r[0]), "=r"(r[1]), "=r"(r[2]), "=r"(r[3]) : "r"(addr));
}
__device__ __forceinline__ void mma_bf16(float* c, const uint32_t* a, const uint32_t* b) {
    asm volatile("mma.sync.aligned.m16n8k16.row.col.f32.bf16.bf16.f32 "
                 "{%0,%1,%2,%3}, {%4,%5,%6,%7}, {%8,%9}, {%0,%1,%2,%3};"
                 : "+f"(c[0]), "+f"(c[1]), "+f"(c[2]), "+f"(c[3])
                 : "r"(a[0]), "r"(a[1]), "r"(a[2]), "r"(a[3]), "r"(b[0]), "r"(b[1]));
}
__device__ __forceinline__ void split2(float v0, float v1,
                                       __nv_bfloat162& hi, __nv_bfloat162& lo) {
    hi = __float22bfloat162_rn(make_float2(v0, v1));
    float2 f = __bfloat1622float2(hi);
    lo = __float22bfloat162_rn(make_float2(v0 - f.x, v1 - f.y));
}

// ---------------- small prep kernels -----------------------------------------
__global__ void silu_k(const float* __restrict__ cond) {
    int i = blockIdx.x * blockDim.x + threadIdx.x;
    if (i < NCELL * DIM) {
        float v = cond[i];
        g_scond[i] = v / (1.0f + __expf(-v));
    }
}

__global__ void split_k(const float* __restrict__ src, __nv_bfloat16* __restrict__ hi,
                        __nv_bfloat16* __restrict__ lo, int n) {
    int i = blockIdx.x * blockDim.x + threadIdx.x;
    if (i < n) {
        float v = src[i];
        __nv_bfloat16 h = __float2bfloat16(v);
        hi[i] = h;
        lo[i] = __float2bfloat16(v - __bfloat162float(h));
    }
}

__global__ void modall_k(const float* __restrict__ a1v, const float* __restrict__ a1g,
                         const float* __restrict__ a2v, const float* __restrict__ a2g,
                         const float* __restrict__ g1v, const float* __restrict__ g1g,
                         const float* __restrict__ g2v, const float* __restrict__ g2g) {
    int cell = blockIdx.x;
    int r = blockIdx.y * 8 + (threadIdx.x >> 5);      // 0..2303
    int lane = threadIdx.x & 31;
    const float* v; const float* g; float* out; int R; int rl;
    if (r < 768)       { rl = r;        v = a1v; g = a1g; out = g_ab1; R = 768; }
    else if (r < 1536) { rl = r - 768;  v = a2v; g = a2g; out = g_ab2; R = 768; }
    else if (r < 1920) { rl = r - 1536; v = g1v; g = g1g; out = g_g1;  R = 384; }
    else               { rl = r - 1920; v = g2v; g = g2g; out = g_g2;  R = 384; }
    const float* sc = g_scond + cell * DIM;
    const float* vr = v + rl * DIM;
    float p = 0.0f, n = 0.0f;
    for (int i = lane; i < DIM; i += 32) {
        float t = vr[i];
        p += sc[i] * t;
        n += t * t;
    }
    #pragma unroll
    for (int o = 16; o; o >>= 1) {
        p += __shfl_xor_sync(0xffffffffu, p, o);
        n += __shfl_xor_sync(0xffffffffu, n, o);
    }
    if (lane == 0) out[cell * R + rl] = g[rl] * rsqrtf(n) * p;
}

// adaLN -> writes bf16 hi/lo directly
__global__ void adaln_k(const float* __restrict__ x, const float* __restrict__ gamma,
                        const float* __restrict__ beta, const float* __restrict__ ab) {
    int t = blockIdx.x;
    int c = threadIdx.x;
    int wid = c >> 5, lane = c & 31;
    __shared__ float red[12];
    __shared__ float s_mu, s_var;
    float v = x[t * DIM + c];

    float s = v;
    #pragma unroll
    for (int o = 16; o; o >>= 1) s += __shfl_xor_sync(0xffffffffu, s, o);
    if (!lane) red[wid] = s;
    __syncthreads();
    if (c == 0) {
        float m = 0.0f;
        #pragma unroll
        for (int i = 0; i < 12; i++) m += red[i];
        s_mu = m * (1.0f / 384.0f);
    }
    __syncthreads();
    float mu = s_mu;
    float d = v - mu;
    s = d * d;
    #pragma unroll
    for (int o = 16; o; o >>= 1) s += __shfl_xor_sync(0xffffffffu, s, o);
    if (!lane) red[wid] = s;
    __syncthreads();
    if (c == 0) {
        float m = 0.0f;
        #pragma unroll
        for (int i = 0; i < 12; i++) m += red[i];
        s_var = m * (1.0f / 384.0f);
    }
    __syncthreads();

    float y = d * rsqrtf(s_var + 1e-6f) * gamma[c] + beta[c];
    int b = t / (HGT * WID);
    int rem = t % (HGT * WID);
    int hh = rem / WID, ww = rem % WID;
    int cell = b * 36 + (hh >> 3) * 6 + (ww >> 3);
    float a = ab[cell * 768 + c];
    float bb = ab[cell * 768 + 384 + c];
    float o = y * (1.0f + a) + bb;
    __nv_bfloat16 h = __float2bfloat16(o);
    g_h_h[t * DIM + c] = h;
    g_h_l[t * DIM + c] = __float2bfloat16(o - __bfloat162float(h));
}

// ================= cp.async double-buffered split-bf16 GEMM ====================
// C = epi(A @ W^T + bias); A,W pre-split bf16 hi/lo; D = Ah*Bh + Ah*Bl + Al*Bh
// EPI 0: fp32 +bias  1: gelu -> bf16 hi/lo out  2/3: fp32 res + val*gate[cell]

#define PITCH 40                 // bf16 per SMEM row (32 + 8 pad)
#define TILE_B 10240             // 128 * PITCH * 2
#define BUF_B  40960             // 4 tiles
#define SMEM_TOT 81920           // 2 buffers

template <int EPI>
__global__ void __launch_bounds__(256, 2)
hgemm_k(const __nv_bfloat16* __restrict__ Ahp, const __nv_bfloat16* __restrict__ Alp,
        const __nv_bfloat16* __restrict__ Whp, const __nv_bfloat16* __restrict__ Wlp,
        const float* __restrict__ bias, float* __restrict__ C,
        int K, int M,
        const float* __restrict__ res, const float* __restrict__ gate,
        __nv_bfloat16* __restrict__ Oh, __nv_bfloat16* __restrict__ Ol) {
    extern __shared__ char smem[];
    const uint32_t sbase = smem_u32(smem);
    const int tid = threadIdx.x;
    const int lane = tid & 31;
    const int w = tid >> 5;
    const int wr = w >> 2;
    const int wc = w & 3;
    const int row0 = blockIdx.y * 128;
    const int col0 = blockIdx.x * 128;

    float acc[4][4][4];
    #pragma unroll
    for (int i = 0; i < 4; i++)
        #pragma unroll
        for (int j = 0; j < 4; j++)
            #pragma unroll
            for (int q = 0; q < 4; q++) acc[i][j][q] = 0.0f;

    const int ldrow = tid >> 1;            // 0..127
    const int lc = (tid & 1) * 32;         // byte offset within 64B row segment
    const char* srcA_h = (const char*)(Ahp + (size_t)(row0 + ldrow) * K) + lc;
    const char* srcA_l = (const char*)(Alp + (size_t)(row0 + ldrow) * K) + lc;
    const char* srcW_h = (const char*)(Whp + (size_t)(col0 + ldrow) * K) + lc;
    const char* srcW_l = (const char*)(Wlp + (size_t)(col0 + ldrow) * K) + lc;
    const uint32_t dbase = sbase + ldrow * (PITCH * 2) + lc;

    const int nCh = K >> 5;

    // issue cp.async loads for chunk c into buffer c&1
    auto issue = [&](int c) {
        const int bo = (c & 1) * BUF_B;
        const int go = c * 64;             // byte offset along K
        #pragma unroll
        for (int j = 0; j < 2; j++) {
            cp16(dbase + bo + 0 * TILE_B + j * 16, srcA_h + go + j * 16);
            cp16(dbase + bo + 1 * TILE_B + j * 16, srcA_l + go + j * 16);
            cp16(dbase + bo + 2 * TILE_B + j * 16, srcW_h + go + j * 16);
            cp16(dbase + bo + 3 * TILE_B + j * 16, srcW_l + go + j * 16);
        }
    };

    issue(0);
    CP_COMMIT();

    const int arow = lane & 15;
    const int acolh = (lane >> 4) << 3;
    const int bnt2 = lane >> 4;            // nt within pair
    const int bkh = (lane >> 3) & 1;       // k half
    const int brow = lane & 7;

    for (int c = 0; c < nCh; c++) {
        if (c + 1 < nCh) { issue(c + 1); CP_COMMIT(); cp_wait<1>(); }
        else             { cp_wait<0>(); }
        __syncthreads();

        const uint32_t bo = sbase + (c & 1) * BUF_B;
        const uint32_t uAh = bo, uAl = bo + TILE_B, uBh = bo + 2 * TILE_B, uBl = bo + 3 * TILE_B;

        #pragma unroll
        for (int ks = 0; ks < 2; ks++) {
            const int k0 = ks * 16;
            uint32_t ah[4][4], al[4][4], bh[4][2], bl[4][2];
            #pragma unroll
            for (int mt = 0; mt < 4; mt++) {
                uint32_t off = (uint32_t)((wr * 64 + mt * 16 + arow) * PITCH + k0 + acolh) * 2;
                ldsm_x4(ah[mt], uAh + off);
                ldsm_x4(al[mt], uAl + off);
            }
            #pragma unroll
            for (int ntp = 0; ntp < 2; ntp++) {
                uint32_t off = (uint32_t)((wc * 32 + (ntp * 2 + bnt2) * 8 + brow) * PITCH
                                          + k0 + bkh * 8) * 2;
                ldsm_x4(&bh[ntp * 2][0], uBh + off);
                ldsm_x4(&bl[ntp * 2][0], uBl + off);
            }
            #pragma unroll
            for (int mt = 0; mt < 4; mt++)
                #pragma unroll
                for (int nt = 0; nt < 4; nt++) {
                    mma_bf16(acc[mt][nt], ah[mt], bh[nt]);
                    mma_bf16(acc[mt][nt], ah[mt], bl[nt]);
                    mma_bf16(acc[mt][nt], al[mt], bh[nt]);
                }
        }
        __syncthreads();
    }

    // epilogue straight from accum registers
    #pragma unroll
    for (int mt = 0; mt < 4; mt++) {
        #pragma unroll
        for (int half = 0; half < 2; half++) {
            const int r = row0 + wr * 64 + mt * 16 + (lane >> 2) + half * 8;
            const float* gt = nullptr;
            const float* rs = nullptr;
            if (EPI >= 2) {
                int b = r / (HGT * WID);
                int rem = r % (HGT * WID);
                int hh = rem / WID, ww = rem % WID;
                gt = gate + (b * 36 + (hh >> 3) * 6 + (ww >> 3)) * 384;
                rs = res + (size_t)r * 384;
            }
            #pragma unroll
            for (int nt = 0; nt < 4; nt++) {
                const int cc = col0 + wc * 32 + nt * 8 + (lane & 3) * 2;
                float v0 = acc[mt][nt][half * 2 + 0] + bias[cc];
                float v1 = acc[mt][nt][half * 2 + 1] + bias[cc + 1];
                if (EPI == 1) {
                    float x3 = v0 * v0 * v0;
                    v0 = 0.5f * v0 * (1.0f + tanhf(0.7978845608028654f * (v0 + 0.044715f * x3)));
                    x3 = v1 * v1 * v1;
                    v1 = 0.5f * v1 * (1.0f + tanhf(0.7978845608028654f * (v1 + 0.044715f * x3)));
                    __nv_bfloat162 hi, lo;
                    split2(v0, v1, hi, lo);
                    *(__nv_bfloat162*)(Oh + (size_t)r * M + cc) = hi;
                    *(__nv_bfloat162*)(Ol + (size_t)r * M + cc) = lo;
                } else if (EPI == 0) {
                    *(float2*)(C + (size_t)r * M + cc) = make_float2(v0, v1);
                } else {
                    float2 o;
                    o.x = rs[cc]     + v0 * gt[cc];
                    o.y = rs[cc + 1] + v1 * gt[cc + 1];
                    *(float2*)(C + (size_t)r * 384 + cc) = o;
                }
            }
        }
    }
}

// ---------------- neighborhood attention (7x7), warp = (token, head) ----------
__global__ void natten_k() {
    int t = blockIdx.x;
    int head = threadIdx.x >> 5;
    int lane = threadIdx.x & 31;
    int b = t / (HGT * WID);
    int rem = t % (HGT * WID);
    int hh = rem / WID, ww = rem % WID;
    int hs = hh - 3; hs = hs < 0 ? 0 : (hs > HGT - 7 ? HGT - 7 : hs);
    int ws = ww - 3; ws = ws < 0 ? 0 : (ws > WID - 7 ? WID - 7 : ws);

    const float2* qb = (const float2*)(g_qkv + (size_t)t * 1152 + head * HD);
    float2 q = qb[lane];

    float lg[49];
    float mx = -1e30f;
    #pragma unroll
    for (int nb = 0; nb < 49; nb++) {
        int tk = (b * HGT + hs + nb / 7) * WID + ws + nb % 7;
        const float2* kb = (const float2*)(g_qkv + (size_t)tk * 1152 + 384 + head * HD);
        float2 kv = kb[lane];
        float p = q.x * kv.x + q.y * kv.y;
        #pragma unroll
        for (int o = 16; o; o >>= 1) p += __shfl_xor_sync(0xffffffffu, p, o);
        p *= 0.125f;
        lg[nb] = p;
        mx = fmaxf(mx, p);
    }
    float s = 0.0f;
    #pragma unroll
    for (int nb = 0; nb < 49; nb++) {
        float e = __expf(lg[nb] - mx);
        lg[nb] = e;
        s += e;
    }
    float inv = 1.0f / s;
    float o0 = 0.0f, o1 = 0.0f;
    #pragma unroll
    for (int nb = 0; nb < 49; nb++) {
        int tk = (b * HGT + hs + nb / 7) * WID + ws + nb % 7;
        const float2* vb = (const float2*)(g_qkv + (size_t)tk * 1152 + 768 + head * HD);
        float2 vv = vb[lane];
        float w = lg[nb] * inv;
        o0 += w * vv.x;
        o1 += w * vv.y;
    }
    __nv_bfloat162 hi, lo;
    split2(o0, o1, hi, lo);
    ((__nv_bfloat162*)(g_attn_h + (size_t)t * DIM + head * HD))[lane] = hi;
    ((__nv_bfloat162*)(g_attn_l + (size_t)t * DIM + head * HD))[lane] = lo;
}

// ---------------- launch ------------------------------------------------------
extern "C" void kernel_launch(void* const* d_in, const int* in_sizes, int n_in,
                              void* d_out, int out_size) {
    const float* x       = (const float*)d_in[0];
    const float* cond    = (const float*)d_in[1];
    const float* ln1_g   = (const float*)d_in[2];
    const float* ln1_b   = (const float*)d_in[3];
    const float* ada1_v  = (const float*)d_in[4];
    const float* ada1_g  = (const float*)d_in[5];
    const float* ln2_g   = (const float*)d_in[6];
    const float* ln2_b   = (const float*)d_in[7];
    const float* ada2_v  = (const float*)d_in[8];
    const float* ada2_g  = (const float*)d_in[9];
    const float* gate1_v = (const float*)d_in[10];
    const float* gate1_g = (const float*)d_in[11];
    const float* gate2_v = (const float*)d_in[12];
    const float* gate2_g = (const float*)d_in[13];
    const float* w_qkv   = (const float*)d_in[14];
    const float* b_qkv   = (const float*)d_in[15];
    const float* w_out   = (const float*)d_in[16];
    const float* b_out   = (const float*)d_in[17];
    const float* w_mlp1  = (const float*)d_in[18];
    const float* b_mlp1  = (const float*)d_in[19];
    const float* w_mlp2  = (const float*)d_in[20];
    const float* b_mlp2  = (const float*)d_in[21];
    float* out = (float*)d_out;

    float *p_ab1, *p_g1, *p_ab2, *p_g2, *p_qkv, *p_x;
    __nv_bfloat16 *p_hh, *p_hl, *p_ah, *p_al, *p_mh, *p_ml;
    __nv_bfloat16 *p_wqh, *p_wql, *p_woh, *p_wol, *p_w1h, *p_w1l, *p_w2h, *p_w2l;
    cudaGetSymbolAddress((void**)&p_ab1, g_ab1);
    cudaGetSymbolAddress((void**)&p_ab2, g_ab2);
    cudaGetSymbolAddress((void**)&p_g1, g_g1);
    cudaGetSymbolAddress((void**)&p_g2, g_g2);
    cudaGetSymbolAddress((void**)&p_qkv, g_qkv);
    cudaGetSymbolAddress((void**)&p_x, g_x);
    cudaGetSymbolAddress((void**)&p_hh, g_h_h);
    cudaGetSymbolAddress((void**)&p_hl, g_h_l);
    cudaGetSymbolAddress((void**)&p_ah, g_attn_h);
    cudaGetSymbolAddress((void**)&p_al, g_attn_l);
    cudaGetSymbolAddress((void**)&p_mh, g_mlp_h);
    cudaGetSymbolAddress((void**)&p_ml, g_mlp_l);
    cudaGetSymbolAddress((void**)&p_wqh, g_wqkv_h);
    cudaGetSymbolAddress((void**)&p_wql, g_wqkv_l);
    cudaGetSymbolAddress((void**)&p_woh, g_wout_h);
    cudaGetSymbolAddress((void**)&p_wol, g_wout_l);
    cudaGetSymbolAddress((void**)&p_w1h, g_wm1_h);
    cudaGetSymbolAddress((void**)&p_w1l, g_wm1_l);
    cudaGetSymbolAddress((void**)&p_w2h, g_wm2_h);
    cudaGetSymbolAddress((void**)&p_w2l, g_wm2_l);

    cudaFuncSetAttribute(hgemm_k<0>, cudaFuncAttributeMaxDynamicSharedMemorySize, SMEM_TOT);
    cudaFuncSetAttribute(hgemm_k<1>, cudaFuncAttributeMaxDynamicSharedMemorySize, SMEM_TOT);
    cudaFuncSetAttribute(hgemm_k<2>, cudaFuncAttributeMaxDynamicSharedMemorySize, SMEM_TOT);
    cudaFuncSetAttribute(hgemm_k<3>, cudaFuncAttributeMaxDynamicSharedMemorySize, SMEM_TOT);

    // weight pre-split + cond path
    split_k<<<(1152 * 384 + 255) / 256, 256>>>(w_qkv, p_wqh, p_wql, 1152 * 384);
    split_k<<<(384 * 384 + 255) / 256, 256>>>(w_out, p_woh, p_wol, 384 * 384);
    split_k<<<(1536 * 384 + 255) / 256, 256>>>(w_mlp1, p_w1h, p_w1l, 1536 * 384);
    split_k<<<(384 * 1536 + 255) / 256, 256>>>(w_mlp2, p_w2h, p_w2l, 384 * 1536);
    silu_k<<<(NCELL * DIM + 255) / 256, 256>>>(cond);
    modall_k<<<dim3(NCELL, 2304 / 8), 256>>>(ada1_v, ada1_g, ada2_v, ada2_g,
                                             gate1_v, gate1_g, gate2_v, gate2_g);

    // branch 1: adaln -> qkv -> natten -> proj(+gate1, +residual)
    adaln_k<<<NTOK, DIM>>>(x, ln1_g, ln1_b, p_ab1);
    hgemm_k<0><<<dim3(1152 / 128, NTOK / 128), 256, SMEM_TOT>>>(
        p_hh, p_hl, p_wqh, p_wql, b_qkv, p_qkv, 384, 1152, nullptr, nullptr, nullptr, nullptr);
    natten_k<<<NTOK, NHEAD * 32>>>();
    hgemm_k<2><<<dim3(384 / 128, NTOK / 128), 256, SMEM_TOT>>>(
        p_ah, p_al, p_woh, p_wol, b_out, p_x, 384, 384, x, p_g1, nullptr, nullptr);

    // branch 2: adaln -> mlp1(gelu->bf16) -> mlp2(+gate2, +residual)
    adaln_k<<<NTOK, DIM>>>(p_x, ln2_g, ln2_b, p_ab2);
    hgemm_k<1><<<dim3(1536 / 128, NTOK / 128), 256, SMEM_TOT>>>(
        p_hh, p_hl, p_w1h, p_w1l, b_mlp1, nullptr, 384, 1536, nullptr, nullptr, p_mh, p_ml);
    hgemm_k<3><<<dim3(384 / 128, NTOK / 128), 256, SMEM_TOT>>>(
        p_mh, p_ml, p_w2h, p_w2l, b_mlp2, out, 1536, 384, p_x, p_g2, nullptr, nullptr);
}

// round 6
// speedup vs baseline: 2.0254x; 1.0348x over previous
#include <cuda_runtime.h>
#include <cuda_bf16.h>
#include <cstdint>
#include <math.h>

// Problem constants
#define NTOK 4608          // B*H*W = 2*48*48
#define DIM 384
#define HGT 48
#define WID 48
#define NCELL 72           // B*6*6
#define NHEAD 6
#define HD 64

// ---------------- scratch (device globals; no allocation allowed) -------------
__device__ float g_scond[NCELL * DIM];
__device__ float g_ab1[NCELL * 768];
__device__ float g_ab2[NCELL * 768];
__device__ float g_g1[NCELL * 384];
__device__ float g_g2[NCELL * 384];
__device__ float g_qkv[NTOK * 1152];
__device__ float g_x[NTOK * DIM];

// bf16 hi/lo pre-split buffers
__device__ __align__(16) __nv_bfloat16 g_wqkv_h[1152 * 384];
__device__ __align__(16) __nv_bfloat16 g_wqkv_l[1152 * 384];
__device__ __align__(16) __nv_bfloat16 g_wout_h[384 * 384];
__device__ __align__(16) __nv_bfloat16 g_wout_l[384 * 384];
__device__ __align__(16) __nv_bfloat16 g_wm1_h[1536 * 384];
__device__ __align__(16) __nv_bfloat16 g_wm1_l[1536 * 384];
__device__ __align__(16) __nv_bfloat16 g_wm2_h[384 * 1536];
__device__ __align__(16) __nv_bfloat16 g_wm2_l[384 * 1536];
__device__ __align__(16) __nv_bfloat16 g_h_h[NTOK * 384];
__device__ __align__(16) __nv_bfloat16 g_h_l[NTOK * 384];
__device__ __align__(16) __nv_bfloat16 g_attn_h[NTOK * 384];
__device__ __align__(16) __nv_bfloat16 g_attn_l[NTOK * 384];
__device__ __align__(16) __nv_bfloat16 g_mlp_h[NTOK * 1536];
__device__ __align__(16) __nv_bfloat16 g_mlp_l[NTOK * 1536];

// ---------------- helpers -----------------------------------------------------
__device__ __forceinline__ uint32_t smem_u32(const void* p) {
    uint32_t a;
    asm("{ .reg .u64 t; cvta.to.shared.u64 t, %1; cvt.u32.u64 %0, t; }" : "=r"(a) : "l"(p));
    return a;
}
__device__ __forceinline__ void cp16(uint32_t dst, const void* src) {
    asm volatile("cp.async.ca.shared.global [%0], [%1], 16;" :: "r"(dst), "l"(src));
}
#define CP_COMMIT() asm volatile("cp.async.commit_group;" ::: "memory")
template <int N> __device__ __forceinline__ void cp_wait() {
    asm volatile("cp.async.wait_group %0;" :: "n"(N) : "memory");
}
__device__ __forceinline__ void ldsm_x4(uint32_t* r, uint32_t addr) {
    asm volatile("ldmatrix.sync.aligned.m8n8.x4.shared.b16 {%0,%1,%2,%3}, [%4];"
                 : "=r"(r[0]), "=r"(r[1]), "=r"(r[2]), "=r"(r[3]) : "r"(addr));
}
__device__ __forceinline__ void mma_bf16(float* c, const uint32_t* a, const uint32_t* b) {
    asm volatile("mma.sync.aligned.m16n8k16.row.col.f32.bf16.bf16.f32 "
                 "{%0,%1,%2,%3}, {%4,%5,%6,%7}, {%8,%9}, {%0,%1,%2,%3};"
                 : "+f"(c[0]), "+f"(c[1]), "+f"(c[2]), "+f"(c[3])
                 : "r"(a[0]), "r"(a[1]), "r"(a[2]), "r"(a[3]), "r"(b[0]), "r"(b[1]));
}
__device__ __forceinline__ void split2(float v0, float v1,
                                       __nv_bfloat162& hi, __nv_bfloat162& lo) {
    hi = __float22bfloat162_rn(make_float2(v0, v1));
    float2 f = __bfloat1622float2(hi);
    lo = __float22bfloat162_rn(make_float2(v0 - f.x, v1 - f.y));
}

// ---------------- small prep kernels -----------------------------------------
__global__ void silu_k(const float* __restrict__ cond) {
    int i = blockIdx.x * blockDim.x + threadIdx.x;
    if (i < NCELL * DIM) {
        float v = cond[i];
        g_scond[i] = v / (1.0f + __expf(-v));
    }
}

// one launch splits all four weight matrices
#define S0 (1152 * 384)
#define S1 (384 * 384)
#define S2 (1536 * 384)
#define S3 (384 * 1536)
__global__ void split4_k(const float* __restrict__ w0, const float* __restrict__ w1,
                         const float* __restrict__ w2, const float* __restrict__ w3) {
    int i = blockIdx.x * blockDim.x + threadIdx.x;
    const float* src; __nv_bfloat16* hi; __nv_bfloat16* lo; int li;
    if (i < S0)                { src = w0; hi = g_wqkv_h; lo = g_wqkv_l; li = i; }
    else if (i < S0 + S1)      { src = w1; hi = g_wout_h; lo = g_wout_l; li = i - S0; }
    else if (i < S0 + S1 + S2) { src = w2; hi = g_wm1_h;  lo = g_wm1_l;  li = i - S0 - S1; }
    else if (i < S0 + S1 + S2 + S3)
                               { src = w3; hi = g_wm2_h;  lo = g_wm2_l;  li = i - S0 - S1 - S2; }
    else return;
    float v = src[li];
    __nv_bfloat16 h = __float2bfloat16(v);
    hi[li] = h;
    lo[li] = __float2bfloat16(v - __bfloat162float(h));
}

__global__ void modall_k(const float* __restrict__ a1v, const float* __restrict__ a1g,
                         const float* __restrict__ a2v, const float* __restrict__ a2g,
                         const float* __restrict__ g1v, const float* __restrict__ g1g,
                         const float* __restrict__ g2v, const float* __restrict__ g2g) {
    int cell = blockIdx.x;
    int r = blockIdx.y * 8 + (threadIdx.x >> 5);
    int lane = threadIdx.x & 31;
    const float* v; const float* g; float* out; int R; int rl;
    if (r < 768)       { rl = r;        v = a1v; g = a1g; out = g_ab1; R = 768; }
    else if (r < 1536) { rl = r - 768;  v = a2v; g = a2g; out = g_ab2; R = 768; }
    else if (r < 1920) { rl = r - 1536; v = g1v; g = g1g; out = g_g1;  R = 384; }
    else               { rl = r - 1920; v = g2v; g = g2g; out = g_g2;  R = 384; }
    const float* sc = g_scond + cell * DIM;
    const float* vr = v + rl * DIM;
    float p = 0.0f, n = 0.0f;
    for (int i = lane; i < DIM; i += 32) {
        float t = vr[i];
        p += sc[i] * t;
        n += t * t;
    }
    #pragma unroll
    for (int o = 16; o; o >>= 1) {
        p += __shfl_xor_sync(0xffffffffu, p, o);
        n += __shfl_xor_sync(0xffffffffu, n, o);
    }
    if (lane == 0) out[cell * R + rl] = g[rl] * rsqrtf(n) * p;
}

// adaLN -> writes bf16 hi/lo directly
__global__ void adaln_k(const float* __restrict__ x, const float* __restrict__ gamma,
                        const float* __restrict__ beta, const float* __restrict__ ab) {
    int t = blockIdx.x;
    int c = threadIdx.x;
    int wid = c >> 5, lane = c & 31;
    __shared__ float red[12];
    __shared__ float s_mu, s_var;
    float v = x[t * DIM + c];

    float s = v;
    #pragma unroll
    for (int o = 16; o; o >>= 1) s += __shfl_xor_sync(0xffffffffu, s, o);
    if (!lane) red[wid] = s;
    __syncthreads();
    if (c == 0) {
        float m = 0.0f;
        #pragma unroll
        for (int i = 0; i < 12; i++) m += red[i];
        s_mu = m * (1.0f / 384.0f);
    }
    __syncthreads();
    float mu = s_mu;
    float d = v - mu;
    s = d * d;
    #pragma unroll
    for (int o = 16; o; o >>= 1) s += __shfl_xor_sync(0xffffffffu, s, o);
    if (!lane) red[wid] = s;
    __syncthreads();
    if (c == 0) {
        float m = 0.0f;
        #pragma unroll
        for (int i = 0; i < 12; i++) m += red[i];
        s_var = m * (1.0f / 384.0f);
    }
    __syncthreads();

    float y = d * rsqrtf(s_var + 1e-6f) * gamma[c] + beta[c];
    int b = t / (HGT * WID);
    int rem = t % (HGT * WID);
    int hh = rem / WID, ww = rem % WID;
    int cell = b * 36 + (hh >> 3) * 6 + (ww >> 3);
    float a = ab[cell * 768 + c];
    float bb = ab[cell * 768 + 384 + c];
    float o = y * (1.0f + a) + bb;
    __nv_bfloat16 h = __float2bfloat16(o);
    g_h_h[t * DIM + c] = h;
    g_h_l[t * DIM + c] = __float2bfloat16(o - __bfloat162float(h));
}

// ================= cp.async 3-stage split-bf16 GEMM ============================
#define PITCH 40                 // bf16 per SMEM row (32 + 8 pad)
#define TILE_B 10240             // 128 * PITCH * 2
#define BUF_B  40960             // 4 tiles
#define SMEM_TOT (3 * BUF_B)     // 3 stages

template <int EPI>
__global__ void __launch_bounds__(256)
hgemm_k(const __nv_bfloat16* __restrict__ Ahp, const __nv_bfloat16* __restrict__ Alp,
        const __nv_bfloat16* __restrict__ Whp, const __nv_bfloat16* __restrict__ Wlp,
        const float* __restrict__ bias, float* __restrict__ C,
        int K, int M,
        const float* __restrict__ res, const float* __restrict__ gate,
        __nv_bfloat16* __restrict__ Oh, __nv_bfloat16* __restrict__ Ol) {
    extern __shared__ char smem[];
    const uint32_t sbase = smem_u32(smem);
    const int tid = threadIdx.x;
    const int lane = tid & 31;
    const int w = tid >> 5;
    const int wr = w >> 2;
    const int wc = w & 3;
    const int row0 = blockIdx.y * 128;
    const int col0 = blockIdx.x * 128;

    float acc[4][4][4];
    #pragma unroll
    for (int i = 0; i < 4; i++)
        #pragma unroll
        for (int j = 0; j < 4; j++)
            #pragma unroll
            for (int q = 0; q < 4; q++) acc[i][j][q] = 0.0f;

    const int ldrow = tid >> 1;
    const int lc = (tid & 1) * 32;
    const char* srcA_h = (const char*)(Ahp + (size_t)(row0 + ldrow) * K) + lc;
    const char* srcA_l = (const char*)(Alp + (size_t)(row0 + ldrow) * K) + lc;
    const char* srcW_h = (const char*)(Whp + (size_t)(col0 + ldrow) * K) + lc;
    const char* srcW_l = (const char*)(Wlp + (size_t)(col0 + ldrow) * K) + lc;
    const uint32_t dbase = sbase + ldrow * (PITCH * 2) + lc;

    const int nCh = K >> 5;

    auto issue = [&](int c) {
        const int bo = (c % 3) * BUF_B;
        const int go = c * 64;
        #pragma unroll
        for (int j = 0; j < 2; j++) {
            cp16(dbase + bo + 0 * TILE_B + j * 16, srcA_h + go + j * 16);
            cp16(dbase + bo + 1 * TILE_B + j * 16, srcA_l + go + j * 16);
            cp16(dbase + bo + 2 * TILE_B + j * 16, srcW_h + go + j * 16);
            cp16(dbase + bo + 3 * TILE_B + j * 16, srcW_l + go + j * 16);
        }
    };

    issue(0); CP_COMMIT();
    if (nCh > 1) issue(1);
    CP_COMMIT();

    const int arow = lane & 15;
    const int acolh = (lane >> 4) << 3;
    const int bnt2 = lane >> 4;
    const int bkh = (lane >> 3) & 1;
    const int brow = lane & 7;

    for (int c = 0; c < nCh; c++) {
        cp_wait<1>();
        __syncthreads();
        if (c + 2 < nCh) issue(c + 2);
        CP_COMMIT();

        const uint32_t bo = sbase + (c % 3) * BUF_B;
        const uint32_t uAh = bo, uAl = bo + TILE_B, uBh = bo + 2 * TILE_B, uBl = bo + 3 * TILE_B;

        #pragma unroll
        for (int ks = 0; ks < 2; ks++) {
            const int k0 = ks * 16;
            uint32_t ah[4][4], al[4][4], bh[4][2], bl[4][2];
            #pragma unroll
            for (int mt = 0; mt < 4; mt++) {
                uint32_t off = (uint32_t)((wr * 64 + mt * 16 + arow) * PITCH + k0 + acolh) * 2;
                ldsm_x4(ah[mt], uAh + off);
                ldsm_x4(al[mt], uAl + off);
            }
            #pragma unroll
            for (int ntp = 0; ntp < 2; ntp++) {
                uint32_t off = (uint32_t)((wc * 32 + (ntp * 2 + bnt2) * 8 + brow) * PITCH
                                          + k0 + bkh * 8) * 2;
                ldsm_x4(&bh[ntp * 2][0], uBh + off);
                ldsm_x4(&bl[ntp * 2][0], uBl + off);
            }
            #pragma unroll
            for (int mt = 0; mt < 4; mt++)
                #pragma unroll
                for (int nt = 0; nt < 4; nt++) {
                    mma_bf16(acc[mt][nt], ah[mt], bh[nt]);
                    mma_bf16(acc[mt][nt], ah[mt], bl[nt]);
                    mma_bf16(acc[mt][nt], al[mt], bh[nt]);
                }
        }
    }

    #pragma unroll
    for (int mt = 0; mt < 4; mt++) {
        #pragma unroll
        for (int half = 0; half < 2; half++) {
            const int r = row0 + wr * 64 + mt * 16 + (lane >> 2) + half * 8;
            const float* gt = nullptr;
            const float* rs = nullptr;
            if (EPI >= 2) {
                int b = r / (HGT * WID);
                int rem = r % (HGT * WID);
                int hh = rem / WID, ww = rem % WID;
                gt = gate + (b * 36 + (hh >> 3) * 6 + (ww >> 3)) * 384;
                rs = res + (size_t)r * 384;
            }
            #pragma unroll
            for (int nt = 0; nt < 4; nt++) {
                const int cc = col0 + wc * 32 + nt * 8 + (lane & 3) * 2;
                float v0 = acc[mt][nt][half * 2 + 0] + bias[cc];
                float v1 = acc[mt][nt][half * 2 + 1] + bias[cc + 1];
                if (EPI == 1) {
                    float x3 = v0 * v0 * v0;
                    v0 = 0.5f * v0 * (1.0f + tanhf(0.7978845608028654f * (v0 + 0.044715f * x3)));
                    x3 = v1 * v1 * v1;
                    v1 = 0.5f * v1 * (1.0f + tanhf(0.7978845608028654f * (v1 + 0.044715f * x3)));
                    __nv_bfloat162 hi, lo;
                    split2(v0, v1, hi, lo);
                    *(__nv_bfloat162*)(Oh + (size_t)r * M + cc) = hi;
                    *(__nv_bfloat162*)(Ol + (size_t)r * M + cc) = lo;
                } else if (EPI == 0) {
                    *(float2*)(C + (size_t)r * M + cc) = make_float2(v0, v1);
                } else {
                    float2 o;
                    o.x = rs[cc]     + v0 * gt[cc];
                    o.y = rs[cc + 1] + v1 * gt[cc + 1];
                    *(float2*)(C + (size_t)r * 384 + cc) = o;
                }
            }
        }
    }
}

// ================= tiled neighborhood attention ================================
// CTA = (8x8 token tile, head). K/V neighbor region (<=14x14 tokens) staged in SMEM.
#define NPITCH 66                      // floats per K/V row (64 + 2 pad)
#define NAT_KV (196 * NPITCH)          // floats per matrix
#define NAT_SMEM ((2 * NAT_KV + 8 * 64) * 4)

__global__ void __launch_bounds__(128) natten_k() {
    extern __shared__ float sm[];
    float* sK = sm;
    float* sV = sm + NAT_KV;
    float* sQ = sm + 2 * NAT_KV;       // 4 warps x 64
    float* sW = sQ + 4 * 64;           // 4 warps x 64

    const int tile = blockIdx.x;       // 0..71
    const int head = blockIdx.y;
    const int b = tile / 36;
    const int trm = tile % 36;
    const int t0h = (trm / 6) * 8;
    const int t0w = (trm % 6) * 8;
    const int rlo = max(0, t0h - 3);
    const int rhi = min(HGT - 1, t0h + 10);
    const int clo = max(0, t0w - 3);
    const int chi = min(WID - 1, t0w + 10);
    const int nr = rhi - rlo + 1;
    const int nc = chi - clo + 1;

    const int tid = threadIdx.x;
    // stage K/V (float2 granularity)
    const int tot = nr * nc * 32;
    for (int i = tid; i < tot; i += 128) {
        int li = i >> 5;
        int d2 = (i & 31) * 2;
        int row = li / nc, col = li % nc;
        size_t gbase = (size_t)((b * HGT + rlo + row) * WID + clo + col) * 1152 + head * HD + d2;
        float2 kv = *(const float2*)(g_qkv + gbase + 384);
        float2 vv = *(const float2*)(g_qkv + gbase + 768);
        int so = (row * 14 + col) * NPITCH + d2;
        *(float2*)(sK + so) = kv;
        *(float2*)(sV + so) = vv;
    }
    __syncthreads();

    const int wid = tid >> 5;
    const int lane = tid & 31;
    float* q = sQ + wid * 64;
    float* wb = sW + wid * 64;
    const int off1 = (lane / 7) * 14 + lane % 7;            // nb = lane (0..31)
    const int nb2 = lane + 32;
    const int off2 = (nb2 / 7) * 14 + nb2 % 7;              // valid if nb2 < 49
    const bool v2ok = nb2 < 49;

    for (int tt = wid * 16; tt < wid * 16 + 16; tt++) {
        const int tr = tt >> 3, tc = tt & 7;
        const int gr = t0h + tr, gc = t0w + tc;
        const int t = (b * HGT + gr) * WID + gc;
        // local window start
        const int sh = min(max(gr - 3, 0), HGT - 7) - rlo;
        const int sw = min(max(gc - 3, 0), WID - 7) - clo;
        const int base = sh * 14 + sw;

        // stage q
        *(float2*)(q + lane * 2) = *(const float2*)(g_qkv + (size_t)t * 1152 + head * HD + lane * 2);
        __syncwarp();

        // QK: lane computes logits for nb=lane and nb=lane+32
        float a1 = 0.0f, a2 = 0.0f;
        const float* k1 = sK + (base + off1) * NPITCH;
        const float* k2 = sK + (base + off2) * NPITCH;
        #pragma unroll
        for (int d = 0; d < 64; d += 2) {
            float2 qd = *(const float2*)(q + d);
            float2 x1 = *(const float2*)(k1 + d);
            float2 x2 = *(const float2*)(k2 + d);
            a1 += qd.x * x1.x + qd.y * x1.y;
            a2 += qd.x * x2.x + qd.y * x2.y;
        }
        a1 *= 0.125f;
        a2 = v2ok ? a2 * 0.125f : -1e30f;

        // softmax over 49
        float m = fmaxf(a1, a2);
        #pragma unroll
        for (int o = 16; o; o >>= 1) m = fmaxf(m, __shfl_xor_sync(0xffffffffu, m, o));
        float e1 = __expf(a1 - m);
        float e2 = v2ok ? __expf(a2 - m) : 0.0f;
        float s = e1 + e2;
        #pragma unroll
        for (int o = 16; o; o >>= 1) s += __shfl_xor_sync(0xffffffffu, s, o);
        float inv = 1.0f / s;
        wb[lane] = e1;
        wb[32 + lane] = e2;
        __syncwarp();

        // AV: lane owns dims 2*lane, 2*lane+1
        float o0 = 0.0f, o1 = 0.0f;
        #pragma unroll
        for (int nb = 0; nb < 49; nb++) {
            const int off = (nb / 7) * 14 + nb % 7;   // compile-time const per iter
            float wv = wb[nb];
            float2 vv = *(const float2*)(sV + (base + off) * NPITCH + lane * 2);
            o0 += wv * vv.x;
            o1 += wv * vv.y;
        }
        o0 *= inv; o1 *= inv;
        __nv_bfloat162 hi, lo;
        split2(o0, o1, hi, lo);
        *(__nv_bfloat162*)(g_attn_h + (size_t)t * DIM + head * HD + lane * 2) = hi;
        *(__nv_bfloat162*)(g_attn_l + (size_t)t * DIM + head * HD + lane * 2) = lo;
        __syncwarp();
    }
}

// ---------------- launch ------------------------------------------------------
extern "C" void kernel_launch(void* const* d_in, const int* in_sizes, int n_in,
                              void* d_out, int out_size) {
    const float* x       = (const float*)d_in[0];
    const float* cond    = (const float*)d_in[1];
    const float* ln1_g   = (const float*)d_in[2];
    const float* ln1_b   = (const float*)d_in[3];
    const float* ada1_v  = (const float*)d_in[4];
    const float* ada1_g  = (const float*)d_in[5];
    const float* ln2_g   = (const float*)d_in[6];
    const float* ln2_b   = (const float*)d_in[7];
    const float* ada2_v  = (const float*)d_in[8];
    const float* ada2_g  = (const float*)d_in[9];
    const float* gate1_v = (const float*)d_in[10];
    const float* gate1_g = (const float*)d_in[11];
    const float* gate2_v = (const float*)d_in[12];
    const float* gate2_g = (const float*)d_in[13];
    const float* w_qkv   = (const float*)d_in[14];
    const float* b_qkv   = (const float*)d_in[15];
    const float* w_out   = (const float*)d_in[16];
    const float* b_out   = (const float*)d_in[17];
    const float* w_mlp1  = (const float*)d_in[18];
    const float* b_mlp1  = (const float*)d_in[19];
    const float* w_mlp2  = (const float*)d_in[20];
    const float* b_mlp2  = (const float*)d_in[21];
    float* out = (float*)d_out;

    float *p_ab1, *p_g1, *p_ab2, *p_g2, *p_qkv, *p_x;
    __nv_bfloat16 *p_hh, *p_hl, *p_ah, *p_al, *p_mh, *p_ml;
    __nv_bfloat16 *p_wqh, *p_wql, *p_woh, *p_wol, *p_w1h, *p_w1l, *p_w2h, *p_w2l;
    cudaGetSymbolAddress((void**)&p_ab1, g_ab1);
    cudaGetSymbolAddress((void**)&p_ab2, g_ab2);
    cudaGetSymbolAddress((void**)&p_g1, g_g1);
    cudaGetSymbolAddress((void**)&p_g2, g_g2);
    cudaGetSymbolAddress((void**)&p_qkv, g_qkv);
    cudaGetSymbolAddress((void**)&p_x, g_x);
    cudaGetSymbolAddress((void**)&p_hh, g_h_h);
    cudaGetSymbolAddress((void**)&p_hl, g_h_l);
    cudaGetSymbolAddress((void**)&p_ah, g_attn_h);
    cudaGetSymbolAddress((void**)&p_al, g_attn_l);
    cudaGetSymbolAddress((void**)&p_mh, g_mlp_h);
    cudaGetSymbolAddress((void**)&p_ml, g_mlp_l);
    cudaGetSymbolAddress((void**)&p_wqh, g_wqkv_h);
    cudaGetSymbolAddress((void**)&p_wql, g_wqkv_l);
    cudaGetSymbolAddress((void**)&p_woh, g_wout_h);
    cudaGetSymbolAddress((void**)&p_wol, g_wout_l);
    cudaGetSymbolAddress((void**)&p_w1h, g_wm1_h);
    cudaGetSymbolAddress((void**)&p_w1l, g_wm1_l);
    cudaGetSymbolAddress((void**)&p_w2h, g_wm2_h);
    cudaGetSymbolAddress((void**)&p_w2l, g_wm2_l);

    cudaFuncSetAttribute(hgemm_k<0>, cudaFuncAttributeMaxDynamicSharedMemorySize, SMEM_TOT);
    cudaFuncSetAttribute(hgemm_k<1>, cudaFuncAttributeMaxDynamicSharedMemorySize, SMEM_TOT);
    cudaFuncSetAttribute(hgemm_k<2>, cudaFuncAttributeMaxDynamicSharedMemorySize, SMEM_TOT);
    cudaFuncSetAttribute(hgemm_k<3>, cudaFuncAttributeMaxDynamicSharedMemorySize, SMEM_TOT);
    cudaFuncSetAttribute(natten_k, cudaFuncAttributeMaxDynamicSharedMemorySize, NAT_SMEM);

    // weight pre-split + cond path
    split4_k<<<(S0 + S1 + S2 + S3 + 255) / 256, 256>>>(w_qkv, w_out, w_mlp1, w_mlp2);
    silu_k<<<(NCELL * DIM + 255) / 256, 256>>>(cond);
    modall_k<<<dim3(NCELL, 2304 / 8), 256>>>(ada1_v, ada1_g, ada2_v, ada2_g,
                                             gate1_v, gate1_g, gate2_v, gate2_g);

    // branch 1: adaln -> qkv -> natten -> proj(+gate1, +residual)
    adaln_k<<<NTOK, DIM>>>(x, ln1_g, ln1_b, p_ab1);
    hgemm_k<0><<<dim3(1152 / 128, NTOK / 128), 256, SMEM_TOT>>>(
        p_hh, p_hl, p_wqh, p_wql, b_qkv, p_qkv, 384, 1152, nullptr, nullptr, nullptr, nullptr);
    natten_k<<<dim3(72, NHEAD), 128, NAT_SMEM>>>();
    hgemm_k<2><<<dim3(384 / 128, NTOK / 128), 256, SMEM_TOT>>>(
        p_ah, p_al, p_woh, p_wol, b_out, p_x, 384, 384, x, p_g1, nullptr, nullptr);

    // branch 2: adaln -> mlp1(gelu->bf16) -> mlp2(+gate2, +residual)
    adaln_k<<<NTOK, DIM>>>(p_x, ln2_g, ln2_b, p_ab2);
    hgemm_k<1><<<dim3(1536 / 128, NTOK / 128), 256, SMEM_TOT>>>(
        p_hh, p_hl, p_w1h, p_w1l, b_mlp1, nullptr, 384, 1536, nullptr, nullptr, p_mh, p_ml);
    hgemm_k<3><<<dim3(384 / 128, NTOK / 128), 256, SMEM_TOT>>>(
        p_mh, p_ml, p_w2h, p_w2l, b_mlp2, out, 1536, 384, p_x, p_g2, nullptr, nullptr);
}

// round 7
// speedup vs baseline: 2.0771x; 1.0256x over previous
#include <cuda_runtime.h>
#include <cuda_bf16.h>
#include <cstdint>
#include <math.h>

// Problem constants
#define NTOK 4608          // B*H*W = 2*48*48
#define DIM 384
#define HGT 48
#define WID 48
#define NCELL 72           // B*6*6
#define NHEAD 6
#define HD 64

// ---------------- scratch (device globals; no allocation allowed) -------------
__device__ float g_scond[NCELL * DIM];
__device__ float g_ab1[NCELL * 768];
__device__ float g_ab2[NCELL * 768];
__device__ float g_g1[NCELL * 384];
__device__ float g_g2[NCELL * 384];
__device__ float g_qkv[NTOK * 1152];
__device__ float g_x[NTOK * DIM];

// bf16 hi/lo pre-split buffers
__device__ __align__(16) __nv_bfloat16 g_wqkv_h[1152 * 384];
__device__ __align__(16) __nv_bfloat16 g_wqkv_l[1152 * 384];
__device__ __align__(16) __nv_bfloat16 g_wout_h[384 * 384];
__device__ __align__(16) __nv_bfloat16 g_wout_l[384 * 384];
__device__ __align__(16) __nv_bfloat16 g_wm1_h[1536 * 384];
__device__ __align__(16) __nv_bfloat16 g_wm1_l[1536 * 384];
__device__ __align__(16) __nv_bfloat16 g_wm2_h[384 * 1536];
__device__ __align__(16) __nv_bfloat16 g_wm2_l[384 * 1536];
__device__ __align__(16) __nv_bfloat16 g_h_h[NTOK * 384];
__device__ __align__(16) __nv_bfloat16 g_h_l[NTOK * 384];
__device__ __align__(16) __nv_bfloat16 g_attn_h[NTOK * 384];
__device__ __align__(16) __nv_bfloat16 g_attn_l[NTOK * 384];
__device__ __align__(16) __nv_bfloat16 g_mlp_h[NTOK * 1536];
__device__ __align__(16) __nv_bfloat16 g_mlp_l[NTOK * 1536];

// ---------------- helpers -----------------------------------------------------
__device__ __forceinline__ uint32_t smem_u32(const void* p) {
    uint32_t a;
    asm("{ .reg .u64 t; cvta.to.shared.u64 t, %1; cvt.u32.u64 %0, t; }" : "=r"(a) : "l"(p));
    return a;
}
__device__ __forceinline__ void cp16(uint32_t dst, const void* src) {
    asm volatile("cp.async.ca.shared.global [%0], [%1], 16;" :: "r"(dst), "l"(src));
}
#define CP_COMMIT() asm volatile("cp.async.commit_group;" ::: "memory")
template <int N> __device__ __forceinline__ void cp_wait() {
    asm volatile("cp.async.wait_group %0;" :: "n"(N) : "memory");
}
__device__ __forceinline__ void ldsm_x4(uint32_t* r, uint32_t addr) {
    asm volatile("ldmatrix.sync.aligned.m8n8.x4.shared.b16 {%0,%1,%2,%3}, [%4];"
                 : "=r"(r[0]), "=r"(r[1]), "=r"(r[2]), "=r"(r[3]) : "r"(addr));
}
__device__ __forceinline__ void mma_bf16(float* c, const uint32_t* a, const uint32_t* b) {
    asm volatile("mma.sync.aligned.m16n8k16.row.col.f32.bf16.bf16.f32 "
                 "{%0,%1,%2,%3}, {%4,%5,%6,%7}, {%8,%9}, {%0,%1,%2,%3};"
                 : "+f"(c[0]), "+f"(c[1]), "+f"(c[2]), "+f"(c[3])
                 : "r"(a[0]), "r"(a[1]), "r"(a[2]), "r"(a[3]), "r"(b[0]), "r"(b[1]));
}
__device__ __forceinline__ void split2(float v0, float v1,
                                       __nv_bfloat162& hi, __nv_bfloat162& lo) {
    hi = __float22bfloat162_rn(make_float2(v0, v1));
    float2 f = __bfloat1622float2(hi);
    lo = __float22bfloat162_rn(make_float2(v0 - f.x, v1 - f.y));
}

// ---------------- small prep kernels -----------------------------------------
__global__ void silu_k(const float* __restrict__ cond) {
    int i = blockIdx.x * blockDim.x + threadIdx.x;
    if (i < NCELL * DIM) {
        float v = cond[i];
        g_scond[i] = v / (1.0f + __expf(-v));
    }
}

#define S0 (1152 * 384)
#define S1 (384 * 384)
#define S2 (1536 * 384)
#define S3 (384 * 1536)
__global__ void split4_k(const float* __restrict__ w0, const float* __restrict__ w1,
                         const float* __restrict__ w2, const float* __restrict__ w3) {
    int i = blockIdx.x * blockDim.x + threadIdx.x;
    const float* src; __nv_bfloat16* hi; __nv_bfloat16* lo; int li;
    if (i < S0)                { src = w0; hi = g_wqkv_h; lo = g_wqkv_l; li = i; }
    else if (i < S0 + S1)      { src = w1; hi = g_wout_h; lo = g_wout_l; li = i - S0; }
    else if (i < S0 + S1 + S2) { src = w2; hi = g_wm1_h;  lo = g_wm1_l;  li = i - S0 - S1; }
    else if (i < S0 + S1 + S2 + S3)
                               { src = w3; hi = g_wm2_h;  lo = g_wm2_l;  li = i - S0 - S1 - S2; }
    else return;
    float v = src[li];
    __nv_bfloat16 h = __float2bfloat16(v);
    hi[li] = h;
    lo[li] = __float2bfloat16(v - __bfloat162float(h));
}

__global__ void modall_k(const float* __restrict__ a1v, const float* __restrict__ a1g,
                         const float* __restrict__ a2v, const float* __restrict__ a2g,
                         const float* __restrict__ g1v, const float* __restrict__ g1g,
                         const float* __restrict__ g2v, const float* __restrict__ g2g) {
    int cell = blockIdx.x;
    int r = blockIdx.y * 8 + (threadIdx.x >> 5);
    int lane = threadIdx.x & 31;
    const float* v; const float* g; float* out; int R; int rl;
    if (r < 768)       { rl = r;        v = a1v; g = a1g; out = g_ab1; R = 768; }
    else if (r < 1536) { rl = r - 768;  v = a2v; g = a2g; out = g_ab2; R = 768; }
    else if (r < 1920) { rl = r - 1536; v = g1v; g = g1g; out = g_g1;  R = 384; }
    else               { rl = r - 1920; v = g2v; g = g2g; out = g_g2;  R = 384; }
    const float* sc = g_scond + cell * DIM;
    const float* vr = v + rl * DIM;
    float p = 0.0f, n = 0.0f;
    for (int i = lane; i < DIM; i += 32) {
        float t = vr[i];
        p += sc[i] * t;
        n += t * t;
    }
    #pragma unroll
    for (int o = 16; o; o >>= 1) {
        p += __shfl_xor_sync(0xffffffffu, p, o);
        n += __shfl_xor_sync(0xffffffffu, n, o);
    }
    if (lane == 0) out[cell * R + rl] = g[rl] * rsqrtf(n) * p;
}

// adaLN, warp-per-token -> writes bf16 hi/lo
__global__ void __launch_bounds__(256) adaln_k(const float* __restrict__ x,
                                               const float* __restrict__ gamma,
                                               const float* __restrict__ beta,
                                               const float* __restrict__ ab) {
    const int t = blockIdx.x * 8 + (threadIdx.x >> 5);
    const int lane = threadIdx.x & 31;
    const float* xr = x + (size_t)t * DIM;

    float2 v[6];
    float s = 0.0f;
    #pragma unroll
    for (int j = 0; j < 6; j++) {
        v[j] = *(const float2*)(xr + j * 64 + lane * 2);
        s += v[j].x + v[j].y;
    }
    #pragma unroll
    for (int o = 16; o; o >>= 1) s += __shfl_xor_sync(0xffffffffu, s, o);
    const float mu = s * (1.0f / 384.0f);

    float q = 0.0f;
    #pragma unroll
    for (int j = 0; j < 6; j++) {
        float dx = v[j].x - mu, dy = v[j].y - mu;
        q += dx * dx + dy * dy;
    }
    #pragma unroll
    for (int o = 16; o; o >>= 1) q += __shfl_xor_sync(0xffffffffu, q, o);
    const float rstd = rsqrtf(q * (1.0f / 384.0f) + 1e-6f);

    const int b = t / (HGT * WID);
    const int rem = t % (HGT * WID);
    const int cell = b * 36 + ((rem / WID) >> 3) * 6 + ((rem % WID) >> 3);
    const float* abp = ab + cell * 768;

    #pragma unroll
    for (int j = 0; j < 6; j++) {
        const int c = j * 64 + lane * 2;
        float2 gm = *(const float2*)(gamma + c);
        float2 bt = *(const float2*)(beta + c);
        float2 aa = *(const float2*)(abp + c);
        float2 bb = *(const float2*)(abp + 384 + c);
        float y0 = (v[j].x - mu) * rstd * gm.x + bt.x;
        float y1 = (v[j].y - mu) * rstd * gm.y + bt.y;
        y0 = y0 * (1.0f + aa.x) + bb.x;
        y1 = y1 * (1.0f + aa.y) + bb.y;
        __nv_bfloat162 hi, lo;
        split2(y0, y1, hi, lo);
        *(__nv_bfloat162*)(g_h_h + (size_t)t * DIM + c) = hi;
        *(__nv_bfloat162*)(g_h_l + (size_t)t * DIM + c) = lo;
    }
}

// ================= cp.async 3-stage split-bf16 GEMM ============================
#define PITCH 40                 // bf16 per SMEM row (32 + 8 pad)
#define TILE_B 10240             // 128 * PITCH * 2
#define BUF_B  40960             // 4 tiles
#define SMEM_TOT (3 * BUF_B)     // 3 stages

template <int EPI>
__global__ void __launch_bounds__(256)
hgemm_k(const __nv_bfloat16* __restrict__ Ahp, const __nv_bfloat16* __restrict__ Alp,
        const __nv_bfloat16* __restrict__ Whp, const __nv_bfloat16* __restrict__ Wlp,
        const float* __restrict__ bias, float* __restrict__ C,
        int K, int M,
        const float* __restrict__ res, const float* __restrict__ gate,
        __nv_bfloat16* __restrict__ Oh, __nv_bfloat16* __restrict__ Ol) {
    extern __shared__ char smem[];
    const uint32_t sbase = smem_u32(smem);
    const int tid = threadIdx.x;
    const int lane = tid & 31;
    const int w = tid >> 5;
    const int wr = w >> 2;
    const int wc = w & 3;
    const int row0 = blockIdx.y * 128;
    const int col0 = blockIdx.x * 128;

    float acc[4][4][4];
    #pragma unroll
    for (int i = 0; i < 4; i++)
        #pragma unroll
        for (int j = 0; j < 4; j++)
            #pragma unroll
            for (int q = 0; q < 4; q++) acc[i][j][q] = 0.0f;

    const int ldrow = tid >> 1;
    const int lc = (tid & 1) * 32;
    const char* srcA_h = (const char*)(Ahp + (size_t)(row0 + ldrow) * K) + lc;
    const char* srcA_l = (const char*)(Alp + (size_t)(row0 + ldrow) * K) + lc;
    const char* srcW_h = (const char*)(Whp + (size_t)(col0 + ldrow) * K) + lc;
    const char* srcW_l = (const char*)(Wlp + (size_t)(col0 + ldrow) * K) + lc;
    const uint32_t dbase = sbase + ldrow * (PITCH * 2) + lc;

    const int nCh = K >> 5;

    auto issue = [&](int c) {
        const int bo = (c % 3) * BUF_B;
        const int go = c * 64;
        #pragma unroll
        for (int j = 0; j < 2; j++) {
            cp16(dbase + bo + 0 * TILE_B + j * 16, srcA_h + go + j * 16);
            cp16(dbase + bo + 1 * TILE_B + j * 16, srcA_l + go + j * 16);
            cp16(dbase + bo + 2 * TILE_B + j * 16, srcW_h + go + j * 16);
            cp16(dbase + bo + 3 * TILE_B + j * 16, srcW_l + go + j * 16);
        }
    };

    issue(0); CP_COMMIT();
    if (nCh > 1) issue(1);
    CP_COMMIT();

    const int arow = lane & 15;
    const int acolh = (lane >> 4) << 3;
    const int bnt2 = lane >> 4;
    const int bkh = (lane >> 3) & 1;
    const int brow = lane & 7;

    for (int c = 0; c < nCh; c++) {
        cp_wait<1>();
        __syncthreads();
        if (c + 2 < nCh) issue(c + 2);
        CP_COMMIT();

        const uint32_t bo = sbase + (c % 3) * BUF_B;
        const uint32_t uAh = bo, uAl = bo + TILE_B, uBh = bo + 2 * TILE_B, uBl = bo + 3 * TILE_B;

        // hoist ALL fragment loads for both k16 steps, then run 96 back-to-back mma
        uint32_t ah[2][4][4], al[2][4][4], bh[2][4][2], bl[2][4][2];
        #pragma unroll
        for (int ks = 0; ks < 2; ks++) {
            const int k0 = ks * 16;
            #pragma unroll
            for (int mt = 0; mt < 4; mt++) {
                uint32_t off = (uint32_t)((wr * 64 + mt * 16 + arow) * PITCH + k0 + acolh) * 2;
                ldsm_x4(ah[ks][mt], uAh + off);
                ldsm_x4(al[ks][mt], uAl + off);
            }
            #pragma unroll
            for (int ntp = 0; ntp < 2; ntp++) {
                uint32_t off = (uint32_t)((wc * 32 + (ntp * 2 + bnt2) * 8 + brow) * PITCH
                                          + k0 + bkh * 8) * 2;
                ldsm_x4(&bh[ks][ntp * 2][0], uBh + off);
                ldsm_x4(&bl[ks][ntp * 2][0], uBl + off);
            }
        }
        #pragma unroll
        for (int ks = 0; ks < 2; ks++)
            #pragma unroll
            for (int mt = 0; mt < 4; mt++)
                #pragma unroll
                for (int nt = 0; nt < 4; nt++) {
                    mma_bf16(acc[mt][nt], ah[ks][mt], bh[ks][nt]);
                    mma_bf16(acc[mt][nt], ah[ks][mt], bl[ks][nt]);
                    mma_bf16(acc[mt][nt], al[ks][mt], bh[ks][nt]);
                }
    }

    #pragma unroll
    for (int mt = 0; mt < 4; mt++) {
        #pragma unroll
        for (int half = 0; half < 2; half++) {
            const int r = row0 + wr * 64 + mt * 16 + (lane >> 2) + half * 8;
            const float* gt = nullptr;
            const float* rs = nullptr;
            if (EPI >= 2) {
                int b = r / (HGT * WID);
                int rem = r % (HGT * WID);
                int hh = rem / WID, ww = rem % WID;
                gt = gate + (b * 36 + (hh >> 3) * 6 + (ww >> 3)) * 384;
                rs = res + (size_t)r * 384;
            }
            #pragma unroll
            for (int nt = 0; nt < 4; nt++) {
                const int cc = col0 + wc * 32 + nt * 8 + (lane & 3) * 2;
                float v0 = acc[mt][nt][half * 2 + 0] + bias[cc];
                float v1 = acc[mt][nt][half * 2 + 1] + bias[cc + 1];
                if (EPI == 1) {
                    float x3 = v0 * v0 * v0;
                    v0 = 0.5f * v0 * (1.0f + tanhf(0.7978845608028654f * (v0 + 0.044715f * x3)));
                    x3 = v1 * v1 * v1;
                    v1 = 0.5f * v1 * (1.0f + tanhf(0.7978845608028654f * (v1 + 0.044715f * x3)));
                    __nv_bfloat162 hi, lo;
                    split2(v0, v1, hi, lo);
                    *(__nv_bfloat162*)(Oh + (size_t)r * M + cc) = hi;
                    *(__nv_bfloat162*)(Ol + (size_t)r * M + cc) = lo;
                } else if (EPI == 0) {
                    *(float2*)(C + (size_t)r * M + cc) = make_float2(v0, v1);
                } else {
                    float2 o;
                    o.x = rs[cc]     + v0 * gt[cc];
                    o.y = rs[cc + 1] + v1 * gt[cc + 1];
                    *(float2*)(C + (size_t)r * 384 + cc) = o;
                }
            }
        }
    }
}

// ================= tiled neighborhood attention ================================
#define NPITCH 66
#define NAT_KV (196 * NPITCH)
#define NAT_SMEM ((2 * NAT_KV + 8 * 64) * 4)

__global__ void __launch_bounds__(128) natten_k() {
    extern __shared__ float sm[];
    float* sK = sm;
    float* sV = sm + NAT_KV;
    float* sQ = sm + 2 * NAT_KV;
    float* sW = sQ + 4 * 64;

    const int tile = blockIdx.x;
    const int head = blockIdx.y;
    const int b = tile / 36;
    const int trm = tile % 36;
    const int t0h = (trm / 6) * 8;
    const int t0w = (trm % 6) * 8;
    const int rlo = max(0, t0h - 3);
    const int rhi = min(HGT - 1, t0h + 10);
    const int clo = max(0, t0w - 3);
    const int chi = min(WID - 1, t0w + 10);
    const int nr = rhi - rlo + 1;
    const int nc = chi - clo + 1;

    const int tid = threadIdx.x;
    const int tot = nr * nc * 32;
    for (int i = tid; i < tot; i += 128) {
        int li = i >> 5;
        int d2 = (i & 31) * 2;
        int row = li / nc, col = li % nc;
        size_t gbase = (size_t)((b * HGT + rlo + row) * WID + clo + col) * 1152 + head * HD + d2;
        float2 kv = *(const float2*)(g_qkv + gbase + 384);
        float2 vv = *(const float2*)(g_qkv + gbase + 768);
        int so = (row * 14 + col) * NPITCH + d2;
        *(float2*)(sK + so) = kv;
        *(float2*)(sV + so) = vv;
    }
    __syncthreads();

    const int wid = tid >> 5;
    const int lane = tid & 31;
    float* q = sQ + wid * 64;
    float* wb = sW + wid * 64;
    const int off1 = (lane / 7) * 14 + lane % 7;
    const int nb2 = lane + 32;
    const int off2 = (nb2 / 7) * 14 + nb2 % 7;
    const bool v2ok = nb2 < 49;

    for (int tt = wid * 16; tt < wid * 16 + 16; tt++) {
        const int tr = tt >> 3, tc = tt & 7;
        const int gr = t0h + tr, gc = t0w + tc;
        const int t = (b * HGT + gr) * WID + gc;
        const int sh = min(max(gr - 3, 0), HGT - 7) - rlo;
        const int sw = min(max(gc - 3, 0), WID - 7) - clo;
        const int base = sh * 14 + sw;

        *(float2*)(q + lane * 2) = *(const float2*)(g_qkv + (size_t)t * 1152 + head * HD + lane * 2);
        __syncwarp();

        float a1 = 0.0f, a2 = 0.0f;
        const float* k1 = sK + (base + off1) * NPITCH;
        const float* k2 = sK + (base + off2) * NPITCH;
        #pragma unroll
        for (int d = 0; d < 64; d += 2) {
            float2 qd = *(const float2*)(q + d);
            float2 x1 = *(const float2*)(k1 + d);
            float2 x2 = *(const float2*)(k2 + d);
            a1 += qd.x * x1.x + qd.y * x1.y;
            a2 += qd.x * x2.x + qd.y * x2.y;
        }
        a1 *= 0.125f;
        a2 = v2ok ? a2 * 0.125f : -1e30f;

        float m = fmaxf(a1, a2);
        #pragma unroll
        for (int o = 16; o; o >>= 1) m = fmaxf(m, __shfl_xor_sync(0xffffffffu, m, o));
        float e1 = __expf(a1 - m);
        float e2 = v2ok ? __expf(a2 - m) : 0.0f;
        float s = e1 + e2;
        #pragma unroll
        for (int o = 16; o; o >>= 1) s += __shfl_xor_sync(0xffffffffu, s, o);
        float inv = 1.0f / s;
        wb[lane] = e1;
        wb[32 + lane] = e2;
        __syncwarp();

        float o0 = 0.0f, o1 = 0.0f;
        #pragma unroll
        for (int nb = 0; nb < 49; nb++) {
            const int off = (nb / 7) * 14 + nb % 7;
            float wv = wb[nb];
            float2 vv = *(const float2*)(sV + (base + off) * NPITCH + lane * 2);
            o0 += wv * vv.x;
            o1 += wv * vv.y;
        }
        o0 *= inv; o1 *= inv;
        __nv_bfloat162 hi, lo;
        split2(o0, o1, hi, lo);
        *(__nv_bfloat162*)(g_attn_h + (size_t)t * DIM + head * HD + lane * 2) = hi;
        *(__nv_bfloat162*)(g_attn_l + (size_t)t * DIM + head * HD + lane * 2) = lo;
        __syncwarp();
    }
}

// ---------------- launch ------------------------------------------------------
extern "C" void kernel_launch(void* const* d_in, const int* in_sizes, int n_in,
                              void* d_out, int out_size) {
    const float* x       = (const float*)d_in[0];
    const float* cond    = (const float*)d_in[1];
    const float* ln1_g   = (const float*)d_in[2];
    const float* ln1_b   = (const float*)d_in[3];
    const float* ada1_v  = (const float*)d_in[4];
    const float* ada1_g  = (const float*)d_in[5];
    const float* ln2_g   = (const float*)d_in[6];
    const float* ln2_b   = (const float*)d_in[7];
    const float* ada2_v  = (const float*)d_in[8];
    const float* ada2_g  = (const float*)d_in[9];
    const float* gate1_v = (const float*)d_in[10];
    const float* gate1_g = (const float*)d_in[11];
    const float* gate2_v = (const float*)d_in[12];
    const float* gate2_g = (const float*)d_in[13];
    const float* w_qkv   = (const float*)d_in[14];
    const float* b_qkv   = (const float*)d_in[15];
    const float* w_out   = (const float*)d_in[16];
    const float* b_out   = (const float*)d_in[17];
    const float* w_mlp1  = (const float*)d_in[18];
    const float* b_mlp1  = (const float*)d_in[19];
    const float* w_mlp2  = (const float*)d_in[20];
    const float* b_mlp2  = (const float*)d_in[21];
    float* out = (float*)d_out;

    float *p_ab1, *p_g1, *p_ab2, *p_g2, *p_qkv, *p_x;
    __nv_bfloat16 *p_hh, *p_hl, *p_ah, *p_al, *p_mh, *p_ml;
    __nv_bfloat16 *p_wqh, *p_wql, *p_woh, *p_wol, *p_w1h, *p_w1l, *p_w2h, *p_w2l;
    cudaGetSymbolAddress((void**)&p_ab1, g_ab1);
    cudaGetSymbolAddress((void**)&p_ab2, g_ab2);
    cudaGetSymbolAddress((void**)&p_g1, g_g1);
    cudaGetSymbolAddress((void**)&p_g2, g_g2);
    cudaGetSymbolAddress((void**)&p_qkv, g_qkv);
    cudaGetSymbolAddress((void**)&p_x, g_x);
    cudaGetSymbolAddress((void**)&p_hh, g_h_h);
    cudaGetSymbolAddress((void**)&p_hl, g_h_l);
    cudaGetSymbolAddress((void**)&p_ah, g_attn_h);
    cudaGetSymbolAddress((void**)&p_al, g_attn_l);
    cudaGetSymbolAddress((void**)&p_mh, g_mlp_h);
    cudaGetSymbolAddress((void**)&p_ml, g_mlp_l);
    cudaGetSymbolAddress((void**)&p_wqh, g_wqkv_h);
    cudaGetSymbolAddress((void**)&p_wql, g_wqkv_l);
    cudaGetSymbolAddress((void**)&p_woh, g_wout_h);
    cudaGetSymbolAddress((void**)&p_wol, g_wout_l);
    cudaGetSymbolAddress((void**)&p_w1h, g_wm1_h);
    cudaGetSymbolAddress((void**)&p_w1l, g_wm1_l);
    cudaGetSymbolAddress((void**)&p_w2h, g_wm2_h);
    cudaGetSymbolAddress((void**)&p_w2l, g_wm2_l);

    cudaFuncSetAttribute(hgemm_k<0>, cudaFuncAttributeMaxDynamicSharedMemorySize, SMEM_TOT);
    cudaFuncSetAttribute(hgemm_k<1>, cudaFuncAttributeMaxDynamicSharedMemorySize, SMEM_TOT);
    cudaFuncSetAttribute(hgemm_k<2>, cudaFuncAttributeMaxDynamicSharedMemorySize, SMEM_TOT);
    cudaFuncSetAttribute(hgemm_k<3>, cudaFuncAttributeMaxDynamicSharedMemorySize, SMEM_TOT);
    cudaFuncSetAttribute(natten_k, cudaFuncAttributeMaxDynamicSharedMemorySize, NAT_SMEM);

    split4_k<<<(S0 + S1 + S2 + S3 + 255) / 256, 256>>>(w_qkv, w_out, w_mlp1, w_mlp2);
    silu_k<<<(NCELL * DIM + 255) / 256, 256>>>(cond);
    modall_k<<<dim3(NCELL, 2304 / 8), 256>>>(ada1_v, ada1_g, ada2_v, ada2_g,
                                             gate1_v, gate1_g, gate2_v, gate2_g);

    adaln_k<<<NTOK / 8, 256>>>(x, ln1_g, ln1_b, p_ab1);
    hgemm_k<0><<<dim3(1152 / 128, NTOK / 128), 256, SMEM_TOT>>>(
        p_hh, p_hl, p_wqh, p_wql, b_qkv, p_qkv, 384, 1152, nullptr, nullptr, nullptr, nullptr);
    natten_k<<<dim3(72, NHEAD), 128, NAT_SMEM>>>();
    hgemm_k<2><<<dim3(384 / 128, NTOK / 128), 256, SMEM_TOT>>>(
        p_ah, p_al, p_woh, p_wol, b_out, p_x, 384, 384, x, p_g1, nullptr, nullptr);

    adaln_k<<<NTOK / 8, 256>>>(p_x, ln2_g, ln2_b, p_ab2);
    hgemm_k<1><<<dim3(1536 / 128, NTOK / 128), 256, SMEM_TOT>>>(
        p_hh, p_hl, p_w1h, p_w1l, b_mlp1, nullptr, 384, 1536, nullptr, nullptr, p_mh, p_ml);
    hgemm_k<3><<<dim3(384 / 128, NTOK / 128), 256, SMEM_TOT>>>(
        p_mh, p_ml, p_w2h, p_w2l, b_mlp2, out, 1536, 384, p_x, p_g2, nullptr, nullptr);
}

// round 8
// speedup vs baseline: 2.6511x; 1.2763x over previous
#include <cuda_runtime.h>
#include <cuda_fp16.h>
#include <cstdint>
#include <math.h>

// Problem constants
#define NTOK 4608          // B*H*W = 2*48*48
#define DIM 384
#define HGT 48
#define WID 48
#define NCELL 72           // B*6*6
#define NHEAD 6
#define HD 64

// ---------------- scratch (device globals; no allocation allowed) -------------
__device__ float g_scond[NCELL * DIM];
__device__ float g_ab1[NCELL * 768];
__device__ float g_ab2[NCELL * 768];
__device__ float g_g1[NCELL * 384];
__device__ float g_g2[NCELL * 384];
__device__ float g_qkv[NTOK * 1152];
__device__ float g_x[NTOK * DIM];

// fp16 weights (hi/lo split) and fp16 activations (single)
__device__ __align__(16) __half g_wqkv_h[1152 * 384];
__device__ __align__(16) __half g_wqkv_l[1152 * 384];
__device__ __align__(16) __half g_wout_h[384 * 384];
__device__ __align__(16) __half g_wout_l[384 * 384];
__device__ __align__(16) __half g_wm1_h[1536 * 384];
__device__ __align__(16) __half g_wm1_l[1536 * 384];
__device__ __align__(16) __half g_wm2_h[384 * 1536];
__device__ __align__(16) __half g_wm2_l[384 * 1536];
__device__ __align__(16) __half g_h[NTOK * 384];
__device__ __align__(16) __half g_attn[NTOK * 384];
__device__ __align__(16) __half g_mlp[NTOK * 1536];

// ---------------- helpers -----------------------------------------------------
__device__ __forceinline__ uint32_t smem_u32(const void* p) {
    uint32_t a;
    asm("{ .reg .u64 t; cvta.to.shared.u64 t, %1; cvt.u32.u64 %0, t; }" : "=r"(a) : "l"(p));
    return a;
}
__device__ __forceinline__ void cp16(uint32_t dst, const void* src) {
    asm volatile("cp.async.ca.shared.global [%0], [%1], 16;" :: "r"(dst), "l"(src));
}
#define CP_COMMIT() asm volatile("cp.async.commit_group;" ::: "memory")
template <int N> __device__ __forceinline__ void cp_wait() {
    asm volatile("cp.async.wait_group %0;" :: "n"(N) : "memory");
}
__device__ __forceinline__ void ldsm_x4(uint32_t* r, uint32_t addr) {
    asm volatile("ldmatrix.sync.aligned.m8n8.x4.shared.b16 {%0,%1,%2,%3}, [%4];"
                 : "=r"(r[0]), "=r"(r[1]), "=r"(r[2]), "=r"(r[3]) : "r"(addr));
}
__device__ __forceinline__ void mma_f16(float* c, const uint32_t* a, const uint32_t* b) {
    asm volatile("mma.sync.aligned.m16n8k16.row.col.f32.f16.f16.f32 "
                 "{%0,%1,%2,%3}, {%4,%5,%6,%7}, {%8,%9}, {%0,%1,%2,%3};"
                 : "+f"(c[0]), "+f"(c[1]), "+f"(c[2]), "+f"(c[3])
                 : "r"(a[0]), "r"(a[1]), "r"(a[2]), "r"(a[3]), "r"(b[0]), "r"(b[1]));
}

// ---------------- small prep kernels -----------------------------------------
__global__ void silu_k(const float* __restrict__ cond) {
    int i = blockIdx.x * blockDim.x + threadIdx.x;
    if (i < NCELL * DIM) {
        float v = cond[i];
        g_scond[i] = v / (1.0f + __expf(-v));
    }
}

#define S0 (1152 * 384)
#define S1 (384 * 384)
#define S2 (1536 * 384)
#define S3 (384 * 1536)
__global__ void split4_k(const float* __restrict__ w0, const float* __restrict__ w1,
                         const float* __restrict__ w2, const float* __restrict__ w3) {
    int i = blockIdx.x * blockDim.x + threadIdx.x;
    const float* src; __half* hi; __half* lo; int li;
    if (i < S0)                { src = w0; hi = g_wqkv_h; lo = g_wqkv_l; li = i; }
    else if (i < S0 + S1)      { src = w1; hi = g_wout_h; lo = g_wout_l; li = i - S0; }
    else if (i < S0 + S1 + S2) { src = w2; hi = g_wm1_h;  lo = g_wm1_l;  li = i - S0 - S1; }
    else if (i < S0 + S1 + S2 + S3)
                               { src = w3; hi = g_wm2_h;  lo = g_wm2_l;  li = i - S0 - S1 - S2; }
    else return;
    float v = src[li];
    __half h = __float2half_rn(v);
    hi[li] = h;
    lo[li] = __float2half_rn(v - __half2float(h));
}

__global__ void modall_k(const float* __restrict__ a1v, const float* __restrict__ a1g,
                         const float* __restrict__ a2v, const float* __restrict__ a2g,
                         const float* __restrict__ g1v, const float* __restrict__ g1g,
                         const float* __restrict__ g2v, const float* __restrict__ g2g) {
    int cell = blockIdx.x;
    int r = blockIdx.y * 8 + (threadIdx.x >> 5);
    int lane = threadIdx.x & 31;
    const float* v; const float* g; float* out; int R; int rl;
    if (r < 768)       { rl = r;        v = a1v; g = a1g; out = g_ab1; R = 768; }
    else if (r < 1536) { rl = r - 768;  v = a2v; g = a2g; out = g_ab2; R = 768; }
    else if (r < 1920) { rl = r - 1536; v = g1v; g = g1g; out = g_g1;  R = 384; }
    else               { rl = r - 1920; v = g2v; g = g2g; out = g_g2;  R = 384; }
    const float* sc = g_scond + cell * DIM;
    const float* vr = v + rl * DIM;
    float p = 0.0f, n = 0.0f;
    for (int i = lane; i < DIM; i += 32) {
        float t = vr[i];
        p += sc[i] * t;
        n += t * t;
    }
    #pragma unroll
    for (int o = 16; o; o >>= 1) {
        p += __shfl_xor_sync(0xffffffffu, p, o);
        n += __shfl_xor_sync(0xffffffffu, n, o);
    }
    if (lane == 0) out[cell * R + rl] = g[rl] * rsqrtf(n) * p;
}

// adaLN, warp-per-token -> writes fp16
__global__ void __launch_bounds__(256) adaln_k(const float* __restrict__ x,
                                               const float* __restrict__ gamma,
                                               const float* __restrict__ beta,
                                               const float* __restrict__ ab) {
    const int t = blockIdx.x * 8 + (threadIdx.x >> 5);
    const int lane = threadIdx.x & 31;
    const float* xr = x + (size_t)t * DIM;

    float2 v[6];
    float s = 0.0f;
    #pragma unroll
    for (int j = 0; j < 6; j++) {
        v[j] = *(const float2*)(xr + j * 64 + lane * 2);
        s += v[j].x + v[j].y;
    }
    #pragma unroll
    for (int o = 16; o; o >>= 1) s += __shfl_xor_sync(0xffffffffu, s, o);
    const float mu = s * (1.0f / 384.0f);

    float q = 0.0f;
    #pragma unroll
    for (int j = 0; j < 6; j++) {
        float dx = v[j].x - mu, dy = v[j].y - mu;
        q += dx * dx + dy * dy;
    }
    #pragma unroll
    for (int o = 16; o; o >>= 1) q += __shfl_xor_sync(0xffffffffu, q, o);
    const float rstd = rsqrtf(q * (1.0f / 384.0f) + 1e-6f);

    const int b = t / (HGT * WID);
    const int rem = t % (HGT * WID);
    const int cell = b * 36 + ((rem / WID) >> 3) * 6 + ((rem % WID) >> 3);
    const float* abp = ab + cell * 768;

    #pragma unroll
    for (int j = 0; j < 6; j++) {
        const int c = j * 64 + lane * 2;
        float2 gm = *(const float2*)(gamma + c);
        float2 bt = *(const float2*)(beta + c);
        float2 aa = *(const float2*)(abp + c);
        float2 bb = *(const float2*)(abp + 384 + c);
        float y0 = (v[j].x - mu) * rstd * gm.x + bt.x;
        float y1 = (v[j].y - mu) * rstd * gm.y + bt.y;
        y0 = y0 * (1.0f + aa.x) + bb.x;
        y1 = y1 * (1.0f + aa.y) + bb.y;
        *(__half2*)(g_h + (size_t)t * DIM + c) = __floats2half2_rn(y0, y1);
    }
}

// ================= cp.async 3-stage fp16 GEMM ==================================
// C = epi(A @ W^T + bias); A fp16 (single), W fp16 hi/lo; D = A*Wh + A*Wl
// EPI 0: fp32 +bias  1: gelu -> fp16 out  2/3: fp32 res + val*gate[cell]
#define PITCH 40                 // fp16 per SMEM row (32 + 8 pad)
#define TILE_B 10240             // 128 * PITCH * 2
#define BUF_B  30720             // 3 tiles (A, Wh, Wl)
#define SMEM_TOT (3 * BUF_B)     // 3 stages

template <int EPI>
__global__ void __launch_bounds__(256)
hgemm_k(const __half* __restrict__ Ap, const __half* __restrict__ Whp,
        const __half* __restrict__ Wlp,
        const float* __restrict__ bias, float* __restrict__ C,
        int K, int M,
        const float* __restrict__ res, const float* __restrict__ gate,
        __half* __restrict__ Oh) {
    extern __shared__ char smem[];
    const uint32_t sbase = smem_u32(smem);
    const int tid = threadIdx.x;
    const int lane = tid & 31;
    const int w = tid >> 5;
    const int wr = w >> 2;
    const int wc = w & 3;
    const int row0 = blockIdx.y * 128;
    const int col0 = blockIdx.x * 128;

    float acc[4][4][4];
    #pragma unroll
    for (int i = 0; i < 4; i++)
        #pragma unroll
        for (int j = 0; j < 4; j++)
            #pragma unroll
            for (int q = 0; q < 4; q++) acc[i][j][q] = 0.0f;

    const int ldrow = tid >> 1;
    const int lc = (tid & 1) * 32;
    const char* srcA  = (const char*)(Ap  + (size_t)(row0 + ldrow) * K) + lc;
    const char* srcWh = (const char*)(Whp + (size_t)(col0 + ldrow) * K) + lc;
    const char* srcWl = (const char*)(Wlp + (size_t)(col0 + ldrow) * K) + lc;
    const uint32_t dbase = sbase + ldrow * (PITCH * 2) + lc;

    const int nCh = K >> 5;

    auto issue = [&](int c) {
        const int bo = (c % 3) * BUF_B;
        const int go = c * 64;
        #pragma unroll
        for (int j = 0; j < 2; j++) {
            cp16(dbase + bo + 0 * TILE_B + j * 16, srcA  + go + j * 16);
            cp16(dbase + bo + 1 * TILE_B + j * 16, srcWh + go + j * 16);
            cp16(dbase + bo + 2 * TILE_B + j * 16, srcWl + go + j * 16);
        }
    };

    issue(0); CP_COMMIT();
    if (nCh > 1) issue(1);
    CP_COMMIT();

    const int arow = lane & 15;
    const int acolh = (lane >> 4) << 3;
    const int bnt2 = lane >> 4;
    const int bkh = (lane >> 3) & 1;
    const int brow = lane & 7;

    for (int c = 0; c < nCh; c++) {
        cp_wait<1>();
        __syncthreads();
        if (c + 2 < nCh) issue(c + 2);
        CP_COMMIT();

        const uint32_t bo = sbase + (c % 3) * BUF_B;
        const uint32_t uA = bo, uBh = bo + TILE_B, uBl = bo + 2 * TILE_B;

        uint32_t ah[2][4][4], bh[2][4][2], bl[2][4][2];
        #pragma unroll
        for (int ks = 0; ks < 2; ks++) {
            const int k0 = ks * 16;
            #pragma unroll
            for (int mt = 0; mt < 4; mt++) {
                uint32_t off = (uint32_t)((wr * 64 + mt * 16 + arow) * PITCH + k0 + acolh) * 2;
                ldsm_x4(ah[ks][mt], uA + off);
            }
            #pragma unroll
            for (int ntp = 0; ntp < 2; ntp++) {
                uint32_t off = (uint32_t)((wc * 32 + (ntp * 2 + bnt2) * 8 + brow) * PITCH
                                          + k0 + bkh * 8) * 2;
                ldsm_x4(&bh[ks][ntp * 2][0], uBh + off);
                ldsm_x4(&bl[ks][ntp * 2][0], uBl + off);
            }
        }
        #pragma unroll
        for (int ks = 0; ks < 2; ks++)
            #pragma unroll
            for (int mt = 0; mt < 4; mt++)
                #pragma unroll
                for (int nt = 0; nt < 4; nt++) {
                    mma_f16(acc[mt][nt], ah[ks][mt], bh[ks][nt]);
                    mma_f16(acc[mt][nt], ah[ks][mt], bl[ks][nt]);
                }
    }

    #pragma unroll
    for (int mt = 0; mt < 4; mt++) {
        #pragma unroll
        for (int half_ = 0; half_ < 2; half_++) {
            const int r = row0 + wr * 64 + mt * 16 + (lane >> 2) + half_ * 8;
            const float* gt = nullptr;
            const float* rs = nullptr;
            if (EPI >= 2) {
                int b = r / (HGT * WID);
                int rem = r % (HGT * WID);
                int hh = rem / WID, ww = rem % WID;
                gt = gate + (b * 36 + (hh >> 3) * 6 + (ww >> 3)) * 384;
                rs = res + (size_t)r * 384;
            }
            #pragma unroll
            for (int nt = 0; nt < 4; nt++) {
                const int cc = col0 + wc * 32 + nt * 8 + (lane & 3) * 2;
                float v0 = acc[mt][nt][half_ * 2 + 0] + bias[cc];
                float v1 = acc[mt][nt][half_ * 2 + 1] + bias[cc + 1];
                if (EPI == 1) {
                    float x3 = v0 * v0 * v0;
                    v0 = 0.5f * v0 * (1.0f + tanhf(0.7978845608028654f * (v0 + 0.044715f * x3)));
                    x3 = v1 * v1 * v1;
                    v1 = 0.5f * v1 * (1.0f + tanhf(0.7978845608028654f * (v1 + 0.044715f * x3)));
                    *(__half2*)(Oh + (size_t)r * M + cc) = __floats2half2_rn(v0, v1);
                } else if (EPI == 0) {
                    *(float2*)(C + (size_t)r * M + cc) = make_float2(v0, v1);
                } else {
                    float2 o;
                    o.x = rs[cc]     + v0 * gt[cc];
                    o.y = rs[cc + 1] + v1 * gt[cc + 1];
                    *(float2*)(C + (size_t)r * 384 + cc) = o;
                }
            }
        }
    }
}

// ================= tiled neighborhood attention ================================
#define NPITCH 66
#define NAT_KV (196 * NPITCH)
#define NAT_SMEM ((2 * NAT_KV + 8 * 64) * 4)

__global__ void __launch_bounds__(128) natten_k() {
    extern __shared__ float sm[];
    float* sK = sm;
    float* sV = sm + NAT_KV;
    float* sQ = sm + 2 * NAT_KV;
    float* sW = sQ + 4 * 64;

    const int tile = blockIdx.x;
    const int head = blockIdx.y;
    const int b = tile / 36;
    const int trm = tile % 36;
    const int t0h = (trm / 6) * 8;
    const int t0w = (trm % 6) * 8;
    const int rlo = max(0, t0h - 3);
    const int rhi = min(HGT - 1, t0h + 10);
    const int clo = max(0, t0w - 3);
    const int chi = min(WID - 1, t0w + 10);
    const int nr = rhi - rlo + 1;
    const int nc = chi - clo + 1;

    const int tid = threadIdx.x;
    const int tot = nr * nc * 32;
    for (int i = tid; i < tot; i += 128) {
        int li = i >> 5;
        int d2 = (i & 31) * 2;
        int row = li / nc, col = li % nc;
        size_t gbase = (size_t)((b * HGT + rlo + row) * WID + clo + col) * 1152 + head * HD + d2;
        float2 kv = *(const float2*)(g_qkv + gbase + 384);
        float2 vv = *(const float2*)(g_qkv + gbase + 768);
        int so = (row * 14 + col) * NPITCH + d2;
        *(float2*)(sK + so) = kv;
        *(float2*)(sV + so) = vv;
    }
    __syncthreads();

    const int wid = tid >> 5;
    const int lane = tid & 31;
    float* q = sQ + wid * 64;
    float* wb = sW + wid * 64;
    const int off1 = (lane / 7) * 14 + lane % 7;
    const int nb2 = lane + 32;
    const int off2 = (nb2 / 7) * 14 + nb2 % 7;
    const bool v2ok = nb2 < 49;

    for (int tt = wid * 16; tt < wid * 16 + 16; tt++) {
        const int tr = tt >> 3, tc = tt & 7;
        const int gr = t0h + tr, gc = t0w + tc;
        const int t = (b * HGT + gr) * WID + gc;
        const int sh = min(max(gr - 3, 0), HGT - 7) - rlo;
        const int sw = min(max(gc - 3, 0), WID - 7) - clo;
        const int base = sh * 14 + sw;

        *(float2*)(q + lane * 2) = *(const float2*)(g_qkv + (size_t)t * 1152 + head * HD + lane * 2);
        __syncwarp();

        float a1 = 0.0f, a2 = 0.0f;
        const float* k1 = sK + (base + off1) * NPITCH;
        const float* k2 = sK + (base + off2) * NPITCH;
        #pragma unroll
        for (int d = 0; d < 64; d += 2) {
            float2 qd = *(const float2*)(q + d);
            float2 x1 = *(const float2*)(k1 + d);
            float2 x2 = *(const float2*)(k2 + d);
            a1 += qd.x * x1.x + qd.y * x1.y;
            a2 += qd.x * x2.x + qd.y * x2.y;
        }
        a1 *= 0.125f;
        a2 = v2ok ? a2 * 0.125f : -1e30f;

        float m = fmaxf(a1, a2);
        #pragma unroll
        for (int o = 16; o; o >>= 1) m = fmaxf(m, __shfl_xor_sync(0xffffffffu, m, o));
        float e1 = __expf(a1 - m);
        float e2 = v2ok ? __expf(a2 - m) : 0.0f;
        float s = e1 + e2;
        #pragma unroll
        for (int o = 16; o; o >>= 1) s += __shfl_xor_sync(0xffffffffu, s, o);
        float inv = 1.0f / s;
        wb[lane] = e1;
        wb[32 + lane] = e2;
        __syncwarp();

        float o0 = 0.0f, o1 = 0.0f;
        #pragma unroll
        for (int nb = 0; nb < 49; nb++) {
            const int off = (nb / 7) * 14 + nb % 7;
            float wv = wb[nb];
            float2 vv = *(const float2*)(sV + (base + off) * NPITCH + lane * 2);
            o0 += wv * vv.x;
            o1 += wv * vv.y;
        }
        o0 *= inv; o1 *= inv;
        *(__half2*)(g_attn + (size_t)t * DIM + head * HD + lane * 2) = __floats2half2_rn(o0, o1);
        __syncwarp();
    }
}

// ---------------- launch ------------------------------------------------------
extern "C" void kernel_launch(void* const* d_in, const int* in_sizes, int n_in,
                              void* d_out, int out_size) {
    const float* x       = (const float*)d_in[0];
    const float* cond    = (const float*)d_in[1];
    const float* ln1_g   = (const float*)d_in[2];
    const float* ln1_b   = (const float*)d_in[3];
    const float* ada1_v  = (const float*)d_in[4];
    const float* ada1_g  = (const float*)d_in[5];
    const float* ln2_g   = (const float*)d_in[6];
    const float* ln2_b   = (const float*)d_in[7];
    const float* ada2_v  = (const float*)d_in[8];
    const float* ada2_g  = (const float*)d_in[9];
    const float* gate1_v = (const float*)d_in[10];
    const float* gate1_g = (const float*)d_in[11];
    const float* gate2_v = (const float*)d_in[12];
    const float* gate2_g = (const float*)d_in[13];
    const float* w_qkv   = (const float*)d_in[14];
    const float* b_qkv   = (const float*)d_in[15];
    const float* w_out   = (const float*)d_in[16];
    const float* b_out   = (const float*)d_in[17];
    const float* w_mlp1  = (const float*)d_in[18];
    const float* b_mlp1  = (const float*)d_in[19];
    const float* w_mlp2  = (const float*)d_in[20];
    const float* b_mlp2  = (const float*)d_in[21];
    float* out = (float*)d_out;

    float *p_ab1, *p_g1, *p_ab2, *p_g2, *p_qkv, *p_x;
    __half *p_h, *p_attn, *p_mlp;
    __half *p_wqh, *p_wql, *p_woh, *p_wol, *p_w1h, *p_w1l, *p_w2h, *p_w2l;
    cudaGetSymbolAddress((void**)&p_ab1, g_ab1);
    cudaGetSymbolAddress((void**)&p_ab2, g_ab2);
    cudaGetSymbolAddress((void**)&p_g1, g_g1);
    cudaGetSymbolAddress((void**)&p_g2, g_g2);
    cudaGetSymbolAddress((void**)&p_qkv, g_qkv);
    cudaGetSymbolAddress((void**)&p_x, g_x);
    cudaGetSymbolAddress((void**)&p_h, g_h);
    cudaGetSymbolAddress((void**)&p_attn, g_attn);
    cudaGetSymbolAddress((void**)&p_mlp, g_mlp);
    cudaGetSymbolAddress((void**)&p_wqh, g_wqkv_h);
    cudaGetSymbolAddress((void**)&p_wql, g_wqkv_l);
    cudaGetSymbolAddress((void**)&p_woh, g_wout_h);
    cudaGetSymbolAddress((void**)&p_wol, g_wout_l);
    cudaGetSymbolAddress((void**)&p_w1h, g_wm1_h);
    cudaGetSymbolAddress((void**)&p_w1l, g_wm1_l);
    cudaGetSymbolAddress((void**)&p_w2h, g_wm2_h);
    cudaGetSymbolAddress((void**)&p_w2l, g_wm2_l);

    cudaFuncSetAttribute(hgemm_k<0>, cudaFuncAttributeMaxDynamicSharedMemorySize, SMEM_TOT);
    cudaFuncSetAttribute(hgemm_k<1>, cudaFuncAttributeMaxDynamicSharedMemorySize, SMEM_TOT);
    cudaFuncSetAttribute(hgemm_k<2>, cudaFuncAttributeMaxDynamicSharedMemorySize, SMEM_TOT);
    cudaFuncSetAttribute(hgemm_k<3>, cudaFuncAttributeMaxDynamicSharedMemorySize, SMEM_TOT);
    cudaFuncSetAttribute(natten_k, cudaFuncAttributeMaxDynamicSharedMemorySize, NAT_SMEM);

    split4_k<<<(S0 + S1 + S2 + S3 + 255) / 256, 256>>>(w_qkv, w_out, w_mlp1, w_mlp2);
    silu_k<<<(NCELL * DIM + 255) / 256, 256>>>(cond);
    modall_k<<<dim3(NCELL, 2304 / 8), 256>>>(ada1_v, ada1_g, ada2_v, ada2_g,
                                             gate1_v, gate1_g, gate2_v, gate2_g);

    adaln_k<<<NTOK / 8, 256>>>(x, ln1_g, ln1_b, p_ab1);
    hgemm_k<0><<<dim3(1152 / 128, NTOK / 128), 256, SMEM_TOT>>>(
        p_h, p_wqh, p_wql, b_qkv, p_qkv, 384, 1152, nullptr, nullptr, nullptr);
    natten_k<<<dim3(72, NHEAD), 128, NAT_SMEM>>>();
    hgemm_k<2><<<dim3(384 / 128, NTOK / 128), 256, SMEM_TOT>>>(
        p_attn, p_woh, p_wol, b_out, p_x, 384, 384, x, p_g1, nullptr);

    adaln_k<<<NTOK / 8, 256>>>(p_x, ln2_g, ln2_b, p_ab2);
    hgemm_k<1><<<dim3(1536 / 128, NTOK / 128), 256, SMEM_TOT>>>(
        p_h, p_w1h, p_w1l, b_mlp1, nullptr, 384, 1536, nullptr, nullptr, p_mlp);
    hgemm_k<3><<<dim3(384 / 128, NTOK / 128), 256, SMEM_TOT>>>(
        p_mlp, p_w2h, p_w2l, b_mlp2, out, 1536, 384, p_x, p_g2, nullptr);
}

// round 9
// speedup vs baseline: 3.2082x; 1.2102x over previous
#include <cuda_runtime.h>
#include <cuda_fp16.h>
#include <cstdint>
#include <math.h>

// Problem constants
#define NTOK 4608          // B*H*W = 2*48*48
#define DIM 384
#define HGT 48
#define WID 48
#define NCELL 72           // B*6*6
#define NHEAD 6
#define HD 64

// ---------------- scratch (device globals; no allocation allowed) -------------
__device__ float g_scond[NCELL * DIM];
__device__ float g_ab1[NCELL * 768];
__device__ float g_ab2[NCELL * 768];
__device__ float g_g1[NCELL * 384];
__device__ float g_g2[NCELL * 384];
__device__ float g_qkv[NTOK * 1152];
__device__ float g_x[NTOK * DIM];

// fp16 weights + fp16 activations (single precision-rounded copies)
__device__ __align__(16) __half g_wqkv[1152 * 384];
__device__ __align__(16) __half g_wout[384 * 384];
__device__ __align__(16) __half g_wm1[1536 * 384];
__device__ __align__(16) __half g_wm2[384 * 1536];
__device__ __align__(16) __half g_h[NTOK * 384];
__device__ __align__(16) __half g_attn[NTOK * 384];
__device__ __align__(16) __half g_mlp[NTOK * 1536];

// ---------------- helpers -----------------------------------------------------
__device__ __forceinline__ uint32_t smem_u32(const void* p) {
    uint32_t a;
    asm("{ .reg .u64 t; cvta.to.shared.u64 t, %1; cvt.u32.u64 %0, t; }" : "=r"(a) : "l"(p));
    return a;
}
__device__ __forceinline__ void cp16(uint32_t dst, const void* src) {
    asm volatile("cp.async.ca.shared.global [%0], [%1], 16;" :: "r"(dst), "l"(src));
}
#define CP_COMMIT() asm volatile("cp.async.commit_group;" ::: "memory")
template <int N> __device__ __forceinline__ void cp_wait() {
    asm volatile("cp.async.wait_group %0;" :: "n"(N) : "memory");
}
__device__ __forceinline__ void ldsm_x4(uint32_t* r, uint32_t addr) {
    asm volatile("ldmatrix.sync.aligned.m8n8.x4.shared.b16 {%0,%1,%2,%3}, [%4];"
                 : "=r"(r[0]), "=r"(r[1]), "=r"(r[2]), "=r"(r[3]) : "r"(addr));
}
__device__ __forceinline__ void mma_f16(float* c, const uint32_t* a, const uint32_t* b) {
    asm volatile("mma.sync.aligned.m16n8k16.row.col.f32.f16.f16.f32 "
                 "{%0,%1,%2,%3}, {%4,%5,%6,%7}, {%8,%9}, {%0,%1,%2,%3};"
                 : "+f"(c[0]), "+f"(c[1]), "+f"(c[2]), "+f"(c[3])
                 : "r"(a[0]), "r"(a[1]), "r"(a[2]), "r"(a[3]), "r"(b[0]), "r"(b[1]));
}

// ---------------- small prep kernels -----------------------------------------
__global__ void silu_k(const float* __restrict__ cond) {
    int i = blockIdx.x * blockDim.x + threadIdx.x;
    if (i < NCELL * DIM) {
        float v = cond[i];
        g_scond[i] = v / (1.0f + __expf(-v));
    }
}

#define S0 (1152 * 384)
#define S1 (384 * 384)
#define S2 (1536 * 384)
#define S3 (384 * 1536)
__global__ void cvt4_k(const float* __restrict__ w0, const float* __restrict__ w1,
                       const float* __restrict__ w2, const float* __restrict__ w3) {
    int i = blockIdx.x * blockDim.x + threadIdx.x;
    const float* src; __half* dst; int li;
    if (i < S0)                { src = w0; dst = g_wqkv; li = i; }
    else if (i < S0 + S1)      { src = w1; dst = g_wout; li = i - S0; }
    else if (i < S0 + S1 + S2) { src = w2; dst = g_wm1;  li = i - S0 - S1; }
    else if (i < S0 + S1 + S2 + S3)
                               { src = w3; dst = g_wm2;  li = i - S0 - S1 - S2; }
    else return;
    dst[li] = __float2half_rn(src[li]);
}

__global__ void modall_k(const float* __restrict__ a1v, const float* __restrict__ a1g,
                         const float* __restrict__ a2v, const float* __restrict__ a2g,
                         const float* __restrict__ g1v, const float* __restrict__ g1g,
                         const float* __restrict__ g2v, const float* __restrict__ g2g) {
    int cell = blockIdx.x;
    int r = blockIdx.y * 8 + (threadIdx.x >> 5);
    int lane = threadIdx.x & 31;
    const float* v; const float* g; float* out; int R; int rl;
    if (r < 768)       { rl = r;        v = a1v; g = a1g; out = g_ab1; R = 768; }
    else if (r < 1536) { rl = r - 768;  v = a2v; g = a2g; out = g_ab2; R = 768; }
    else if (r < 1920) { rl = r - 1536; v = g1v; g = g1g; out = g_g1;  R = 384; }
    else               { rl = r - 1920; v = g2v; g = g2g; out = g_g2;  R = 384; }
    const float* sc = g_scond + cell * DIM;
    const float* vr = v + rl * DIM;
    float p = 0.0f, n = 0.0f;
    for (int i = lane; i < DIM; i += 32) {
        float t = vr[i];
        p += sc[i] * t;
        n += t * t;
    }
    #pragma unroll
    for (int o = 16; o; o >>= 1) {
        p += __shfl_xor_sync(0xffffffffu, p, o);
        n += __shfl_xor_sync(0xffffffffu, n, o);
    }
    if (lane == 0) out[cell * R + rl] = g[rl] * rsqrtf(n) * p;
}

// adaLN, warp-per-token -> writes fp16
__global__ void __launch_bounds__(256) adaln_k(const float* __restrict__ x,
                                               const float* __restrict__ gamma,
                                               const float* __restrict__ beta,
                                               const float* __restrict__ ab) {
    const int t = blockIdx.x * 8 + (threadIdx.x >> 5);
    const int lane = threadIdx.x & 31;
    const float* xr = x + (size_t)t * DIM;

    float2 v[6];
    float s = 0.0f;
    #pragma unroll
    for (int j = 0; j < 6; j++) {
        v[j] = *(const float2*)(xr + j * 64 + lane * 2);
        s += v[j].x + v[j].y;
    }
    #pragma unroll
    for (int o = 16; o; o >>= 1) s += __shfl_xor_sync(0xffffffffu, s, o);
    const float mu = s * (1.0f / 384.0f);

    float q = 0.0f;
    #pragma unroll
    for (int j = 0; j < 6; j++) {
        float dx = v[j].x - mu, dy = v[j].y - mu;
        q += dx * dx + dy * dy;
    }
    #pragma unroll
    for (int o = 16; o; o >>= 1) q += __shfl_xor_sync(0xffffffffu, q, o);
    const float rstd = rsqrtf(q * (1.0f / 384.0f) + 1e-6f);

    const int b = t / (HGT * WID);
    const int rem = t % (HGT * WID);
    const int cell = b * 36 + ((rem / WID) >> 3) * 6 + ((rem % WID) >> 3);
    const float* abp = ab + cell * 768;

    #pragma unroll
    for (int j = 0; j < 6; j++) {
        const int c = j * 64 + lane * 2;
        float2 gm = *(const float2*)(gamma + c);
        float2 bt = *(const float2*)(beta + c);
        float2 aa = *(const float2*)(abp + c);
        float2 bb = *(const float2*)(abp + 384 + c);
        float y0 = (v[j].x - mu) * rstd * gm.x + bt.x;
        float y1 = (v[j].y - mu) * rstd * gm.y + bt.y;
        y0 = y0 * (1.0f + aa.x) + bb.x;
        y1 = y1 * (1.0f + aa.y) + bb.y;
        *(__half2*)(g_h + (size_t)t * DIM + c) = __floats2half2_rn(y0, y1);
    }
}

// ================= cp.async 3-stage fp16 GEMM ==================================
// C = epi(A @ W^T + bias); A, W single fp16; fp32 accum
// EPI 0: fp32 +bias  1: gelu -> fp16 out  2/3: fp32 res + val*gate[cell]
#define PITCH 40                 // fp16 per SMEM row (32 + 8 pad)
#define TILE_B 10240             // 128 * PITCH * 2
#define BUF_B  20480             // 2 tiles (A, W)
#define SMEM_TOT (3 * BUF_B)     // 3 stages

template <int EPI>
__global__ void __launch_bounds__(256)
hgemm_k(const __half* __restrict__ Ap, const __half* __restrict__ Wp,
        const float* __restrict__ bias, float* __restrict__ C,
        int K, int M,
        const float* __restrict__ res, const float* __restrict__ gate,
        __half* __restrict__ Oh) {
    extern __shared__ char smem[];
    const uint32_t sbase = smem_u32(smem);
    const int tid = threadIdx.x;
    const int lane = tid & 31;
    const int w = tid >> 5;
    const int wr = w >> 2;
    const int wc = w & 3;
    const int row0 = blockIdx.y * 128;
    const int col0 = blockIdx.x * 128;

    float acc[4][4][4];
    #pragma unroll
    for (int i = 0; i < 4; i++)
        #pragma unroll
        for (int j = 0; j < 4; j++)
            #pragma unroll
            for (int q = 0; q < 4; q++) acc[i][j][q] = 0.0f;

    const int ldrow = tid >> 1;
    const int lc = (tid & 1) * 32;
    const char* srcA = (const char*)(Ap + (size_t)(row0 + ldrow) * K) + lc;
    const char* srcW = (const char*)(Wp + (size_t)(col0 + ldrow) * K) + lc;
    const uint32_t dbase = sbase + ldrow * (PITCH * 2) + lc;

    const int nCh = K >> 5;

    auto issue = [&](int c) {
        const int bo = (c % 3) * BUF_B;
        const int go = c * 64;
        #pragma unroll
        for (int j = 0; j < 2; j++) {
            cp16(dbase + bo + 0 * TILE_B + j * 16, srcA + go + j * 16);
            cp16(dbase + bo + 1 * TILE_B + j * 16, srcW + go + j * 16);
        }
    };

    issue(0); CP_COMMIT();
    if (nCh > 1) issue(1);
    CP_COMMIT();

    const int arow = lane & 15;
    const int acolh = (lane >> 4) << 3;
    const int bnt2 = lane >> 4;
    const int bkh = (lane >> 3) & 1;
    const int brow = lane & 7;

    for (int c = 0; c < nCh; c++) {
        cp_wait<1>();
        __syncthreads();
        if (c + 2 < nCh) issue(c + 2);
        CP_COMMIT();

        const uint32_t bo = sbase + (c % 3) * BUF_B;
        const uint32_t uA = bo, uB = bo + TILE_B;

        uint32_t ah[2][4][4], bh[2][4][2];
        #pragma unroll
        for (int ks = 0; ks < 2; ks++) {
            const int k0 = ks * 16;
            #pragma unroll
            for (int mt = 0; mt < 4; mt++) {
                uint32_t off = (uint32_t)((wr * 64 + mt * 16 + arow) * PITCH + k0 + acolh) * 2;
                ldsm_x4(ah[ks][mt], uA + off);
            }
            #pragma unroll
            for (int ntp = 0; ntp < 2; ntp++) {
                uint32_t off = (uint32_t)((wc * 32 + (ntp * 2 + bnt2) * 8 + brow) * PITCH
                                          + k0 + bkh * 8) * 2;
                ldsm_x4(&bh[ks][ntp * 2][0], uB + off);
            }
        }
        #pragma unroll
        for (int ks = 0; ks < 2; ks++)
            #pragma unroll
            for (int mt = 0; mt < 4; mt++)
                #pragma unroll
                for (int nt = 0; nt < 4; nt++)
                    mma_f16(acc[mt][nt], ah[ks][mt], bh[ks][nt]);
    }

    #pragma unroll
    for (int mt = 0; mt < 4; mt++) {
        #pragma unroll
        for (int half_ = 0; half_ < 2; half_++) {
            const int r = row0 + wr * 64 + mt * 16 + (lane >> 2) + half_ * 8;
            const float* gt = nullptr;
            const float* rs = nullptr;
            if (EPI >= 2) {
                int b = r / (HGT * WID);
                int rem = r % (HGT * WID);
                int hh = rem / WID, ww = rem % WID;
                gt = gate + (b * 36 + (hh >> 3) * 6 + (ww >> 3)) * 384;
                rs = res + (size_t)r * 384;
            }
            #pragma unroll
            for (int nt = 0; nt < 4; nt++) {
                const int cc = col0 + wc * 32 + nt * 8 + (lane & 3) * 2;
                float v0 = acc[mt][nt][half_ * 2 + 0] + bias[cc];
                float v1 = acc[mt][nt][half_ * 2 + 1] + bias[cc + 1];
                if (EPI == 1) {
                    float x3 = v0 * v0 * v0;
                    v0 = 0.5f * v0 * (1.0f + tanhf(0.7978845608028654f * (v0 + 0.044715f * x3)));
                    x3 = v1 * v1 * v1;
                    v1 = 0.5f * v1 * (1.0f + tanhf(0.7978845608028654f * (v1 + 0.044715f * x3)));
                    *(__half2*)(Oh + (size_t)r * M + cc) = __floats2half2_rn(v0, v1);
                } else if (EPI == 0) {
                    *(float2*)(C + (size_t)r * M + cc) = make_float2(v0, v1);
                } else {
                    float2 o;
                    o.x = rs[cc]     + v0 * gt[cc];
                    o.y = rs[cc + 1] + v1 * gt[cc + 1];
                    *(float2*)(C + (size_t)r * 384 + cc) = o;
                }
            }
        }
    }
}

// ================= tiled neighborhood attention ================================
#define NPITCH 66
#define NAT_KV (196 * NPITCH)
#define NAT_SMEM ((2 * NAT_KV + 8 * 64) * 4)

__global__ void __launch_bounds__(128) natten_k() {
    extern __shared__ float sm[];
    float* sK = sm;
    float* sV = sm + NAT_KV;
    float* sQ = sm + 2 * NAT_KV;
    float* sW = sQ + 4 * 64;

    const int tile = blockIdx.x;
    const int head = blockIdx.y;
    const int b = tile / 36;
    const int trm = tile % 36;
    const int t0h = (trm / 6) * 8;
    const int t0w = (trm % 6) * 8;
    const int rlo = max(0, t0h - 3);
    const int rhi = min(HGT - 1, t0h + 10);
    const int clo = max(0, t0w - 3);
    const int chi = min(WID - 1, t0w + 10);
    const int nr = rhi - rlo + 1;
    const int nc = chi - clo + 1;

    const int tid = threadIdx.x;
    const int tot = nr * nc * 32;
    for (int i = tid; i < tot; i += 128) {
        int li = i >> 5;
        int d2 = (i & 31) * 2;
        int row = li / nc, col = li % nc;
        size_t gbase = (size_t)((b * HGT + rlo + row) * WID + clo + col) * 1152 + head * HD + d2;
        float2 kv = *(const float2*)(g_qkv + gbase + 384);
        float2 vv = *(const float2*)(g_qkv + gbase + 768);
        int so = (row * 14 + col) * NPITCH + d2;
        *(float2*)(sK + so) = kv;
        *(float2*)(sV + so) = vv;
    }
    __syncthreads();

    const int wid = tid >> 5;
    const int lane = tid & 31;
    float* q = sQ + wid * 64;
    float* wb = sW + wid * 64;
    const int off1 = (lane / 7) * 14 + lane % 7;
    const int nb2 = lane + 32;
    const int off2 = (nb2 / 7) * 14 + nb2 % 7;
    const bool v2ok = nb2 < 49;

    for (int tt = wid * 16; tt < wid * 16 + 16; tt++) {
        const int tr = tt >> 3, tc = tt & 7;
        const int gr = t0h + tr, gc = t0w + tc;
        const int t = (b * HGT + gr) * WID + gc;
        const int sh = min(max(gr - 3, 0), HGT - 7) - rlo;
        const int sw = min(max(gc - 3, 0), WID - 7) - clo;
        const int base = sh * 14 + sw;

        *(float2*)(q + lane * 2) = *(const float2*)(g_qkv + (size_t)t * 1152 + head * HD + lane * 2);
        __syncwarp();

        float a1 = 0.0f, a2 = 0.0f;
        const float* k1 = sK + (base + off1) * NPITCH;
        const float* k2 = sK + (base + off2) * NPITCH;
        #pragma unroll
        for (int d = 0; d < 64; d += 2) {
            float2 qd = *(const float2*)(q + d);
            float2 x1 = *(const float2*)(k1 + d);
            float2 x2 = *(const float2*)(k2 + d);
            a1 += qd.x * x1.x + qd.y * x1.y;
            a2 += qd.x * x2.x + qd.y * x2.y;
        }
        a1 *= 0.125f;
        a2 = v2ok ? a2 * 0.125f : -1e30f;

        float m = fmaxf(a1, a2);
        #pragma unroll
        for (int o = 16; o; o >>= 1) m = fmaxf(m, __shfl_xor_sync(0xffffffffu, m, o));
        float e1 = __expf(a1 - m);
        float e2 = v2ok ? __expf(a2 - m) : 0.0f;
        float s = e1 + e2;
        #pragma unroll
        for (int o = 16; o; o >>= 1) s += __shfl_xor_sync(0xffffffffu, s, o);
        float inv = 1.0f / s;
        wb[lane] = e1;
        wb[32 + lane] = e2;
        __syncwarp();

        float o0 = 0.0f, o1 = 0.0f;
        #pragma unroll
        for (int nb = 0; nb < 49; nb++) {
            const int off = (nb / 7) * 14 + nb % 7;
            float wv = wb[nb];
            float2 vv = *(const float2*)(sV + (base + off) * NPITCH + lane * 2);
            o0 += wv * vv.x;
            o1 += wv * vv.y;
        }
        o0 *= inv; o1 *= inv;
        *(__half2*)(g_attn + (size_t)t * DIM + head * HD + lane * 2) = __floats2half2_rn(o0, o1);
        __syncwarp();
    }
}

// ---------------- launch ------------------------------------------------------
extern "C" void kernel_launch(void* const* d_in, const int* in_sizes, int n_in,
                              void* d_out, int out_size) {
    const float* x       = (const float*)d_in[0];
    const float* cond    = (const float*)d_in[1];
    const float* ln1_g   = (const float*)d_in[2];
    const float* ln1_b   = (const float*)d_in[3];
    const float* ada1_v  = (const float*)d_in[4];
    const float* ada1_g  = (const float*)d_in[5];
    const float* ln2_g   = (const float*)d_in[6];
    const float* ln2_b   = (const float*)d_in[7];
    const float* ada2_v  = (const float*)d_in[8];
    const float* ada2_g  = (const float*)d_in[9];
    const float* gate1_v = (const float*)d_in[10];
    const float* gate1_g = (const float*)d_in[11];
    const float* gate2_v = (const float*)d_in[12];
    const float* gate2_g = (const float*)d_in[13];
    const float* w_qkv   = (const float*)d_in[14];
    const float* b_qkv   = (const float*)d_in[15];
    const float* w_out   = (const float*)d_in[16];
    const float* b_out   = (const float*)d_in[17];
    const float* w_mlp1  = (const float*)d_in[18];
    const float* b_mlp1  = (const float*)d_in[19];
    const float* w_mlp2  = (const float*)d_in[20];
    const float* b_mlp2  = (const float*)d_in[21];
    float* out = (float*)d_out;

    float *p_ab1, *p_g1, *p_ab2, *p_g2, *p_qkv, *p_x;
    __half *p_h, *p_attn, *p_mlp, *p_wq, *p_wo, *p_w1, *p_w2;
    cudaGetSymbolAddress((void**)&p_ab1, g_ab1);
    cudaGetSymbolAddress((void**)&p_ab2, g_ab2);
    cudaGetSymbolAddress((void**)&p_g1, g_g1);
    cudaGetSymbolAddress((void**)&p_g2, g_g2);
    cudaGetSymbolAddress((void**)&p_qkv, g_qkv);
    cudaGetSymbolAddress((void**)&p_x, g_x);
    cudaGetSymbolAddress((void**)&p_h, g_h);
    cudaGetSymbolAddress((void**)&p_attn, g_attn);
    cudaGetSymbolAddress((void**)&p_mlp, g_mlp);
    cudaGetSymbolAddress((void**)&p_wq, g_wqkv);
    cudaGetSymbolAddress((void**)&p_wo, g_wout);
    cudaGetSymbolAddress((void**)&p_w1, g_wm1);
    cudaGetSymbolAddress((void**)&p_w2, g_wm2);

    cudaFuncSetAttribute(hgemm_k<0>, cudaFuncAttributeMaxDynamicSharedMemorySize, SMEM_TOT);
    cudaFuncSetAttribute(hgemm_k<1>, cudaFuncAttributeMaxDynamicSharedMemorySize, SMEM_TOT);
    cudaFuncSetAttribute(hgemm_k<2>, cudaFuncAttributeMaxDynamicSharedMemorySize, SMEM_TOT);
    cudaFuncSetAttribute(hgemm_k<3>, cudaFuncAttributeMaxDynamicSharedMemorySize, SMEM_TOT);
    cudaFuncSetAttribute(natten_k, cudaFuncAttributeMaxDynamicSharedMemorySize, NAT_SMEM);

    cvt4_k<<<(S0 + S1 + S2 + S3 + 255) / 256, 256>>>(w_qkv, w_out, w_mlp1, w_mlp2);
    silu_k<<<(NCELL * DIM + 255) / 256, 256>>>(cond);
    modall_k<<<dim3(NCELL, 2304 / 8), 256>>>(ada1_v, ada1_g, ada2_v, ada2_g,
                                             gate1_v, gate1_g, gate2_v, gate2_g);

    adaln_k<<<NTOK / 8, 256>>>(x, ln1_g, ln1_b, p_ab1);
    hgemm_k<0><<<dim3(1152 / 128, NTOK / 128), 256, SMEM_TOT>>>(
        p_h, p_wq, b_qkv, p_qkv, 384, 1152, nullptr, nullptr, nullptr);
    natten_k<<<dim3(72, NHEAD), 128, NAT_SMEM>>>();
    hgemm_k<2><<<dim3(384 / 128, NTOK / 128), 256, SMEM_TOT>>>(
        p_attn, p_wo, b_out, p_x, 384, 384, x, p_g1, nullptr);

    adaln_k<<<NTOK / 8, 256>>>(p_x, ln2_g, ln2_b, p_ab2);
    hgemm_k<1><<<dim3(1536 / 128, NTOK / 128), 256, SMEM_TOT>>>(
        p_h, p_w1, b_mlp1, nullptr, 384, 1536, nullptr, nullptr, p_mlp);
    hgemm_k<3><<<dim3(384 / 128, NTOK / 128), 256, SMEM_TOT>>>(
        p_mlp, p_w2, b_mlp2, out, 1536, 384, p_x, p_g2, nullptr);
}

// round 10
// speedup vs baseline: 3.5151x; 1.0957x over previous
#include <cuda_runtime.h>
#include <cuda_fp16.h>
#include <cstdint>
#include <math.h>

#define NTOK 4608
#define DIM 384
#define HGT 48
#define WID 48
#define NCELL 72
#define NHEAD 6
#define HD 64

// ---------------- scratch -----------------------------------------------------
__device__ float g_ab1[NCELL * 768];
__device__ float g_ab2[NCELL * 768];
__device__ float g_g1[NCELL * 384];
__device__ float g_g2[NCELL * 384];
__device__ float g_x[NTOK * DIM];

__device__ __align__(16) __half g_wqkv[1152 * 384];
__device__ __align__(16) __half g_wout[384 * 384];
__device__ __align__(16) __half g_wm1[1536 * 384];
__device__ __align__(16) __half g_wm2[384 * 1536];
__device__ __align__(16) __half g_h[NTOK * 384];
__device__ __align__(16) __half g_qkvh[NTOK * 1152];
__device__ __align__(16) __half g_attn[NTOK * 384];
__device__ __align__(16) __half g_mlp[NTOK * 1536];

// ---------------- helpers -----------------------------------------------------
#define GDC_WAIT() asm volatile("griddepcontrol.wait;" ::: "memory")

__device__ __forceinline__ uint32_t smem_u32(const void* p) {
    uint32_t a;
    asm("{ .reg .u64 t; cvta.to.shared.u64 t, %1; cvt.u32.u64 %0, t; }" : "=r"(a) : "l"(p));
    return a;
}
__device__ __forceinline__ void cp16(uint32_t dst, const void* src) {
    asm volatile("cp.async.ca.shared.global [%0], [%1], 16;" :: "r"(dst), "l"(src));
}
#define CP_COMMIT() asm volatile("cp.async.commit_group;" ::: "memory")
template <int N> __device__ __forceinline__ void cp_wait() {
    asm volatile("cp.async.wait_group %0;" :: "n"(N) : "memory");
}
__device__ __forceinline__ void ldsm_x4(uint32_t* r, uint32_t addr) {
    asm volatile("ldmatrix.sync.aligned.m8n8.x4.shared.b16 {%0,%1,%2,%3}, [%4];"
                 : "=r"(r[0]), "=r"(r[1]), "=r"(r[2]), "=r"(r[3]) : "r"(addr));
}
__device__ __forceinline__ void mma_f16(float* c, const uint32_t* a, const uint32_t* b) {
    asm volatile("mma.sync.aligned.m16n8k16.row.col.f32.f16.f16.f32 "
                 "{%0,%1,%2,%3}, {%4,%5,%6,%7}, {%8,%9}, {%0,%1,%2,%3};"
                 : "+f"(c[0]), "+f"(c[1]), "+f"(c[2]), "+f"(c[3])
                 : "r"(a[0]), "r"(a[1]), "r"(a[2]), "r"(a[3]), "r"(b[0]), "r"(b[1]));
}

// ================ merged prep kernel ==========================================
// blocks [0,72):   modall — stage silu(cond) in smem, 32 weight rows per CTA
// blocks [72,504): weight fp32->fp16 convert (vectorized)
#define PREP_SMEM (NCELL * DIM * 4)        // 110592 B
#define CVT_F4_0 110592                    // float4 counts
#define CVT_F4_1 36864
#define CVT_F4_2 147456
#define CVT_F4_3 147456

__global__ void __launch_bounds__(256) prep_k(
    const float* __restrict__ cond,
    const float* __restrict__ a1v, const float* __restrict__ a1g,
    const float* __restrict__ a2v, const float* __restrict__ a2g,
    const float* __restrict__ g1v, const float* __restrict__ g1g,
    const float* __restrict__ g2v, const float* __restrict__ g2g,
    const float* __restrict__ w0, const float* __restrict__ w1,
    const float* __restrict__ w2, const float* __restrict__ w3) {
    const int tid = threadIdx.x;
    if (blockIdx.x >= 72) {
        // weight convert: 442368 float4 total, 432 blocks x 256 x 4
        const int cb = blockIdx.x - 72;
        #pragma unroll
        for (int t = 0; t < 4; t++) {
            int i4 = cb * 1024 + t * 256 + tid;
            const float* src; __half* dst; int li;
            if (i4 < CVT_F4_0)                      { src = w0; dst = g_wqkv; li = i4; }
            else if (i4 < CVT_F4_0 + CVT_F4_1)      { src = w1; dst = g_wout; li = i4 - CVT_F4_0; }
            else if (i4 < CVT_F4_0 + CVT_F4_1 + CVT_F4_2)
                                                    { src = w2; dst = g_wm1;  li = i4 - CVT_F4_0 - CVT_F4_1; }
            else                                    { src = w3; dst = g_wm2;  li = i4 - CVT_F4_0 - CVT_F4_1 - CVT_F4_2; }
            float4 v = ((const float4*)src)[li];
            __half2 h0 = __floats2half2_rn(v.x, v.y);
            __half2 h1 = __floats2half2_rn(v.z, v.w);
            uint2 u;
            u.x = *reinterpret_cast<uint32_t*>(&h0);
            u.y = *reinterpret_cast<uint32_t*>(&h1);
            *reinterpret_cast<uint2*>(dst + (size_t)li * 4) = u;
        }
        return;
    }
    // ---- modall block ----
    extern __shared__ float sc[];          // silu(cond): 72*384 floats
    for (int i = tid; i < NCELL * DIM; i += 256) {
        float v = cond[i];
        sc[i] = v / (1.0f + __expf(-v));
    }
    __syncthreads();

    const int r0 = blockIdx.x * 32;        // 32 rows per CTA, never spans buffers
    const int w = tid >> 5, lane = tid & 31;
    const float* v; const float* g; float* out; int R; int rb;
    if (r0 < 768)       { v = a1v; g = a1g; out = g_ab1; R = 768; rb = r0; }
    else if (r0 < 1536) { v = a2v; g = a2g; out = g_ab2; R = 768; rb = r0 - 768; }
    else if (r0 < 1920) { v = g1v; g = g1g; out = g_g1;  R = 384; rb = r0 - 1536; }
    else                { v = g2v; g = g2g; out = g_g2;  R = 384; rb = r0 - 1920; }

    // warp handles rows rb + w*4 .. +3
    float vr[4][12];
    float sr[4];
    #pragma unroll
    for (int j = 0; j < 4; j++) {
        const int rl = rb + w * 4 + j;
        const float* row = v + (size_t)rl * DIM;
        float n = 0.0f;
        #pragma unroll
        for (int q = 0; q < 12; q++) {
            float t = row[lane + 32 * q];
            vr[j][q] = t;
            n += t * t;
        }
        #pragma unroll
        for (int o = 16; o; o >>= 1) n += __shfl_xor_sync(0xffffffffu, n, o);
        sr[j] = g[rl] * rsqrtf(n);
    }
    for (int cell = 0; cell < NCELL; cell++) {
        const float* scc = sc + cell * DIM;
        float p[4] = {0.0f, 0.0f, 0.0f, 0.0f};
        #pragma unroll
        for (int q = 0; q < 12; q++) {
            float s = scc[lane + 32 * q];
            #pragma unroll
            for (int j = 0; j < 4; j++) p[j] += s * vr[j][q];
        }
        #pragma unroll
        for (int j = 0; j < 4; j++) {
            #pragma unroll
            for (int o = 16; o; o >>= 1) p[j] += __shfl_xor_sync(0xffffffffu, p[j], o);
        }
        if (lane < 4) out[cell * R + rb + w * 4 + lane] = p[lane] * sr[lane];
    }
}

// ---------------- adaLN, warp-per-token -> fp16 --------------------------------
__global__ void __launch_bounds__(256) adaln_k(const float* __restrict__ x,
                                               const float* __restrict__ gamma,
                                               const float* __restrict__ beta,
                                               const float* __restrict__ ab) {
    GDC_WAIT();
    const int t = blockIdx.x * 8 + (threadIdx.x >> 5);
    const int lane = threadIdx.x & 31;
    const float* xr = x + (size_t)t * DIM;

    float2 v[6];
    float s = 0.0f;
    #pragma unroll
    for (int j = 0; j < 6; j++) {
        v[j] = *(const float2*)(xr + j * 64 + lane * 2);
        s += v[j].x + v[j].y;
    }
    #pragma unroll
    for (int o = 16; o; o >>= 1) s += __shfl_xor_sync(0xffffffffu, s, o);
    const float mu = s * (1.0f / 384.0f);

    float q = 0.0f;
    #pragma unroll
    for (int j = 0; j < 6; j++) {
        float dx = v[j].x - mu, dy = v[j].y - mu;
        q += dx * dx + dy * dy;
    }
    #pragma unroll
    for (int o = 16; o; o >>= 1) q += __shfl_xor_sync(0xffffffffu, q, o);
    const float rstd = rsqrtf(q * (1.0f / 384.0f) + 1e-6f);

    const int b = t / (HGT * WID);
    const int rem = t % (HGT * WID);
    const int cell = b * 36 + ((rem / WID) >> 3) * 6 + ((rem % WID) >> 3);
    const float* abp = ab + cell * 768;

    #pragma unroll
    for (int j = 0; j < 6; j++) {
        const int c = j * 64 + lane * 2;
        float2 gm = *(const float2*)(gamma + c);
        float2 bt = *(const float2*)(beta + c);
        float2 aa = *(const float2*)(abp + c);
        float2 bb = *(const float2*)(abp + 384 + c);
        float y0 = (v[j].x - mu) * rstd * gm.x + bt.x;
        float y1 = (v[j].y - mu) * rstd * gm.y + bt.y;
        y0 = y0 * (1.0f + aa.x) + bb.x;
        y1 = y1 * (1.0f + aa.y) + bb.y;
        *(__half2*)(g_h + (size_t)t * DIM + c) = __floats2half2_rn(y0, y1);
    }
}

// ================= cp.async 3-stage fp16 GEMM ==================================
// EPI 0: +bias -> fp16 Oh   1: gelu -> fp16 Oh   2/3: fp32 res + val*gate[cell]
#define PITCH 40
#define TILE_B 10240
#define BUF_B  20480
#define SMEM_TOT (3 * BUF_B)

template <int EPI>
__global__ void __launch_bounds__(256)
hgemm_k(const __half* __restrict__ Ap, const __half* __restrict__ Wp,
        const float* __restrict__ bias, float* __restrict__ C,
        int K, int M,
        const float* __restrict__ res, const float* __restrict__ gate,
        __half* __restrict__ Oh) {
    extern __shared__ char smem[];
    const uint32_t sbase = smem_u32(smem);
    const int tid = threadIdx.x;
    const int lane = tid & 31;
    const int w = tid >> 5;
    const int wr = w >> 2;
    const int wc = w & 3;
    const int row0 = blockIdx.y * 128;
    const int col0 = blockIdx.x * 128;

    float acc[4][4][4];
    #pragma unroll
    for (int i = 0; i < 4; i++)
        #pragma unroll
        for (int j = 0; j < 4; j++)
            #pragma unroll
            for (int q = 0; q < 4; q++) acc[i][j][q] = 0.0f;

    const int ldrow = tid >> 1;
    const int lc = (tid & 1) * 32;
    const char* srcA = (const char*)(Ap + (size_t)(row0 + ldrow) * K) + lc;
    const char* srcW = (const char*)(Wp + (size_t)(col0 + ldrow) * K) + lc;
    const uint32_t dbase = sbase + ldrow * (PITCH * 2) + lc;

    const int nCh = K >> 5;

    auto issue = [&](int c) {
        const int bo = (c % 3) * BUF_B;
        const int go = c * 64;
        #pragma unroll
        for (int j = 0; j < 2; j++) {
            cp16(dbase + bo + 0 * TILE_B + j * 16, srcA + go + j * 16);
            cp16(dbase + bo + 1 * TILE_B + j * 16, srcW + go + j * 16);
        }
    };

    GDC_WAIT();
    issue(0); CP_COMMIT();
    if (nCh > 1) issue(1);
    CP_COMMIT();

    const int arow = lane & 15;
    const int acolh = (lane >> 4) << 3;
    const int bnt2 = lane >> 4;
    const int bkh = (lane >> 3) & 1;
    const int brow = lane & 7;

    for (int c = 0; c < nCh; c++) {
        cp_wait<1>();
        __syncthreads();
        if (c + 2 < nCh) issue(c + 2);
        CP_COMMIT();

        const uint32_t bo = sbase + (c % 3) * BUF_B;
        const uint32_t uA = bo, uB = bo + TILE_B;

        uint32_t ah[2][4][4], bh[2][4][2];
        #pragma unroll
        for (int ks = 0; ks < 2; ks++) {
            const int k0 = ks * 16;
            #pragma unroll
            for (int mt = 0; mt < 4; mt++) {
                uint32_t off = (uint32_t)((wr * 64 + mt * 16 + arow) * PITCH + k0 + acolh) * 2;
                ldsm_x4(ah[ks][mt], uA + off);
            }
            #pragma unroll
            for (int ntp = 0; ntp < 2; ntp++) {
                uint32_t off = (uint32_t)((wc * 32 + (ntp * 2 + bnt2) * 8 + brow) * PITCH
                                          + k0 + bkh * 8) * 2;
                ldsm_x4(&bh[ks][ntp * 2][0], uB + off);
            }
        }
        #pragma unroll
        for (int ks = 0; ks < 2; ks++)
            #pragma unroll
            for (int mt = 0; mt < 4; mt++)
                #pragma unroll
                for (int nt = 0; nt < 4; nt++)
                    mma_f16(acc[mt][nt], ah[ks][mt], bh[ks][nt]);
    }

    #pragma unroll
    for (int mt = 0; mt < 4; mt++) {
        #pragma unroll
        for (int half_ = 0; half_ < 2; half_++) {
            const int r = row0 + wr * 64 + mt * 16 + (lane >> 2) + half_ * 8;
            const float* gt = nullptr;
            const float* rs = nullptr;
            if (EPI >= 2) {
                int b = r / (HGT * WID);
                int rem = r % (HGT * WID);
                int hh = rem / WID, ww = rem % WID;
                gt = gate + (b * 36 + (hh >> 3) * 6 + (ww >> 3)) * 384;
                rs = res + (size_t)r * 384;
            }
            #pragma unroll
            for (int nt = 0; nt < 4; nt++) {
                const int cc = col0 + wc * 32 + nt * 8 + (lane & 3) * 2;
                float v0 = acc[mt][nt][half_ * 2 + 0] + bias[cc];
                float v1 = acc[mt][nt][half_ * 2 + 1] + bias[cc + 1];
                if (EPI == 1) {
                    float x3 = v0 * v0 * v0;
                    v0 = 0.5f * v0 * (1.0f + tanhf(0.7978845608028654f * (v0 + 0.044715f * x3)));
                    x3 = v1 * v1 * v1;
                    v1 = 0.5f * v1 * (1.0f + tanhf(0.7978845608028654f * (v1 + 0.044715f * x3)));
                }
                if (EPI <= 1) {
                    *(__half2*)(Oh + (size_t)r * M + cc) = __floats2half2_rn(v0, v1);
                } else {
                    float2 o;
                    o.x = rs[cc]     + v0 * gt[cc];
                    o.y = rs[cc + 1] + v1 * gt[cc + 1];
                    *(float2*)(C + (size_t)r * 384 + cc) = o;
                }
            }
        }
    }
}

// ================= tiled neighborhood attention (fp16 qkv) =====================
#define NPITCH 66
#define NAT_KV (196 * NPITCH)
#define NAT_SMEM ((2 * NAT_KV + 8 * 64) * 4)

__global__ void __launch_bounds__(128) natten_k() {
    extern __shared__ float sm[];
    float* sK = sm;
    float* sV = sm + NAT_KV;
    float* sQ = sm + 2 * NAT_KV;
    float* sW = sQ + 4 * 64;

    const int tile = blockIdx.x;
    const int head = blockIdx.y;
    const int b = tile / 36;
    const int trm = tile % 36;
    const int t0h = (trm / 6) * 8;
    const int t0w = (trm % 6) * 8;
    const int rlo = max(0, t0h - 3);
    const int rhi = min(HGT - 1, t0h + 10);
    const int clo = max(0, t0w - 3);
    const int chi = min(WID - 1, t0w + 10);
    const int nr = rhi - rlo + 1;
    const int nc = chi - clo + 1;

    GDC_WAIT();
    const int tid = threadIdx.x;
    const int tot = nr * nc * 32;
    for (int i = tid; i < tot; i += 128) {
        int li = i >> 5;
        int d2 = (i & 31) * 2;
        int row = li / nc, col = li % nc;
        size_t gbase = (size_t)((b * HGT + rlo + row) * WID + clo + col) * 1152 + head * HD + d2;
        float2 kv = __half22float2(*(const __half2*)(g_qkvh + gbase + 384));
        float2 vv = __half22float2(*(const __half2*)(g_qkvh + gbase + 768));
        int so = (row * 14 + col) * NPITCH + d2;
        *(float2*)(sK + so) = kv;
        *(float2*)(sV + so) = vv;
    }
    __syncthreads();

    const int wid = tid >> 5;
    const int lane = tid & 31;
    float* q = sQ + wid * 64;
    float* wb = sW + wid * 64;
    const int off1 = (lane / 7) * 14 + lane % 7;
    const int nb2 = lane + 32;
    const int off2 = (nb2 / 7) * 14 + nb2 % 7;
    const bool v2ok = nb2 < 49;

    for (int tt = wid * 16; tt < wid * 16 + 16; tt++) {
        const int tr = tt >> 3, tc = tt & 7;
        const int gr = t0h + tr, gc = t0w + tc;
        const int t = (b * HGT + gr) * WID + gc;
        const int sh = min(max(gr - 3, 0), HGT - 7) - rlo;
        const int sw = min(max(gc - 3, 0), WID - 7) - clo;
        const int base = sh * 14 + sw;

        *(float2*)(q + lane * 2) = __half22float2(
            *(const __half2*)(g_qkvh + (size_t)t * 1152 + head * HD + lane * 2));
        __syncwarp();

        float a1 = 0.0f, a2 = 0.0f;
        const float* k1 = sK + (base + off1) * NPITCH;
        const float* k2 = sK + (base + off2) * NPITCH;
        #pragma unroll
        for (int d = 0; d < 64; d += 2) {
            float2 qd = *(const float2*)(q + d);
            float2 x1 = *(const float2*)(k1 + d);
            float2 x2 = *(const float2*)(k2 + d);
            a1 += qd.x * x1.x + qd.y * x1.y;
            a2 += qd.x * x2.x + qd.y * x2.y;
        }
        a1 *= 0.125f;
        a2 = v2ok ? a2 * 0.125f : -1e30f;

        float m = fmaxf(a1, a2);
        #pragma unroll
        for (int o = 16; o; o >>= 1) m = fmaxf(m, __shfl_xor_sync(0xffffffffu, m, o));
        float e1 = __expf(a1 - m);
        float e2 = v2ok ? __expf(a2 - m) : 0.0f;
        float s = e1 + e2;
        #pragma unroll
        for (int o = 16; o; o >>= 1) s += __shfl_xor_sync(0xffffffffu, s, o);
        float inv = 1.0f / s;
        wb[lane] = e1;
        wb[32 + lane] = e2;
        __syncwarp();

        float o0 = 0.0f, o1 = 0.0f;
        #pragma unroll
        for (int nb = 0; nb < 49; nb++) {
            const int off = (nb / 7) * 14 + nb % 7;
            float wv = wb[nb];
            float2 vv = *(const float2*)(sV + (base + off) * NPITCH + lane * 2);
            o0 += wv * vv.x;
            o1 += wv * vv.y;
        }
        o0 *= inv; o1 *= inv;
        *(__half2*)(g_attn + (size_t)t * DIM + head * HD + lane * 2) = __floats2half2_rn(o0, o1);
        __syncwarp();
    }
}

// ---------------- launch ------------------------------------------------------
template <typename F, typename... Args>
static void launch_pdl(F f, dim3 g, dim3 b, size_t smem, Args... args) {
    cudaLaunchConfig_t cfg = {};
    cfg.gridDim = g;
    cfg.blockDim = b;
    cfg.dynamicSmemBytes = smem;
    cfg.stream = 0;
    cudaLaunchAttribute at[1];
    at[0].id = cudaLaunchAttributeProgrammaticStreamSerialization;
    at[0].val.programmaticStreamSerializationAllowed = 1;
    cfg.attrs = at;
    cfg.numAttrs = 1;
    cudaLaunchKernelEx(&cfg, f, args...);
}

extern "C" void kernel_launch(void* const* d_in, const int* in_sizes, int n_in,
                              void* d_out, int out_size) {
    const float* x       = (const float*)d_in[0];
    const float* cond    = (const float*)d_in[1];
    const float* ln1_g   = (const float*)d_in[2];
    const float* ln1_b   = (const float*)d_in[3];
    const float* ada1_v  = (const float*)d_in[4];
    const float* ada1_g  = (const float*)d_in[5];
    const float* ln2_g   = (const float*)d_in[6];
    const float* ln2_b   = (const float*)d_in[7];
    const float* ada2_v  = (const float*)d_in[8];
    const float* ada2_g  = (const float*)d_in[9];
    const float* gate1_v = (const float*)d_in[10];
    const float* gate1_g = (const float*)d_in[11];
    const float* gate2_v = (const float*)d_in[12];
    const float* gate2_g = (const float*)d_in[13];
    const float* w_qkv   = (const float*)d_in[14];
    const float* b_qkv   = (const float*)d_in[15];
    const float* w_out   = (const float*)d_in[16];
    const float* b_out   = (const float*)d_in[17];
    const float* w_mlp1  = (const float*)d_in[18];
    const float* b_mlp1  = (const float*)d_in[19];
    const float* w_mlp2  = (const float*)d_in[20];
    const float* b_mlp2  = (const float*)d_in[21];
    float* out = (float*)d_out;

    float *p_ab1, *p_g1, *p_ab2, *p_g2, *p_x;
    __half *p_h, *p_qkvh, *p_attn, *p_mlp, *p_wq, *p_wo, *p_w1, *p_w2;
    cudaGetSymbolAddress((void**)&p_ab1, g_ab1);
    cudaGetSymbolAddress((void**)&p_ab2, g_ab2);
    cudaGetSymbolAddress((void**)&p_g1, g_g1);
    cudaGetSymbolAddress((void**)&p_g2, g_g2);
    cudaGetSymbolAddress((void**)&p_x, g_x);
    cudaGetSymbolAddress((void**)&p_h, g_h);
    cudaGetSymbolAddress((void**)&p_qkvh, g_qkvh);
    cudaGetSymbolAddress((void**)&p_attn, g_attn);
    cudaGetSymbolAddress((void**)&p_mlp, g_mlp);
    cudaGetSymbolAddress((void**)&p_wq, g_wqkv);
    cudaGetSymbolAddress((void**)&p_wo, g_wout);
    cudaGetSymbolAddress((void**)&p_w1, g_wm1);
    cudaGetSymbolAddress((void**)&p_w2, g_wm2);

    cudaFuncSetAttribute(prep_k, cudaFuncAttributeMaxDynamicSharedMemorySize, PREP_SMEM);
    cudaFuncSetAttribute(hgemm_k<0>, cudaFuncAttributeMaxDynamicSharedMemorySize, SMEM_TOT);
    cudaFuncSetAttribute(hgemm_k<1>, cudaFuncAttributeMaxDynamicSharedMemorySize, SMEM_TOT);
    cudaFuncSetAttribute(hgemm_k<2>, cudaFuncAttributeMaxDynamicSharedMemorySize, SMEM_TOT);
    cudaFuncSetAttribute(hgemm_k<3>, cudaFuncAttributeMaxDynamicSharedMemorySize, SMEM_TOT);
    cudaFuncSetAttribute(natten_k, cudaFuncAttributeMaxDynamicSharedMemorySize, NAT_SMEM);

    // 1) prep (modall + weight convert), normal launch (first kernel)
    prep_k<<<72 + 432, 256, PREP_SMEM>>>(cond, ada1_v, ada1_g, ada2_v, ada2_g,
                                         gate1_v, gate1_g, gate2_v, gate2_g,
                                         w_qkv, w_out, w_mlp1, w_mlp2);

    const float* nullf = nullptr;
    __half* nullh = nullptr;

    // 2..8) PDL chain
    launch_pdl(adaln_k, dim3(NTOK / 8), dim3(256), 0, x, ln1_g, ln1_b, (const float*)p_ab1);
    launch_pdl(hgemm_k<0>, dim3(1152 / 128, NTOK / 128), dim3(256), (size_t)SMEM_TOT,
               (const __half*)p_h, (const __half*)p_wq, b_qkv, (float*)nullptr, 384, 1152,
               nullf, nullf, p_qkvh);
    launch_pdl(natten_k, dim3(72, NHEAD), dim3(128), (size_t)NAT_SMEM);
    launch_pdl(hgemm_k<2>, dim3(384 / 128, NTOK / 128), dim3(256), (size_t)SMEM_TOT,
               (const __half*)p_attn, (const __half*)p_wo, b_out, p_x, 384, 384,
               x, (const float*)p_g1, nullh);
    launch_pdl(adaln_k, dim3(NTOK / 8), dim3(256), 0, (const float*)p_x, ln2_g, ln2_b,
               (const float*)p_ab2);
    launch_pdl(hgemm_k<1>, dim3(1536 / 128, NTOK / 128), dim3(256), (size_t)SMEM_TOT,
               (const __half*)p_h, (const __half*)p_w1, b_mlp1, (float*)nullptr, 384, 1536,
               nullf, nullf, p_mlp);
    launch_pdl(hgemm_k<3>, dim3(384 / 128, NTOK / 128), dim3(256), (size_t)SMEM_TOT,
               (const __half*)p_mlp, (const __half*)p_w2, b_mlp2, out, 1536, 384,
               (const float*)p_x, (const float*)p_g2, nullh);
}

// round 11
// speedup vs baseline: 4.4294x; 1.2601x over previous
#include <cuda_runtime.h>
#include <cuda_fp16.h>
#include <cstdint>
#include <math.h>

#define NTOK 4608
#define DIM 384
#define HGT 48
#define WID 48
#define NCELL 72
#define NHEAD 6
#define HD 64

// ---------------- scratch -----------------------------------------------------
__device__ float g_ab1[NCELL * 768];
__device__ float g_ab2[NCELL * 768];
__device__ float g_g1[NCELL * 384];
__device__ float g_g2[NCELL * 384];
__device__ float g_x[NTOK * DIM];

__device__ __align__(16) __half g_wqkv[1152 * 384];
__device__ __align__(16) __half g_wout[384 * 384];
__device__ __align__(16) __half g_wm1[1536 * 384];
__device__ __align__(16) __half g_wm2[384 * 1536];
__device__ __align__(16) __half g_h[NTOK * 384];
__device__ __align__(16) __half g_qkvh[NTOK * 1152];
__device__ __align__(16) __half g_attn[NTOK * 384];
__device__ __align__(16) __half g_mlp[NTOK * 1536];

// ---------------- helpers -----------------------------------------------------
#define GDC_WAIT() asm volatile("griddepcontrol.wait;" ::: "memory")

__device__ __forceinline__ uint32_t smem_u32(const void* p) {
    uint32_t a;
    asm("{ .reg .u64 t; cvta.to.shared.u64 t, %1; cvt.u32.u64 %0, t; }" : "=r"(a) : "l"(p));
    return a;
}
__device__ __forceinline__ void cp16(uint32_t dst, const void* src) {
    asm volatile("cp.async.ca.shared.global [%0], [%1], 16;" :: "r"(dst), "l"(src));
}
#define CP_COMMIT() asm volatile("cp.async.commit_group;" ::: "memory")
template <int N> __device__ __forceinline__ void cp_wait() {
    asm volatile("cp.async.wait_group %0;" :: "n"(N) : "memory");
}
__device__ __forceinline__ void ldsm_x4(uint32_t* r, uint32_t addr) {
    asm volatile("ldmatrix.sync.aligned.m8n8.x4.shared.b16 {%0,%1,%2,%3}, [%4];"
                 : "=r"(r[0]), "=r"(r[1]), "=r"(r[2]), "=r"(r[3]) : "r"(addr));
}
__device__ __forceinline__ void mma_f16(float* c, const uint32_t* a, const uint32_t* b) {
    asm volatile("mma.sync.aligned.m16n8k16.row.col.f32.f16.f16.f32 "
                 "{%0,%1,%2,%3}, {%4,%5,%6,%7}, {%8,%9}, {%0,%1,%2,%3};"
                 : "+f"(c[0]), "+f"(c[1]), "+f"(c[2]), "+f"(c[3])
                 : "r"(a[0]), "r"(a[1]), "r"(a[2]), "r"(a[3]), "r"(b[0]), "r"(b[1]));
}
__device__ __forceinline__ float tanh_fast(float x) {
    float y;
    asm("tanh.approx.f32 %0, %1;" : "=f"(y) : "f"(x));
    return y;
}

// ================ merged prep kernel ==========================================
#define PREP_SMEM (NCELL * DIM * 4)
#define CVT_F4_0 110592
#define CVT_F4_1 36864
#define CVT_F4_2 147456
#define CVT_F4_3 147456

__global__ void __launch_bounds__(256) prep_k(
    const float* __restrict__ cond,
    const float* __restrict__ a1v, const float* __restrict__ a1g,
    const float* __restrict__ a2v, const float* __restrict__ a2g,
    const float* __restrict__ g1v, const float* __restrict__ g1g,
    const float* __restrict__ g2v, const float* __restrict__ g2g,
    const float* __restrict__ w0, const float* __restrict__ w1,
    const float* __restrict__ w2, const float* __restrict__ w3) {
    const int tid = threadIdx.x;
    if (blockIdx.x >= 72) {
        const int cb = blockIdx.x - 72;
        #pragma unroll
        for (int t = 0; t < 4; t++) {
            int i4 = cb * 1024 + t * 256 + tid;
            const float* src; __half* dst; int li;
            if (i4 < CVT_F4_0)                      { src = w0; dst = g_wqkv; li = i4; }
            else if (i4 < CVT_F4_0 + CVT_F4_1)      { src = w1; dst = g_wout; li = i4 - CVT_F4_0; }
            else if (i4 < CVT_F4_0 + CVT_F4_1 + CVT_F4_2)
                                                    { src = w2; dst = g_wm1;  li = i4 - CVT_F4_0 - CVT_F4_1; }
            else                                    { src = w3; dst = g_wm2;  li = i4 - CVT_F4_0 - CVT_F4_1 - CVT_F4_2; }
            float4 v = ((const float4*)src)[li];
            __half2 h0 = __floats2half2_rn(v.x, v.y);
            __half2 h1 = __floats2half2_rn(v.z, v.w);
            uint2 u;
            u.x = *reinterpret_cast<uint32_t*>(&h0);
            u.y = *reinterpret_cast<uint32_t*>(&h1);
            *reinterpret_cast<uint2*>(dst + (size_t)li * 4) = u;
        }
        return;
    }
    extern __shared__ float sc[];
    for (int i = tid; i < NCELL * DIM; i += 256) {
        float v = cond[i];
        sc[i] = v / (1.0f + __expf(-v));
    }
    __syncthreads();

    const int r0 = blockIdx.x * 32;
    const int w = tid >> 5, lane = tid & 31;
    const float* v; const float* g; float* out; int R; int rb;
    if (r0 < 768)       { v = a1v; g = a1g; out = g_ab1; R = 768; rb = r0; }
    else if (r0 < 1536) { v = a2v; g = a2g; out = g_ab2; R = 768; rb = r0 - 768; }
    else if (r0 < 1920) { v = g1v; g = g1g; out = g_g1;  R = 384; rb = r0 - 1536; }
    else                { v = g2v; g = g2g; out = g_g2;  R = 384; rb = r0 - 1920; }

    float vr[4][12];
    float sr[4];
    #pragma unroll
    for (int j = 0; j < 4; j++) {
        const int rl = rb + w * 4 + j;
        const float* row = v + (size_t)rl * DIM;
        float n = 0.0f;
        #pragma unroll
        for (int q = 0; q < 12; q++) {
            float t = row[lane + 32 * q];
            vr[j][q] = t;
            n += t * t;
        }
        #pragma unroll
        for (int o = 16; o; o >>= 1) n += __shfl_xor_sync(0xffffffffu, n, o);
        sr[j] = g[rl] * rsqrtf(n);
    }
    for (int cell = 0; cell < NCELL; cell++) {
        const float* scc = sc + cell * DIM;
        float p[4] = {0.0f, 0.0f, 0.0f, 0.0f};
        #pragma unroll
        for (int q = 0; q < 12; q++) {
            float s = scc[lane + 32 * q];
            #pragma unroll
            for (int j = 0; j < 4; j++) p[j] += s * vr[j][q];
        }
        #pragma unroll
        for (int j = 0; j < 4; j++) {
            #pragma unroll
            for (int o = 16; o; o >>= 1) p[j] += __shfl_xor_sync(0xffffffffu, p[j], o);
        }
        if (lane < 4) out[cell * R + rb + w * 4 + lane] = p[lane] * sr[lane];
    }
}

// ---------------- adaLN, warp-per-token -> fp16 --------------------------------
__global__ void __launch_bounds__(256) adaln_k(const float* __restrict__ x,
                                               const float* __restrict__ gamma,
                                               const float* __restrict__ beta,
                                               const float* __restrict__ ab) {
    GDC_WAIT();
    const int t = blockIdx.x * 8 + (threadIdx.x >> 5);
    const int lane = threadIdx.x & 31;
    const float* xr = x + (size_t)t * DIM;

    float2 v[6];
    float s = 0.0f;
    #pragma unroll
    for (int j = 0; j < 6; j++) {
        v[j] = *(const float2*)(xr + j * 64 + lane * 2);
        s += v[j].x + v[j].y;
    }
    #pragma unroll
    for (int o = 16; o; o >>= 1) s += __shfl_xor_sync(0xffffffffu, s, o);
    const float mu = s * (1.0f / 384.0f);

    float q = 0.0f;
    #pragma unroll
    for (int j = 0; j < 6; j++) {
        float dx = v[j].x - mu, dy = v[j].y - mu;
        q += dx * dx + dy * dy;
    }
    #pragma unroll
    for (int o = 16; o; o >>= 1) q += __shfl_xor_sync(0xffffffffu, q, o);
    const float rstd = rsqrtf(q * (1.0f / 384.0f) + 1e-6f);

    const int b = t / (HGT * WID);
    const int rem = t % (HGT * WID);
    const int cell = b * 36 + ((rem / WID) >> 3) * 6 + ((rem % WID) >> 3);
    const float* abp = ab + cell * 768;

    #pragma unroll
    for (int j = 0; j < 6; j++) {
        const int c = j * 64 + lane * 2;
        float2 gm = *(const float2*)(gamma + c);
        float2 bt = *(const float2*)(beta + c);
        float2 aa = *(const float2*)(abp + c);
        float2 bb = *(const float2*)(abp + 384 + c);
        float y0 = (v[j].x - mu) * rstd * gm.x + bt.x;
        float y1 = (v[j].y - mu) * rstd * gm.y + bt.y;
        y0 = y0 * (1.0f + aa.x) + bb.x;
        y1 = y1 * (1.0f + aa.y) + bb.y;
        *(__half2*)(g_h + (size_t)t * DIM + c) = __floats2half2_rn(y0, y1);
    }
}

// ================= cp.async 3-stage fp16 GEMM ==================================
#define PITCH 40
#define TILE_B 10240
#define BUF_B  20480
#define SMEM_TOT (3 * BUF_B)

template <int EPI>
__global__ void __launch_bounds__(256)
hgemm_k(const __half* __restrict__ Ap, const __half* __restrict__ Wp,
        const float* __restrict__ bias, float* __restrict__ C,
        int K, int M,
        const float* __restrict__ res, const float* __restrict__ gate,
        __half* __restrict__ Oh) {
    extern __shared__ char smem[];
    const uint32_t sbase = smem_u32(smem);
    const int tid = threadIdx.x;
    const int lane = tid & 31;
    const int w = tid >> 5;
    const int wr = w >> 2;
    const int wc = w & 3;
    const int row0 = blockIdx.y * 128;
    const int col0 = blockIdx.x * 128;

    float acc[4][4][4];
    #pragma unroll
    for (int i = 0; i < 4; i++)
        #pragma unroll
        for (int j = 0; j < 4; j++)
            #pragma unroll
            for (int q = 0; q < 4; q++) acc[i][j][q] = 0.0f;

    const int ldrow = tid >> 1;
    const int lc = (tid & 1) * 32;
    const char* srcA = (const char*)(Ap + (size_t)(row0 + ldrow) * K) + lc;
    const char* srcW = (const char*)(Wp + (size_t)(col0 + ldrow) * K) + lc;
    const uint32_t dbase = sbase + ldrow * (PITCH * 2) + lc;

    const int nCh = K >> 5;

    auto issue = [&](int c) {
        const int bo = (c % 3) * BUF_B;
        const int go = c * 64;
        #pragma unroll
        for (int j = 0; j < 2; j++) {
            cp16(dbase + bo + 0 * TILE_B + j * 16, srcA + go + j * 16);
            cp16(dbase + bo + 1 * TILE_B + j * 16, srcW + go + j * 16);
        }
    };

    GDC_WAIT();
    issue(0); CP_COMMIT();
    if (nCh > 1) issue(1);
    CP_COMMIT();

    const int arow = lane & 15;
    const int acolh = (lane >> 4) << 3;
    const int bnt2 = lane >> 4;
    const int bkh = (lane >> 3) & 1;
    const int brow = lane & 7;

    for (int c = 0; c < nCh; c++) {
        cp_wait<1>();
        __syncthreads();
        if (c + 2 < nCh) issue(c + 2);
        CP_COMMIT();

        const uint32_t bo = sbase + (c % 3) * BUF_B;
        const uint32_t uA = bo, uB = bo + TILE_B;

        uint32_t ah[2][4][4], bh[2][4][2];
        #pragma unroll
        for (int ks = 0; ks < 2; ks++) {
            const int k0 = ks * 16;
            #pragma unroll
            for (int mt = 0; mt < 4; mt++) {
                uint32_t off = (uint32_t)((wr * 64 + mt * 16 + arow) * PITCH + k0 + acolh) * 2;
                ldsm_x4(ah[ks][mt], uA + off);
            }
            #pragma unroll
            for (int ntp = 0; ntp < 2; ntp++) {
                uint32_t off = (uint32_t)((wc * 32 + (ntp * 2 + bnt2) * 8 + brow) * PITCH
                                          + k0 + bkh * 8) * 2;
                ldsm_x4(&bh[ks][ntp * 2][0], uB + off);
            }
        }
        #pragma unroll
        for (int ks = 0; ks < 2; ks++)
            #pragma unroll
            for (int mt = 0; mt < 4; mt++)
                #pragma unroll
                for (int nt = 0; nt < 4; nt++)
                    mma_f16(acc[mt][nt], ah[ks][mt], bh[ks][nt]);
    }

    #pragma unroll
    for (int mt = 0; mt < 4; mt++) {
        #pragma unroll
        for (int half_ = 0; half_ < 2; half_++) {
            const int r = row0 + wr * 64 + mt * 16 + (lane >> 2) + half_ * 8;
            const float* gt = nullptr;
            const float* rs = nullptr;
            if (EPI >= 2) {
                int b = r / (HGT * WID);
                int rem = r % (HGT * WID);
                int hh = rem / WID, ww = rem % WID;
                gt = gate + (b * 36 + (hh >> 3) * 6 + (ww >> 3)) * 384;
                rs = res + (size_t)r * 384;
            }
            #pragma unroll
            for (int nt = 0; nt < 4; nt++) {
                const int cc = col0 + wc * 32 + nt * 8 + (lane & 3) * 2;
                float v0 = acc[mt][nt][half_ * 2 + 0] + bias[cc];
                float v1 = acc[mt][nt][half_ * 2 + 1] + bias[cc + 1];
                if (EPI == 1) {
                    float x3 = v0 * v0 * v0;
                    v0 = 0.5f * v0 * (1.0f + tanh_fast(0.7978845608028654f * (v0 + 0.044715f * x3)));
                    x3 = v1 * v1 * v1;
                    v1 = 0.5f * v1 * (1.0f + tanh_fast(0.7978845608028654f * (v1 + 0.044715f * x3)));
                }
                if (EPI <= 1) {
                    *(__half2*)(Oh + (size_t)r * M + cc) = __floats2half2_rn(v0, v1);
                } else {
                    float2 o;
                    o.x = rs[cc]     + v0 * gt[cc];
                    o.y = rs[cc + 1] + v1 * gt[cc + 1];
                    *(float2*)(C + (size_t)r * 384 + cc) = o;
                }
            }
        }
    }
}

// ================= tiled neighborhood attention (fp16 smem) ====================
// 256 threads (8 warps x 8 tokens), fp16 K/V in smem, pitch 68 halves (136B rows)
#define NPITCH 68
#define NAT_KVH (196 * NPITCH)                  // halves per matrix
#define NAT_SK 0
#define NAT_SV (NAT_KVH * 2)                    // byte offsets
#define NAT_SQ (NAT_SV + NAT_KVH * 2)           // 8 warps x 128B
#define NAT_SW (NAT_SQ + 8 * 128)               // 8 warps x 256B (floats)
#define NAT_SMEM (NAT_SW + 8 * 256)

__global__ void __launch_bounds__(256) natten_k() {
    extern __shared__ char nsm[];
    __half* sK = (__half*)(nsm + NAT_SK);
    __half* sV = (__half*)(nsm + NAT_SV);

    const int tile = blockIdx.x;
    const int head = blockIdx.y;
    const int b = tile / 36;
    const int trm = tile % 36;
    const int t0h = (trm / 6) * 8;
    const int t0w = (trm % 6) * 8;
    const int rlo = max(0, t0h - 3);
    const int rhi = min(HGT - 1, t0h + 10);
    const int clo = max(0, t0w - 3);
    const int chi = min(WID - 1, t0w + 10);
    const int nr = rhi - rlo + 1;
    const int nc = chi - clo + 1;

    GDC_WAIT();
    const int tid = threadIdx.x;
    const int tot = nr * nc * 32;          // half2 units per matrix
    for (int i = tid; i < tot; i += 256) {
        int li = i >> 5;
        int d2 = (i & 31);                 // half2 index
        int row = li / nc, col = li % nc;
        size_t gbase = (size_t)((b * HGT + rlo + row) * WID + clo + col) * 1152 + head * HD + d2 * 2;
        int so = (row * 14 + col) * NPITCH + d2 * 2;
        *(__half2*)(sK + so) = *(const __half2*)(g_qkvh + gbase + 384);
        *(__half2*)(sV + so) = *(const __half2*)(g_qkvh + gbase + 768);
    }
    __syncthreads();

    const int wid = tid >> 5;
    const int lane = tid & 31;
    __half* q = (__half*)(nsm + NAT_SQ + wid * 128);
    float* wb = (float*)(nsm + NAT_SW + wid * 256);
    const int off1 = (lane / 7) * 14 + lane % 7;
    const int nb2 = lane + 32;
    const int off2 = (nb2 / 7) * 14 + nb2 % 7;
    const bool v2ok = nb2 < 49;

    for (int tt = wid * 8; tt < wid * 8 + 8; tt++) {
        const int tr = tt >> 3, tc = tt & 7;
        const int gr = t0h + tr, gc = t0w + tc;
        const int t = (b * HGT + gr) * WID + gc;
        const int sh = min(max(gr - 3, 0), HGT - 7) - rlo;
        const int sw = min(max(gc - 3, 0), WID - 7) - clo;
        const int base = sh * 14 + sw;

        // stage q (64 halves) for broadcast reads
        *(__half2*)(q + lane * 2) = *(const __half2*)(g_qkvh + (size_t)t * 1152 + head * HD + lane * 2);
        __syncwarp();

        float a1 = 0.0f, a2 = 0.0f;
        const uint2* qv = (const uint2*)q;
        const uint2* k1 = (const uint2*)(sK + (base + off1) * NPITCH);
        const uint2* k2 = (const uint2*)(sK + (base + off2) * NPITCH);
        #pragma unroll
        for (int d = 0; d < 16; d++) {
            uint2 qu = qv[d];
            uint2 u1 = k1[d];
            uint2 u2 = k2[d];
            float2 qa = __half22float2(*(const __half2*)&qu.x);
            float2 qb = __half22float2(*(const __half2*)&qu.y);
            float2 x1a = __half22float2(*(const __half2*)&u1.x);
            float2 x1b = __half22float2(*(const __half2*)&u1.y);
            float2 x2a = __half22float2(*(const __half2*)&u2.x);
            float2 x2b = __half22float2(*(const __half2*)&u2.y);
            a1 += qa.x * x1a.x + qa.y * x1a.y + qb.x * x1b.x + qb.y * x1b.y;
            a2 += qa.x * x2a.x + qa.y * x2a.y + qb.x * x2b.x + qb.y * x2b.y;
        }
        a1 *= 0.125f;
        a2 = v2ok ? a2 * 0.125f : -1e30f;

        float m = fmaxf(a1, a2);
        #pragma unroll
        for (int o = 16; o; o >>= 1) m = fmaxf(m, __shfl_xor_sync(0xffffffffu, m, o));
        float e1 = __expf(a1 - m);
        float e2 = v2ok ? __expf(a2 - m) : 0.0f;
        float s = e1 + e2;
        #pragma unroll
        for (int o = 16; o; o >>= 1) s += __shfl_xor_sync(0xffffffffu, s, o);
        float inv = 1.0f / s;
        wb[lane] = e1;
        wb[32 + lane] = e2;
        __syncwarp();

        // AV: lane owns dims 2*lane, 2*lane+1
        float o0 = 0.0f, o1 = 0.0f;
        #pragma unroll
        for (int nb = 0; nb < 49; nb++) {
            const int off = (nb / 7) * 14 + nb % 7;
            float wv = wb[nb];
            float2 vv = __half22float2(*(const __half2*)(sV + (base + off) * NPITCH + lane * 2));
            o0 += wv * vv.x;
            o1 += wv * vv.y;
        }
        o0 *= inv; o1 *= inv;
        *(__half2*)(g_attn + (size_t)t * DIM + head * HD + lane * 2) = __floats2half2_rn(o0, o1);
        __syncwarp();
    }
}

// ---------------- launch ------------------------------------------------------
template <typename F, typename... Args>
static void launch_pdl(F f, dim3 g, dim3 b, size_t smem, Args... args) {
    cudaLaunchConfig_t cfg = {};
    cfg.gridDim = g;
    cfg.blockDim = b;
    cfg.dynamicSmemBytes = smem;
    cfg.stream = 0;
    cudaLaunchAttribute at[1];
    at[0].id = cudaLaunchAttributeProgrammaticStreamSerialization;
    at[0].val.programmaticStreamSerializationAllowed = 1;
    cfg.attrs = at;
    cfg.numAttrs = 1;
    cudaLaunchKernelEx(&cfg, f, args...);
}

extern "C" void kernel_launch(void* const* d_in, const int* in_sizes, int n_in,
                              void* d_out, int out_size) {
    const float* x       = (const float*)d_in[0];
    const float* cond    = (const float*)d_in[1];
    const float* ln1_g   = (const float*)d_in[2];
    const float* ln1_b   = (const float*)d_in[3];
    const float* ada1_v  = (const float*)d_in[4];
    const float* ada1_g  = (const float*)d_in[5];
    const float* ln2_g   = (const float*)d_in[6];
    const float* ln2_b   = (const float*)d_in[7];
    const float* ada2_v  = (const float*)d_in[8];
    const float* ada2_g  = (const float*)d_in[9];
    const float* gate1_v = (const float*)d_in[10];
    const float* gate1_g = (const float*)d_in[11];
    const float* gate2_v = (const float*)d_in[12];
    const float* gate2_g = (const float*)d_in[13];
    const float* w_qkv   = (const float*)d_in[14];
    const float* b_qkv   = (const float*)d_in[15];
    const float* w_out   = (const float*)d_in[16];
    const float* b_out   = (const float*)d_in[17];
    const float* w_mlp1  = (const float*)d_in[18];
    const float* b_mlp1  = (const float*)d_in[19];
    const float* w_mlp2  = (const float*)d_in[20];
    const float* b_mlp2  = (const float*)d_in[21];
    float* out = (float*)d_out;

    float *p_ab1, *p_g1, *p_ab2, *p_g2, *p_x;
    __half *p_h, *p_qkvh, *p_attn, *p_mlp, *p_wq, *p_wo, *p_w1, *p_w2;
    cudaGetSymbolAddress((void**)&p_ab1, g_ab1);
    cudaGetSymbolAddress((void**)&p_ab2, g_ab2);
    cudaGetSymbolAddress((void**)&p_g1, g_g1);
    cudaGetSymbolAddress((void**)&p_g2, g_g2);
    cudaGetSymbolAddress((void**)&p_x, g_x);
    cudaGetSymbolAddress((void**)&p_h, g_h);
    cudaGetSymbolAddress((void**)&p_qkvh, g_qkvh);
    cudaGetSymbolAddress((void**)&p_attn, g_attn);
    cudaGetSymbolAddress((void**)&p_mlp, g_mlp);
    cudaGetSymbolAddress((void**)&p_wq, g_wqkv);
    cudaGetSymbolAddress((void**)&p_wo, g_wout);
    cudaGetSymbolAddress((void**)&p_w1, g_wm1);
    cudaGetSymbolAddress((void**)&p_w2, g_wm2);

    cudaFuncSetAttribute(prep_k, cudaFuncAttributeMaxDynamicSharedMemorySize, PREP_SMEM);
    cudaFuncSetAttribute(hgemm_k<0>, cudaFuncAttributeMaxDynamicSharedMemorySize, SMEM_TOT);
    cudaFuncSetAttribute(hgemm_k<1>, cudaFuncAttributeMaxDynamicSharedMemorySize, SMEM_TOT);
    cudaFuncSetAttribute(hgemm_k<2>, cudaFuncAttributeMaxDynamicSharedMemorySize, SMEM_TOT);
    cudaFuncSetAttribute(hgemm_k<3>, cudaFuncAttributeMaxDynamicSharedMemorySize, SMEM_TOT);
    cudaFuncSetAttribute(natten_k, cudaFuncAttributeMaxDynamicSharedMemorySize, NAT_SMEM);

    prep_k<<<72 + 432, 256, PREP_SMEM>>>(cond, ada1_v, ada1_g, ada2_v, ada2_g,
                                         gate1_v, gate1_g, gate2_v, gate2_g,
                                         w_qkv, w_out, w_mlp1, w_mlp2);

    const float* nullf = nullptr;
    __half* nullh = nullptr;

    launch_pdl(adaln_k, dim3(NTOK / 8), dim3(256), 0, x, ln1_g, ln1_b, (const float*)p_ab1);
    launch_pdl(hgemm_k<0>, dim3(1152 / 128, NTOK / 128), dim3(256), (size_t)SMEM_TOT,
               (const __half*)p_h, (const __half*)p_wq, b_qkv, (float*)nullptr, 384, 1152,
               nullf, nullf, p_qkvh);
    launch_pdl(natten_k, dim3(72, NHEAD), dim3(256), (size_t)NAT_SMEM);
    launch_pdl(hgemm_k<2>, dim3(384 / 128, NTOK / 128), dim3(256), (size_t)SMEM_TOT,
               (const __half*)p_attn, (const __half*)p_wo, b_out, p_x, 384, 384,
               x, (const float*)p_g1, nullh);
    launch_pdl(adaln_k, dim3(NTOK / 8), dim3(256), 0, (const float*)p_x, ln2_g, ln2_b,
               (const float*)p_ab2);
    launch_pdl(hgemm_k<1>, dim3(1536 / 128, NTOK / 128), dim3(256), (size_t)SMEM_TOT,
               (const __half*)p_h, (const __half*)p_w1, b_mlp1, (float*)nullptr, 384, 1536,
               nullf, nullf, p_mlp);
    launch_pdl(hgemm_k<3>, dim3(384 / 128, NTOK / 128), dim3(256), (size_t)SMEM_TOT,
               (const __half*)p_mlp, (const __half*)p_w2, b_mlp2, out, 1536, 384,
               (const float*)p_x, (const float*)p_g2, nullh);
}